// round 1
// baseline (speedup 1.0000x reference)
#include <cuda_runtime.h>
#include <cuda_bf16.h>
#include <math.h>

// Problem constants
#define TT    2048
#define DM    1024
#define NH    16
#define NKV   4
#define HD    64
#define EPSN  1e-6f

// ---------------------------------------------------------------------------
// Device scratch (no cudaMalloc allowed)
// ---------------------------------------------------------------------------
__device__ float g_q[TT * NH * HD];     // 8 MB   [t][h][d]
__device__ float g_k[TT * NKV * HD];    // 2 MB   [t][kvh][d]
__device__ float g_v[TT * NKV * HD];    // 2 MB
__device__ float g_attn[TT * NH * HD];  // 8 MB   [t][h*64+d]
__device__ float g_q0[TT * NH];
__device__ float g_k0[TT * NKV];
__device__ float g_qn[TT * NH];

// ---------------------------------------------------------------------------
// SGEMM: C[M,N] = A[M,K] * B[N,K]^T    (all row-major, dims multiples of 64/16)
// 64x64 tile, BK=16, 256 threads, 4x4 per thread, transposed smem tiles so the
// inner loop does 2x LDS.128 + 16 FFMA.
// ---------------------------------------------------------------------------
#define BM 64
#define BN 64
#define BK 16

__global__ __launch_bounds__(256) void sgemm_abt(const float* __restrict__ A,
                                                 const float* __restrict__ B,
                                                 float* __restrict__ C,
                                                 int M, int N, int K) {
    __shared__ __align__(16) float As[BK][BM + 4];
    __shared__ __align__(16) float Bs[BK][BN + 4];

    const int tid = threadIdx.x;
    const int tx = tid & 15;         // 0..15
    const int ty = tid >> 4;         // 0..15
    const int m0 = blockIdx.y * BM;
    const int n0 = blockIdx.x * BN;

    const int lrow = tid >> 2;       // 0..63
    const int lcol = (tid & 3) * 4;  // 0,4,8,12

    float acc[4][4];
#pragma unroll
    for (int i = 0; i < 4; i++)
#pragma unroll
        for (int j = 0; j < 4; j++) acc[i][j] = 0.f;

    for (int k0 = 0; k0 < K; k0 += BK) {
        float4 a = *(const float4*)&A[(size_t)(m0 + lrow) * K + k0 + lcol];
        float4 b = *(const float4*)&B[(size_t)(n0 + lrow) * K + k0 + lcol];
        As[lcol + 0][lrow] = a.x; As[lcol + 1][lrow] = a.y;
        As[lcol + 2][lrow] = a.z; As[lcol + 3][lrow] = a.w;
        Bs[lcol + 0][lrow] = b.x; Bs[lcol + 1][lrow] = b.y;
        Bs[lcol + 2][lrow] = b.z; Bs[lcol + 3][lrow] = b.w;
        __syncthreads();

#pragma unroll
        for (int kk = 0; kk < BK; kk++) {
            float4 av = *(const float4*)&As[kk][ty * 4];
            float4 bv = *(const float4*)&Bs[kk][tx * 4];
            float ar[4] = {av.x, av.y, av.z, av.w};
            float br[4] = {bv.x, bv.y, bv.z, bv.w};
#pragma unroll
            for (int i = 0; i < 4; i++)
#pragma unroll
                for (int j = 0; j < 4; j++) acc[i][j] = fmaf(ar[i], br[j], acc[i][j]);
        }
        __syncthreads();
    }

#pragma unroll
    for (int i = 0; i < 4; i++) {
        float4 cv = make_float4(acc[i][0], acc[i][1], acc[i][2], acc[i][3]);
        *(float4*)&C[(size_t)(m0 + ty * 4 + i) * N + n0 + tx * 4] = cv;
    }
}

// ---------------------------------------------------------------------------
// RMSNorm + RoPE (in-place on q/k), also computes q0/k0 (Minkowski time comp.)
// and per-(t,h) spatial norm of q.  grid=(TT, NH+NKV), block=64.
// ---------------------------------------------------------------------------
__global__ __launch_bounds__(64) void rms_rope_kernel(float* __restrict__ qb,
                                                      float* __restrict__ kb,
                                                      float* __restrict__ q0,
                                                      float* __restrict__ k0,
                                                      float* __restrict__ qn,
                                                      const float* __restrict__ curv) {
    const int t = blockIdx.x;
    const int hh = blockIdx.y;
    const int d = threadIdx.x;

    float* vec = (hh < NH) ? (qb + ((size_t)t * NH + hh) * HD)
                           : (kb + ((size_t)t * NKV + (hh - NH)) * HD);
    float v = vec[d];

    __shared__ float sh[64];
    __shared__ float shn[64];
    sh[d] = v * v;
    __syncthreads();
#pragma unroll
    for (int s = 32; s > 0; s >>= 1) {
        if (d < s) sh[d] += sh[d + s];
        __syncthreads();
    }
    float ss = sh[0];
    float inv = rsqrtf(ss * (1.0f / 64.0f) + EPSN);
    float xn = v * inv;
    shn[d] = xn;
    __syncthreads();

    // RoPE: freq index i = d mod 32, inv_freq = 10000^(-i/32)
    int i = d & 31;
    // log(10000)/32
    float invf = expf(-(float)i * 0.28782313662425572f);
    float ang = (float)t * invf;
    float sv, cv;
    sincosf(ang, &sv, &cv);
    float outv;
    if (d < 32) outv = fmaf(shn[d], cv, shn[d + 32] * sv);
    else        outv = fmaf(-shn[i], sv, shn[d] * cv);
    vec[d] = outv;

    if (d == 0) {
        float sum2 = ss * inv * inv;  // |q_norm|^2 (RoPE preserves norm)
        float c = *curv;
        float h0 = sqrtf(1.0f / c + sum2);
        if (hh < NH) {
            q0[t * NH + hh] = h0;
            qn[t * NH + hh] = sqrtf(sum2);
        } else {
            k0[t * NKV + (hh - NH)] = h0;
        }
    }
}

// ---------------------------------------------------------------------------
// Attention: block = (8 queries, 1 head). Two passes over K/V chunks through
// shared memory; full score row in smem → exact softmax.
// ---------------------------------------------------------------------------
#define QB 8
#define CK 128
#define ATTN_THREADS 128
// smem floats: sc QB*TT + tile CK*65 + qsh QB*64 + red 128
#define ATTN_SMEM_FLOATS (QB * TT + CK * 65 + QB * 64 + 128)
#define ATTN_SMEM_BYTES  (ATTN_SMEM_FLOATS * 4)

__global__ __launch_bounds__(ATTN_THREADS) void attn_kernel(
    const float* __restrict__ Q, const float* __restrict__ K,
    const float* __restrict__ V, const float* __restrict__ q0a,
    const float* __restrict__ k0a, const float* __restrict__ temp,
    const float* __restrict__ curv, float* __restrict__ attn) {
    extern __shared__ float smem[];
    float* sc   = smem;                      // [QB][TT]
    float* tile = sc + QB * TT;              // [CK][65]
    float* qsh  = tile + CK * 65;            // [QB][64]
    float* red  = qsh + QB * 64;             // [128]

    const int tid = threadIdx.x;
    const int h = blockIdx.y;
    const int t0 = blockIdx.x * QB;
    const int kvh = h >> 2;                  // rep = NH/NKV = 4
    const int nkeys = t0 + QB;               // keys 0..t0+QB-1 needed

    const float c = *curv;
    const float inv_sqc = rsqrtf(c);
    const float itemp = 1.0f / temp[h];
    const float lo = 1.0f + 1e-5f;

    // load q tile
    for (int i = tid; i < QB * 64; i += ATTN_THREADS) {
        int qi = i >> 6, d = i & 63;
        qsh[i] = Q[((size_t)(t0 + qi) * NH + h) * HD + d];
    }
    __syncthreads();

    float q0v[QB];
#pragma unroll
    for (int qi = 0; qi < QB; qi++) q0v[qi] = q0a[(t0 + qi) * NH + h];

    // ---- pass 1: scores ----
    for (int c0 = 0; c0 < nkeys; c0 += CK) {
        int nk = min(CK, nkeys - c0);
        for (int i = tid; i < nk * 64; i += ATTN_THREADS) {
            int kl = i >> 6, d = i & 63;
            tile[kl * 65 + d] = K[((size_t)(c0 + kl) * NKV + kvh) * HD + d];
        }
        __syncthreads();
        if (tid < nk) {
            int kk = c0 + tid;
            float k0v = k0a[kk * NKV + kvh];
            float dot[QB];
#pragma unroll
            for (int qi = 0; qi < QB; qi++) dot[qi] = 0.f;
#pragma unroll
            for (int j = 0; j < 64; j++) {
                float kv = tile[tid * 65 + j];
#pragma unroll
                for (int qi = 0; qi < QB; qi++)
                    dot[qi] = fmaf(kv, qsh[qi * 64 + j], dot[qi]);
            }
#pragma unroll
            for (int qi = 0; qi < QB; qi++) {
                float s;
                if (kk <= t0 + qi) {
                    float arg = fmaxf(c * (q0v[qi] * k0v - dot[qi]), lo);
                    float dist = acoshf(arg) * inv_sqc;
                    s = -dist * itemp;
                } else {
                    s = -INFINITY;
                }
                sc[qi * TT + kk] = s;
            }
        }
        __syncthreads();
    }

    // ---- softmax (exact two-pass over smem scores) ----
    float den[QB];
#pragma unroll
    for (int qi = 0; qi < QB; qi++) {
        float m = -INFINITY;
        for (int k = tid; k < nkeys; k += ATTN_THREADS) m = fmaxf(m, sc[qi * TT + k]);
        red[tid] = m;
        __syncthreads();
#pragma unroll
        for (int s = 64; s > 0; s >>= 1) {
            if (tid < s) red[tid] = fmaxf(red[tid], red[tid + s]);
            __syncthreads();
        }
        m = red[0];
        __syncthreads();
        float sum = 0.f;
        for (int k = tid; k < nkeys; k += ATTN_THREADS) {
            float w = expf(sc[qi * TT + k] - m);  // exp(-inf)=0 handles mask
            sc[qi * TT + k] = w;
            sum += w;
        }
        red[tid] = sum;
        __syncthreads();
#pragma unroll
        for (int s = 64; s > 0; s >>= 1) {
            if (tid < s) red[tid] += red[tid + s];
            __syncthreads();
        }
        den[qi] = red[0];
        __syncthreads();
    }

    // ---- pass 2: weighted sum over V ----
    const int d = tid & 63;
    const int half = tid >> 6;
    float acc[QB];
#pragma unroll
    for (int qi = 0; qi < QB; qi++) acc[qi] = 0.f;

    for (int c0 = 0; c0 < nkeys; c0 += CK) {
        int nk = min(CK, nkeys - c0);
        for (int i = tid; i < nk * 64; i += ATTN_THREADS) {
            int kl = i >> 6, dd = i & 63;
            tile[kl * 65 + dd] = V[((size_t)(c0 + kl) * NKV + kvh) * HD + dd];
        }
        __syncthreads();
        for (int kl = half; kl < nk; kl += 2) {
            float vv = tile[kl * 65 + d];
            int kk = c0 + kl;
#pragma unroll
            for (int qi = 0; qi < QB; qi++)
                acc[qi] = fmaf(sc[qi * TT + kk], vv, acc[qi]);
        }
        __syncthreads();
    }

    // combine the two halves and write out
#pragma unroll
    for (int qi = 0; qi < QB; qi++) {
        if (half == 0) red[d] = acc[qi];
        __syncthreads();
        if (half == 1) {
            float r = (red[d] + acc[qi]) / den[qi];
            attn[(size_t)(t0 + qi) * (NH * HD) + h * HD + d] = r;
        }
        __syncthreads();
    }
}

// ---------------------------------------------------------------------------
// spatial_norm = mean over (t,h) of |q|
// ---------------------------------------------------------------------------
__global__ __launch_bounds__(256) void norm_reduce_kernel(const float* __restrict__ qn,
                                                          float* __restrict__ out_scalar) {
    __shared__ float red[256];
    int tid = threadIdx.x;
    float s = 0.f;
    for (int i = tid; i < TT * NH; i += 256) s += qn[i];
    red[tid] = s;
    __syncthreads();
#pragma unroll
    for (int k = 128; k > 0; k >>= 1) {
        if (tid < k) red[tid] += red[tid + k];
        __syncthreads();
    }
    if (tid == 0) *out_scalar = red[0] * (1.0f / (float)(TT * NH));
}

// ---------------------------------------------------------------------------
// Launch
// ---------------------------------------------------------------------------
extern "C" void kernel_launch(void* const* d_in, const int* in_sizes, int n_in,
                              void* d_out, int out_size) {
    const float* x    = (const float*)d_in[0];
    const float* q_w  = (const float*)d_in[1];
    const float* k_w  = (const float*)d_in[2];
    const float* v_w  = (const float*)d_in[3];
    const float* o_w  = (const float*)d_in[4];
    const float* temp = (const float*)d_in[5];
    const float* curv = (const float*)d_in[6];
    float* out = (float*)d_out;

    float *pq, *pk, *pv, *pattn, *pq0, *pk0, *pqn;
    cudaGetSymbolAddress((void**)&pq, g_q);
    cudaGetSymbolAddress((void**)&pk, g_k);
    cudaGetSymbolAddress((void**)&pv, g_v);
    cudaGetSymbolAddress((void**)&pattn, g_attn);
    cudaGetSymbolAddress((void**)&pq0, g_q0);
    cudaGetSymbolAddress((void**)&pk0, g_k0);
    cudaGetSymbolAddress((void**)&pqn, g_qn);

    cudaFuncSetAttribute(attn_kernel, cudaFuncAttributeMaxDynamicSharedMemorySize,
                         ATTN_SMEM_BYTES);

    // QKV projections
    sgemm_abt<<<dim3(DM / BN, TT / BM), 256>>>(x, q_w, pq, TT, DM, DM);
    sgemm_abt<<<dim3((NKV * HD) / BN, TT / BM), 256>>>(x, k_w, pk, TT, NKV * HD, DM);
    sgemm_abt<<<dim3((NKV * HD) / BN, TT / BM), 256>>>(x, v_w, pv, TT, NKV * HD, DM);

    // RMSNorm + RoPE + q0/k0 + per-head norms
    rms_rope_kernel<<<dim3(TT, NH + NKV), 64>>>(pq, pk, pq0, pk0, pqn, curv);

    // Hyperbolic causal attention
    attn_kernel<<<dim3(TT / QB, NH), ATTN_THREADS, ATTN_SMEM_BYTES>>>(
        pq, pk, pv, pq0, pk0, temp, curv, pattn);

    // Output projection → first TT*DM elements of d_out
    sgemm_abt<<<dim3(DM / BN, TT / BM), 256>>>(pattn, o_w, out, TT, DM, DM);

    // spatial_norm scalar → last element
    norm_reduce_kernel<<<1, 256>>>(pqn, out + (out_size - 1));
}

// round 2
// speedup vs baseline: 2.1113x; 2.1113x over previous
#include <cuda_runtime.h>
#include <cuda_bf16.h>
#include <math.h>

// Problem constants
#define TT    2048
#define DM    1024
#define NH    16
#define NKV   4
#define HD    64
#define EPSN  1e-6f

// ---------------------------------------------------------------------------
// Device scratch (no cudaMalloc allowed)
// ---------------------------------------------------------------------------
__device__ float g_q[TT * NH * HD];     // 8 MB   [t][h][d]
__device__ float g_k[TT * NKV * HD];    // 2 MB   [t][kvh][d]
__device__ float g_v[TT * NKV * HD];    // 2 MB
__device__ float g_attn[TT * NH * HD];  // 8 MB   [t][h*64+d]
__device__ float g_q0[TT * NH];
__device__ float g_k0[TT * NKV];
__device__ float g_qn[TT * NH];

// ---------------------------------------------------------------------------
// SGEMM: C[M,N] = A[M,K] * B[N,K]^T  (row-major; M%64==0, N%128==0, K%16==0)
// 64x128 tile, BK=16, 256 threads, 4x8 per thread.
// Inner loop: 3x LDS.128 + 32 FFMA (conflict-free reads).
// ---------------------------------------------------------------------------
#define GM 64
#define GN 128
#define GK 16

__global__ __launch_bounds__(256) void sgemm_abt(const float* __restrict__ A,
                                                 const float* __restrict__ B,
                                                 float* __restrict__ C,
                                                 int M, int N, int K) {
    __shared__ __align__(16) float As[GK][GM + 4];   // transposed A tile
    __shared__ __align__(16) float Bs[GK][GN + 4];   // transposed B tile

    const int tid = threadIdx.x;
    const int tx = tid & 15;          // 0..15  -> 8 cols (split 4+4)
    const int ty = tid >> 4;          // 0..15  -> 4 rows
    const int m0 = blockIdx.y * GM;
    const int n0 = blockIdx.x * GN;

    const int lrow = tid >> 2;        // 0..63
    const int lcol = (tid & 3) * 4;   // 0,4,8,12

    float acc[4][8];
#pragma unroll
    for (int i = 0; i < 4; i++)
#pragma unroll
        for (int j = 0; j < 8; j++) acc[i][j] = 0.f;

    for (int k0 = 0; k0 < K; k0 += GK) {
        float4 a  = *(const float4*)&A[(size_t)(m0 + lrow) * K + k0 + lcol];
        float4 b0 = *(const float4*)&B[(size_t)(n0 + lrow) * K + k0 + lcol];
        float4 b1 = *(const float4*)&B[(size_t)(n0 + lrow + 64) * K + k0 + lcol];
        As[lcol + 0][lrow] = a.x;  As[lcol + 1][lrow] = a.y;
        As[lcol + 2][lrow] = a.z;  As[lcol + 3][lrow] = a.w;
        Bs[lcol + 0][lrow] = b0.x; Bs[lcol + 1][lrow] = b0.y;
        Bs[lcol + 2][lrow] = b0.z; Bs[lcol + 3][lrow] = b0.w;
        Bs[lcol + 0][lrow + 64] = b1.x; Bs[lcol + 1][lrow + 64] = b1.y;
        Bs[lcol + 2][lrow + 64] = b1.z; Bs[lcol + 3][lrow + 64] = b1.w;
        __syncthreads();

#pragma unroll
        for (int kk = 0; kk < GK; kk++) {
            float4 av  = *(const float4*)&As[kk][ty * 4];
            float4 bv0 = *(const float4*)&Bs[kk][tx * 4];
            float4 bv1 = *(const float4*)&Bs[kk][tx * 4 + 64];
            float ar[4] = {av.x, av.y, av.z, av.w};
            float br[8] = {bv0.x, bv0.y, bv0.z, bv0.w, bv1.x, bv1.y, bv1.z, bv1.w};
#pragma unroll
            for (int i = 0; i < 4; i++)
#pragma unroll
                for (int j = 0; j < 8; j++) acc[i][j] = fmaf(ar[i], br[j], acc[i][j]);
        }
        __syncthreads();
    }

#pragma unroll
    for (int i = 0; i < 4; i++) {
        float4 c0 = make_float4(acc[i][0], acc[i][1], acc[i][2], acc[i][3]);
        float4 c1 = make_float4(acc[i][4], acc[i][5], acc[i][6], acc[i][7]);
        *(float4*)&C[(size_t)(m0 + ty * 4 + i) * N + n0 + tx * 4] = c0;
        *(float4*)&C[(size_t)(m0 + ty * 4 + i) * N + n0 + 64 + tx * 4] = c1;
    }
}

// ---------------------------------------------------------------------------
// RMSNorm + RoPE (in-place on q/k), also computes q0/k0 and per-(t,h) |q|.
// ---------------------------------------------------------------------------
__global__ __launch_bounds__(64) void rms_rope_kernel(float* __restrict__ qb,
                                                      float* __restrict__ kb,
                                                      float* __restrict__ q0,
                                                      float* __restrict__ k0,
                                                      float* __restrict__ qn,
                                                      const float* __restrict__ curv) {
    const int t = blockIdx.x;
    const int hh = blockIdx.y;
    const int d = threadIdx.x;

    float* vec = (hh < NH) ? (qb + ((size_t)t * NH + hh) * HD)
                           : (kb + ((size_t)t * NKV + (hh - NH)) * HD);
    float v = vec[d];

    __shared__ float sh[64];
    __shared__ float shn[64];
    sh[d] = v * v;
    __syncthreads();
#pragma unroll
    for (int s = 32; s > 0; s >>= 1) {
        if (d < s) sh[d] += sh[d + s];
        __syncthreads();
    }
    float ss = sh[0];
    float inv = rsqrtf(ss * (1.0f / 64.0f) + EPSN);
    float xn = v * inv;
    shn[d] = xn;
    __syncthreads();

    int i = d & 31;
    float invf = expf(-(float)i * 0.28782313662425572f);  // 10000^(-i/32)
    float ang = (float)t * invf;
    float sv, cv;
    sincosf(ang, &sv, &cv);
    float outv;
    if (d < 32) outv = fmaf(shn[d], cv, shn[d + 32] * sv);
    else        outv = fmaf(-shn[i], sv, shn[d] * cv);
    vec[d] = outv;

    if (d == 0) {
        float sum2 = ss * inv * inv;  // |q_norm|^2 (RoPE preserves norm)
        float c = *curv;
        float h0 = sqrtf(1.0f / c + sum2);
        if (hh < NH) {
            q0[t * NH + hh] = h0;
            qn[t * NH + hh] = sqrtf(sum2);
        } else {
            k0[t * NKV + (hh - NH)] = h0;
        }
    }
}

// ---------------------------------------------------------------------------
// Flash-style hyperbolic attention.
// Block = 64 queries x 1 head, 256 threads (16x16), 4x4 register tiles.
// Online softmax; P staged transposed in smem aliasing the K tile.
// ---------------------------------------------------------------------------
#define BQ 64
#define LDT 68   // padded row length for 64-wide tiles

// smem floats: Qst 64*68 + Kst/Ps 64*68 + Vs 64*68 + k0s 64
#define FA_SMEM_FLOATS (3 * 64 * LDT + 64)
#define FA_SMEM_BYTES  (FA_SMEM_FLOATS * 4)

__global__ __launch_bounds__(256) void flash_attn_kernel(
    const float* __restrict__ Q, const float* __restrict__ K,
    const float* __restrict__ V, const float* __restrict__ q0a,
    const float* __restrict__ k0a, const float* __restrict__ temp,
    const float* __restrict__ curv, float* __restrict__ attn) {
    extern __shared__ float sm[];
    float* Qst = sm;                   // [64][LDT]  Q^T: Qst[d][qi]
    float* Kst = Qst + 64 * LDT;       // [64][LDT]  K^T: Kst[d][kj]; later P^T
    float* Vs  = Kst + 64 * LDT;       // [64][LDT]  V:   Vs[kj][d]
    float* k0s = Vs + 64 * LDT;        // [64]

    const int tid = threadIdx.x;
    const int tx = tid & 15;
    const int ty = tid >> 4;
    const int h = blockIdx.y;
    const int t0 = ((int)gridDim.x - 1 - (int)blockIdx.x) * BQ;  // heavy first
    const int kvh = h >> 2;

    const float c = *curv;
    const float sscale = rsqrtf(c) / temp[h];
    const float lo = 1.0f + 1e-5f;

    // load Q tile transposed (coalesced LDG.128 along d, scalar STS)
    {
        const int d4 = (tid & 15) * 4;
        for (int ql = tid >> 4; ql < BQ; ql += 16) {
            float4 qv = *(const float4*)&Q[((size_t)(t0 + ql) * NH + h) * HD + d4];
            Qst[(d4 + 0) * LDT + ql] = qv.x;
            Qst[(d4 + 1) * LDT + ql] = qv.y;
            Qst[(d4 + 2) * LDT + ql] = qv.z;
            Qst[(d4 + 3) * LDT + ql] = qv.w;
        }
    }

    float q0v[4];
#pragma unroll
    for (int i = 0; i < 4; i++) q0v[i] = q0a[(t0 + ty * 4 + i) * NH + h];

    float m_i[4], l_i[4], O[4][4];
#pragma unroll
    for (int i = 0; i < 4; i++) {
        m_i[i] = -INFINITY;
        l_i[i] = 0.f;
#pragma unroll
        for (int j = 0; j < 4; j++) O[i][j] = 0.f;
    }

    for (int c0 = 0; c0 <= t0; c0 += BQ) {
        // ---- load K (transposed) + V (natural) + k0 ----
        {
            const int d4 = (tid & 15) * 4;
            for (int kl = tid >> 4; kl < BQ; kl += 16) {
                size_t base = ((size_t)(c0 + kl) * NKV + kvh) * HD + d4;
                float4 kv = *(const float4*)&K[base];
                Kst[(d4 + 0) * LDT + kl] = kv.x;
                Kst[(d4 + 1) * LDT + kl] = kv.y;
                Kst[(d4 + 2) * LDT + kl] = kv.z;
                Kst[(d4 + 3) * LDT + kl] = kv.w;
                float4 vv = *(const float4*)&V[base];
                *(float4*)&Vs[kl * LDT + d4] = vv;
            }
            if (tid < BQ) k0s[tid] = k0a[(c0 + tid) * NKV + kvh];
        }
        __syncthreads();

        // ---- S = Q K^T (4x4 per thread) ----
        float s[4][4];
#pragma unroll
        for (int i = 0; i < 4; i++)
#pragma unroll
            for (int j = 0; j < 4; j++) s[i][j] = 0.f;

#pragma unroll 8
        for (int kk = 0; kk < BQ; kk++) {
            float4 qv = *(const float4*)&Qst[kk * LDT + ty * 4];
            float4 kv = *(const float4*)&Kst[kk * LDT + tx * 4];
            float qr[4] = {qv.x, qv.y, qv.z, qv.w};
            float kr[4] = {kv.x, kv.y, kv.z, kv.w};
#pragma unroll
            for (int i = 0; i < 4; i++)
#pragma unroll
                for (int j = 0; j < 4; j++) s[i][j] = fmaf(qr[i], kr[j], s[i][j]);
        }

        // ---- hyperbolic transform + online softmax update ----
        const bool diag = (c0 == t0);
        float k0r[4];
#pragma unroll
        for (int j = 0; j < 4; j++) k0r[j] = k0s[tx * 4 + j];

#pragma unroll
        for (int i = 0; i < 4; i++) {
            float rm = -INFINITY;
#pragma unroll
            for (int j = 0; j < 4; j++) {
                float v;
                if (diag && (tx * 4 + j > ty * 4 + i)) {
                    v = -INFINITY;
                } else {
                    float arg = fmaxf(c * fmaf(q0v[i], k0r[j], -s[i][j]), lo);
                    float dist = __logf(arg + __fsqrt_rn(fmaf(arg, arg, -1.0f)));
                    v = -dist * sscale;
                }
                s[i][j] = v;
                rm = fmaxf(rm, v);
            }
            // reduce row max over the 16 lanes holding this row
#pragma unroll
            for (int o = 8; o >= 1; o >>= 1)
                rm = fmaxf(rm, __shfl_xor_sync(0xffffffffu, rm, o));

            float mnew = fmaxf(m_i[i], rm);
            float corr = __expf(m_i[i] - mnew);
            m_i[i] = mnew;
            float rs = 0.f;
#pragma unroll
            for (int j = 0; j < 4; j++) {
                float p = __expf(s[i][j] - mnew);
                s[i][j] = p;
                rs += p;
            }
#pragma unroll
            for (int o = 8; o >= 1; o >>= 1)
                rs += __shfl_xor_sync(0xffffffffu, rs, o);
            l_i[i] = l_i[i] * corr + rs;
#pragma unroll
            for (int j = 0; j < 4; j++) O[i][j] *= corr;
        }
        __syncthreads();   // everyone done reading Kst

        // ---- write P^T into Kst region ----
        float* Ps = Kst;
#pragma unroll
        for (int j = 0; j < 4; j++) {
            float4 pv = make_float4(s[0][j], s[1][j], s[2][j], s[3][j]);
            *(float4*)&Ps[(tx * 4 + j) * LDT + ty * 4] = pv;
        }
        __syncthreads();

        // ---- O += P V (4x4 per thread) ----
#pragma unroll 8
        for (int kk = 0; kk < BQ; kk++) {
            float4 pv = *(const float4*)&Ps[kk * LDT + ty * 4];
            float4 vv = *(const float4*)&Vs[kk * LDT + tx * 4];
            float pr[4] = {pv.x, pv.y, pv.z, pv.w};
            float vr[4] = {vv.x, vv.y, vv.z, vv.w};
#pragma unroll
            for (int i = 0; i < 4; i++)
#pragma unroll
                for (int j = 0; j < 4; j++) O[i][j] = fmaf(pr[i], vr[j], O[i][j]);
        }
        __syncthreads();   // before next chunk overwrites Kst/Vs
    }

    // ---- epilogue ----
#pragma unroll
    for (int i = 0; i < 4; i++) {
        float inv = 1.0f / l_i[i];
        float4 o = make_float4(O[i][0] * inv, O[i][1] * inv, O[i][2] * inv, O[i][3] * inv);
        *(float4*)&attn[(size_t)(t0 + ty * 4 + i) * (NH * HD) + h * HD + tx * 4] = o;
    }
}

// ---------------------------------------------------------------------------
// spatial_norm = mean over (t,h) of |q|
// ---------------------------------------------------------------------------
__global__ __launch_bounds__(256) void norm_reduce_kernel(const float* __restrict__ qn,
                                                          float* __restrict__ out_scalar) {
    __shared__ float red[256];
    int tid = threadIdx.x;
    float s = 0.f;
    for (int i = tid; i < TT * NH; i += 256) s += qn[i];
    red[tid] = s;
    __syncthreads();
#pragma unroll
    for (int k = 128; k > 0; k >>= 1) {
        if (tid < k) red[tid] += red[tid + k];
        __syncthreads();
    }
    if (tid == 0) *out_scalar = red[0] * (1.0f / (float)(TT * NH));
}

// ---------------------------------------------------------------------------
// Launch
// ---------------------------------------------------------------------------
extern "C" void kernel_launch(void* const* d_in, const int* in_sizes, int n_in,
                              void* d_out, int out_size) {
    const float* x    = (const float*)d_in[0];
    const float* q_w  = (const float*)d_in[1];
    const float* k_w  = (const float*)d_in[2];
    const float* v_w  = (const float*)d_in[3];
    const float* o_w  = (const float*)d_in[4];
    const float* temp = (const float*)d_in[5];
    const float* curv = (const float*)d_in[6];
    float* out = (float*)d_out;

    float *pq, *pk, *pv, *pattn, *pq0, *pk0, *pqn;
    cudaGetSymbolAddress((void**)&pq, g_q);
    cudaGetSymbolAddress((void**)&pk, g_k);
    cudaGetSymbolAddress((void**)&pv, g_v);
    cudaGetSymbolAddress((void**)&pattn, g_attn);
    cudaGetSymbolAddress((void**)&pq0, g_q0);
    cudaGetSymbolAddress((void**)&pk0, g_k0);
    cudaGetSymbolAddress((void**)&pqn, g_qn);

    cudaFuncSetAttribute(flash_attn_kernel, cudaFuncAttributeMaxDynamicSharedMemorySize,
                         FA_SMEM_BYTES);

    // QKV projections
    sgemm_abt<<<dim3(DM / GN, TT / GM), 256>>>(x, q_w, pq, TT, DM, DM);
    sgemm_abt<<<dim3((NKV * HD) / GN, TT / GM), 256>>>(x, k_w, pk, TT, NKV * HD, DM);
    sgemm_abt<<<dim3((NKV * HD) / GN, TT / GM), 256>>>(x, v_w, pv, TT, NKV * HD, DM);

    // RMSNorm + RoPE + q0/k0 + per-head norms
    rms_rope_kernel<<<dim3(TT, NH + NKV), 64>>>(pq, pk, pq0, pk0, pqn, curv);

    // Hyperbolic causal attention (flash)
    flash_attn_kernel<<<dim3(TT / BQ, NH), 256, FA_SMEM_BYTES>>>(
        pq, pk, pv, pq0, pk0, temp, curv, pattn);

    // Output projection
    sgemm_abt<<<dim3(DM / GN, TT / GM), 256>>>(pattn, o_w, out, TT, DM, DM);

    // spatial_norm scalar
    norm_reduce_kernel<<<1, 256>>>(pqn, out + (out_size - 1));
}

// round 4
// speedup vs baseline: 2.7937x; 1.3232x over previous
#include <cuda_runtime.h>
#include <cuda_bf16.h>
#include <math.h>
#include <stdint.h>

// Problem constants
#define TT    2048
#define DM    1024
#define NH    16
#define NKV   4
#define HD    64
#define EPSN  1e-6f

// ---------------------------------------------------------------------------
// Device scratch (no cudaMalloc allowed)
// ---------------------------------------------------------------------------
__device__ float g_q[TT * NH * HD];
__device__ float g_k[TT * NKV * HD];
__device__ float g_v[TT * NKV * HD];
__device__ float g_q0[TT * NH];
__device__ float g_k0[TT * NKV];
__device__ float g_qn[TT * NH];

// bf16 hi/lo split storage (uint4 for alignment; cast to bytes)
__device__ uint4 g_xh[TT * DM / 8],  g_xl[TT * DM / 8];
__device__ uint4 g_qwh[DM * DM / 8], g_qwl[DM * DM / 8];
__device__ uint4 g_kwh[256 * DM / 8], g_kwl[256 * DM / 8];
__device__ uint4 g_vwh[256 * DM / 8], g_vwl[256 * DM / 8];
__device__ uint4 g_owh[DM * DM / 8], g_owl[DM * DM / 8];
__device__ uint4 g_ah[TT * DM / 8],  g_al[TT * DM / 8];

// ---------------------------------------------------------------------------
// mma.sync helpers (baseline PTX — no sm_103a-gated instructions)
// ---------------------------------------------------------------------------
__device__ __forceinline__ uint32_t smem_u32(const void* p) {
    uint32_t a;
    asm("{ .reg .u64 t; cvta.to.shared.u64 t, %1; cvt.u32.u64 %0, t; }" : "=r"(a) : "l"(p));
    return a;
}
__device__ __forceinline__ void ldsm_x4(uint32_t* r, uint32_t addr) {
    asm volatile("ldmatrix.sync.aligned.m8n8.x4.shared.b16 {%0,%1,%2,%3}, [%4];"
                 : "=r"(r[0]), "=r"(r[1]), "=r"(r[2]), "=r"(r[3]) : "r"(addr));
}
__device__ __forceinline__ void mma16816(float* c, const uint32_t* a, const uint32_t* b) {
    asm volatile("mma.sync.aligned.m16n8k16.row.col.f32.bf16.bf16.f32 "
                 "{%0,%1,%2,%3}, {%4,%5,%6,%7}, {%8,%9}, {%0,%1,%2,%3};"
                 : "+f"(c[0]), "+f"(c[1]), "+f"(c[2]), "+f"(c[3])
                 : "r"(a[0]), "r"(a[1]), "r"(a[2]), "r"(a[3]), "r"(b[0]), "r"(b[1]));
}
__device__ __forceinline__ void sts128(uint32_t addr, uint4 v) {
    asm volatile("st.shared.v4.b32 [%0], {%1,%2,%3,%4};"
                 :: "r"(addr), "r"(v.x), "r"(v.y), "r"(v.z), "r"(v.w) : "memory");
}
#define SW128(o) ((o) ^ (((o) >> 3) & 0x70))

// ---------------------------------------------------------------------------
// fp32 -> bf16 hi/lo split conversion (4 floats per thread)
// ---------------------------------------------------------------------------
__global__ __launch_bounds__(256) void f32_to_hl(const float* __restrict__ in,
                                                 char* __restrict__ hi,
                                                 char* __restrict__ lo, int n4) {
    int i = blockIdx.x * 256 + threadIdx.x;
    if (i >= n4) return;
    float4 v = ((const float4*)in)[i];
    union { __nv_bfloat16 b[4]; uint2 u; } h, l;
    float f[4] = {v.x, v.y, v.z, v.w};
#pragma unroll
    for (int j = 0; j < 4; j++) {
        h.b[j] = __float2bfloat16(f[j]);
        l.b[j] = __float2bfloat16(f[j] - __bfloat162float(h.b[j]));
    }
    ((uint2*)hi)[i] = h.u;
    ((uint2*)lo)[i] = l.u;
}

// ---------------------------------------------------------------------------
// HMMA bf16 hi/lo-split GEMM: C[M,N] = A[M,K] * B[N,K]^T  (fp32 out)
// CTA tile 128x128, BK=64, 256 threads (8 warps 4x2), warp tile 32x64.
// smem: 4 tiles (Ah, Al, Bh, Bl) of [128][64] bf16, SW128 swizzled.
// ---------------------------------------------------------------------------
#define BKG 64
#define TILE_B 16384
#define GEMM_SMEM_BYTES (4 * TILE_B + 1024)

__global__ __launch_bounds__(256) void gemm_mma_hl(
    const char* __restrict__ Ah, const char* __restrict__ Al,
    const char* __restrict__ Bh, const char* __restrict__ Bl,
    float* __restrict__ C, int Ntot, int K) {
    extern __shared__ __align__(16) char sm[];
    uint32_t ts = (smem_u32(sm) + 1023) & ~1023u;

    const int tid = threadIdx.x;
    const int lane = tid & 31;
    const int wid = tid >> 5;
    const int wm = wid >> 1;        // 0..3 -> m offset wm*32
    const int wn = wid & 1;         // 0..1 -> n offset wn*64
    const int m0 = blockIdx.y * 128;
    const int n0 = blockIdx.x * 128;
    const size_t K2 = (size_t)K * 2;

    const uint32_t tAh = ts, tAl = ts + TILE_B, tBh = ts + 2 * TILE_B, tBl = ts + 3 * TILE_B;

    const char* srcs[4] = { Ah + (size_t)m0 * K2, Al + (size_t)m0 * K2,
                            Bh + (size_t)n0 * K2, Bl + (size_t)n0 * K2 };

    // producer indices
    const int u = tid & 7;          // 16B unit within the 128B row
    const int r0 = tid >> 3;        // 0..31

    float acc[2][8][4];
#pragma unroll
    for (int a = 0; a < 2; a++)
#pragma unroll
        for (int b = 0; b < 8; b++)
#pragma unroll
            for (int cc = 0; cc < 4; cc++) acc[a][b][cc] = 0.f;

    // fragment smem offsets (per thread, constant across chunks except ks)
    const int amat = lane >> 3, arow = lane & 7;

    const int nchunks = K / BKG;
    for (int ch = 0; ch < nchunks; ch++) {
        __syncthreads();
        const size_t koff = (size_t)ch * 128 + u * 16;
#pragma unroll
        for (int t = 0; t < 4; t++) {
            const char* src = srcs[t] + koff;
            const uint32_t tb = ts + t * TILE_B;
#pragma unroll
            for (int it = 0; it < 4; it++) {
                const int row = it * 32 + r0;
                uint4 v = *(const uint4*)(src + (size_t)row * K2);
                uint32_t off = row * 128 + u * 16;
                sts128(tb + SW128(off), v);
            }
        }
        __syncthreads();

#pragma unroll
        for (int ks = 0; ks < 4; ks++) {
            uint32_t ah[2][4], al[2][4], bh[4][4], bl[4][4];
#pragma unroll
            for (int mb = 0; mb < 2; mb++) {
                int m = wm * 32 + mb * 16 + (amat & 1) * 8 + arow;
                int kb = ks * 32 + (amat >> 1) * 16;
                uint32_t off = SW128((uint32_t)(m * 128 + kb));
                ldsm_x4(ah[mb], tAh + off);
                ldsm_x4(al[mb], tAl + off);
            }
#pragma unroll
            for (int p = 0; p < 4; p++) {
                int n = wn * 64 + p * 16 + (amat >> 1) * 8 + arow;
                int kb = ks * 32 + (amat & 1) * 16;
                uint32_t off = SW128((uint32_t)(n * 128 + kb));
                ldsm_x4(bh[p], tBh + off);
                ldsm_x4(bl[p], tBl + off);
            }
#pragma unroll
            for (int mb = 0; mb < 2; mb++)
#pragma unroll
                for (int p = 0; p < 4; p++) {
                    mma16816(acc[mb][2 * p],     ah[mb], &bh[p][0]);
                    mma16816(acc[mb][2 * p + 1], ah[mb], &bh[p][2]);
                    mma16816(acc[mb][2 * p],     ah[mb], &bl[p][0]);
                    mma16816(acc[mb][2 * p + 1], ah[mb], &bl[p][2]);
                    mma16816(acc[mb][2 * p],     al[mb], &bh[p][0]);
                    mma16816(acc[mb][2 * p + 1], al[mb], &bh[p][2]);
                }
        }
    }

    // epilogue: fragment -> global
    const int crow = lane >> 2;            // 0..7
    const int ccol = (lane & 3) * 2;
#pragma unroll
    for (int mb = 0; mb < 2; mb++) {
#pragma unroll
        for (int nb = 0; nb < 8; nb++) {
            int m = m0 + wm * 32 + mb * 16 + crow;
            int n = n0 + wn * 64 + nb * 8 + ccol;
            *(float2*)&C[(size_t)m * Ntot + n]       = make_float2(acc[mb][nb][0], acc[mb][nb][1]);
            *(float2*)&C[(size_t)(m + 8) * Ntot + n] = make_float2(acc[mb][nb][2], acc[mb][nb][3]);
        }
    }
}

// ---------------------------------------------------------------------------
// RMSNorm + RoPE (warp per vector), q0/k0 and |q| side outputs.
// ---------------------------------------------------------------------------
__global__ __launch_bounds__(256) void rms_rope_kernel(float* __restrict__ qb,
                                                       float* __restrict__ kb,
                                                       float* __restrict__ q0,
                                                       float* __restrict__ k0,
                                                       float* __restrict__ qn,
                                                       const float* __restrict__ curv) {
    const int wid = threadIdx.x >> 5;
    const int lane = threadIdx.x & 31;
    const int vi = blockIdx.x * 8 + wid;
    const int t = vi & 2047;
    const int hh = vi >> 11;

    float* vec = (hh < NH) ? (qb + ((size_t)t * NH + hh) * HD)
                           : (kb + ((size_t)t * NKV + (hh - NH)) * HD);
    float x1 = vec[lane], x2 = vec[lane + 32];
    float ss = x1 * x1 + x2 * x2;
#pragma unroll
    for (int o = 16; o >= 1; o >>= 1) ss += __shfl_xor_sync(0xffffffffu, ss, o);

    float inv = rsqrtf(ss * (1.0f / 64.0f) + EPSN);
    x1 *= inv; x2 *= inv;

    float invf = expf(-(float)lane * 0.28782313662425572f);
    float ang = (float)t * invf;
    float sv, cv;
    sincosf(ang, &sv, &cv);
    vec[lane]      = fmaf(x1, cv, x2 * sv);
    vec[lane + 32] = fmaf(-x1, sv, x2 * cv);

    if (lane == 0) {
        float sum2 = ss * inv * inv;
        float c = *curv;
        float h0 = sqrtf(1.0f / c + sum2);
        if (hh < NH) {
            q0[t * NH + hh] = h0;
            qn[t * NH + hh] = sqrtf(sum2);
        } else {
            k0[t * NKV + (hh - NH)] = h0;
        }
    }
}

// ---------------------------------------------------------------------------
// Flash-style hyperbolic attention (fp32), emits bf16 hi/lo of attn output.
// ---------------------------------------------------------------------------
#define BQ 64
#define LDT 68
#define FA_SMEM_FLOATS (3 * 64 * LDT + 64)
#define FA_SMEM_BYTES  (FA_SMEM_FLOATS * 4)

__global__ __launch_bounds__(256) void flash_attn_kernel(
    const float* __restrict__ Q, const float* __restrict__ K,
    const float* __restrict__ V, const float* __restrict__ q0a,
    const float* __restrict__ k0a, const float* __restrict__ temp,
    const float* __restrict__ curv,
    char* __restrict__ ah, char* __restrict__ al) {
    extern __shared__ float smf[];
    float* Qst = smf;
    float* Kst = Qst + 64 * LDT;
    float* Vs  = Kst + 64 * LDT;
    float* k0s = Vs + 64 * LDT;

    const int tid = threadIdx.x;
    const int tx = tid & 15;
    const int ty = tid >> 4;
    const int h = blockIdx.y;
    const int t0 = ((int)gridDim.x - 1 - (int)blockIdx.x) * BQ;
    const int kvh = h >> 2;

    const float c = *curv;
    const float sscale = rsqrtf(c) / temp[h];
    const float lo = 1.0f + 1e-5f;

    {
        const int d4 = (tid & 15) * 4;
        for (int ql = tid >> 4; ql < BQ; ql += 16) {
            float4 qv = *(const float4*)&Q[((size_t)(t0 + ql) * NH + h) * HD + d4];
            Qst[(d4 + 0) * LDT + ql] = qv.x;
            Qst[(d4 + 1) * LDT + ql] = qv.y;
            Qst[(d4 + 2) * LDT + ql] = qv.z;
            Qst[(d4 + 3) * LDT + ql] = qv.w;
        }
    }

    float q0v[4];
#pragma unroll
    for (int i = 0; i < 4; i++) q0v[i] = q0a[(t0 + ty * 4 + i) * NH + h];

    float m_i[4], l_i[4], O[4][4];
#pragma unroll
    for (int i = 0; i < 4; i++) {
        m_i[i] = -INFINITY; l_i[i] = 0.f;
#pragma unroll
        for (int j = 0; j < 4; j++) O[i][j] = 0.f;
    }

    for (int c0 = 0; c0 <= t0; c0 += BQ) {
        {
            const int d4 = (tid & 15) * 4;
            for (int kl = tid >> 4; kl < BQ; kl += 16) {
                size_t bidx = ((size_t)(c0 + kl) * NKV + kvh) * HD + d4;
                float4 kv = *(const float4*)&K[bidx];
                Kst[(d4 + 0) * LDT + kl] = kv.x;
                Kst[(d4 + 1) * LDT + kl] = kv.y;
                Kst[(d4 + 2) * LDT + kl] = kv.z;
                Kst[(d4 + 3) * LDT + kl] = kv.w;
                float4 vv = *(const float4*)&V[bidx];
                *(float4*)&Vs[kl * LDT + d4] = vv;
            }
            if (tid < BQ) k0s[tid] = k0a[(c0 + tid) * NKV + kvh];
        }
        __syncthreads();

        float s[4][4];
#pragma unroll
        for (int i = 0; i < 4; i++)
#pragma unroll
            for (int j = 0; j < 4; j++) s[i][j] = 0.f;

#pragma unroll 8
        for (int kk = 0; kk < BQ; kk++) {
            float4 qv = *(const float4*)&Qst[kk * LDT + ty * 4];
            float4 kv = *(const float4*)&Kst[kk * LDT + tx * 4];
            float qr[4] = {qv.x, qv.y, qv.z, qv.w};
            float kr[4] = {kv.x, kv.y, kv.z, kv.w};
#pragma unroll
            for (int i = 0; i < 4; i++)
#pragma unroll
                for (int j = 0; j < 4; j++) s[i][j] = fmaf(qr[i], kr[j], s[i][j]);
        }

        const bool diag = (c0 == t0);
        float k0r[4];
#pragma unroll
        for (int j = 0; j < 4; j++) k0r[j] = k0s[tx * 4 + j];

#pragma unroll
        for (int i = 0; i < 4; i++) {
            float rm = -INFINITY;
#pragma unroll
            for (int j = 0; j < 4; j++) {
                float v;
                if (diag && (tx * 4 + j > ty * 4 + i)) {
                    v = -INFINITY;
                } else {
                    float arg = fmaxf(c * fmaf(q0v[i], k0r[j], -s[i][j]), lo);
                    float dist = __logf(arg + __fsqrt_rn(fmaf(arg, arg, -1.0f)));
                    v = -dist * sscale;
                }
                s[i][j] = v;
                rm = fmaxf(rm, v);
            }
#pragma unroll
            for (int o = 8; o >= 1; o >>= 1)
                rm = fmaxf(rm, __shfl_xor_sync(0xffffffffu, rm, o));

            float mnew = fmaxf(m_i[i], rm);
            float corr = __expf(m_i[i] - mnew);
            m_i[i] = mnew;
            float rs = 0.f;
#pragma unroll
            for (int j = 0; j < 4; j++) {
                float p = __expf(s[i][j] - mnew);
                s[i][j] = p;
                rs += p;
            }
#pragma unroll
            for (int o = 8; o >= 1; o >>= 1)
                rs += __shfl_xor_sync(0xffffffffu, rs, o);
            l_i[i] = l_i[i] * corr + rs;
#pragma unroll
            for (int j = 0; j < 4; j++) O[i][j] *= corr;
        }
        __syncthreads();

        float* Ps = Kst;
#pragma unroll
        for (int j = 0; j < 4; j++) {
            float4 pv = make_float4(s[0][j], s[1][j], s[2][j], s[3][j]);
            *(float4*)&Ps[(tx * 4 + j) * LDT + ty * 4] = pv;
        }
        __syncthreads();

#pragma unroll 8
        for (int kk = 0; kk < BQ; kk++) {
            float4 pv = *(const float4*)&Ps[kk * LDT + ty * 4];
            float4 vv = *(const float4*)&Vs[kk * LDT + tx * 4];
            float pr[4] = {pv.x, pv.y, pv.z, pv.w};
            float vr[4] = {vv.x, vv.y, vv.z, vv.w};
#pragma unroll
            for (int i = 0; i < 4; i++)
#pragma unroll
                for (int j = 0; j < 4; j++) O[i][j] = fmaf(pr[i], vr[j], O[i][j]);
        }
        __syncthreads();
    }

#pragma unroll
    for (int i = 0; i < 4; i++) {
        float inv = 1.0f / l_i[i];
        float o[4] = {O[i][0] * inv, O[i][1] * inv, O[i][2] * inv, O[i][3] * inv};
        union { __nv_bfloat16 b[4]; uint2 u; } hv, lv;
#pragma unroll
        for (int j = 0; j < 4; j++) {
            hv.b[j] = __float2bfloat16(o[j]);
            lv.b[j] = __float2bfloat16(o[j] - __bfloat162float(hv.b[j]));
        }
        size_t idx = (size_t)(t0 + ty * 4 + i) * DM + h * HD + tx * 4;
        *(uint2*)(ah + idx * 2) = hv.u;
        *(uint2*)(al + idx * 2) = lv.u;
    }
}

// ---------------------------------------------------------------------------
// spatial_norm = mean over (t,h) of |q|
// ---------------------------------------------------------------------------
__global__ __launch_bounds__(256) void norm_reduce_kernel(const float* __restrict__ qn,
                                                          float* __restrict__ out_scalar) {
    __shared__ float red[256];
    int tid = threadIdx.x;
    float s = 0.f;
    for (int i = tid; i < TT * NH; i += 256) s += qn[i];
    red[tid] = s;
    __syncthreads();
#pragma unroll
    for (int k = 128; k > 0; k >>= 1) {
        if (tid < k) red[tid] += red[tid + k];
        __syncthreads();
    }
    if (tid == 0) *out_scalar = red[0] * (1.0f / (float)(TT * NH));
}

// ---------------------------------------------------------------------------
// Launch
// ---------------------------------------------------------------------------
extern "C" void kernel_launch(void* const* d_in, const int* in_sizes, int n_in,
                              void* d_out, int out_size) {
    const float* x    = (const float*)d_in[0];
    const float* q_w  = (const float*)d_in[1];
    const float* k_w  = (const float*)d_in[2];
    const float* v_w  = (const float*)d_in[3];
    const float* o_w  = (const float*)d_in[4];
    const float* temp = (const float*)d_in[5];
    const float* curv = (const float*)d_in[6];
    float* out = (float*)d_out;

    float *pq, *pk, *pv, *pq0, *pk0, *pqn;
    char *xh, *xl, *qwh, *qwl, *kwh, *kwl, *vwh, *vwl, *owh, *owl, *ah, *al;
    cudaGetSymbolAddress((void**)&pq, g_q);
    cudaGetSymbolAddress((void**)&pk, g_k);
    cudaGetSymbolAddress((void**)&pv, g_v);
    cudaGetSymbolAddress((void**)&pq0, g_q0);
    cudaGetSymbolAddress((void**)&pk0, g_k0);
    cudaGetSymbolAddress((void**)&pqn, g_qn);
    cudaGetSymbolAddress((void**)&xh, g_xh);
    cudaGetSymbolAddress((void**)&xl, g_xl);
    cudaGetSymbolAddress((void**)&qwh, g_qwh);
    cudaGetSymbolAddress((void**)&qwl, g_qwl);
    cudaGetSymbolAddress((void**)&kwh, g_kwh);
    cudaGetSymbolAddress((void**)&kwl, g_kwl);
    cudaGetSymbolAddress((void**)&vwh, g_vwh);
    cudaGetSymbolAddress((void**)&vwl, g_vwl);
    cudaGetSymbolAddress((void**)&owh, g_owh);
    cudaGetSymbolAddress((void**)&owl, g_owl);
    cudaGetSymbolAddress((void**)&ah, g_ah);
    cudaGetSymbolAddress((void**)&al, g_al);

    cudaFuncSetAttribute(flash_attn_kernel, cudaFuncAttributeMaxDynamicSharedMemorySize,
                         FA_SMEM_BYTES);
    cudaFuncSetAttribute(gemm_mma_hl, cudaFuncAttributeMaxDynamicSharedMemorySize,
                         GEMM_SMEM_BYTES);

    // fp32 -> bf16 hi/lo conversions
    f32_to_hl<<<TT * DM / 4 / 256, 256>>>(x, xh, xl, TT * DM / 4);
    f32_to_hl<<<DM * DM / 4 / 256, 256>>>(q_w, qwh, qwl, DM * DM / 4);
    f32_to_hl<<<256 * DM / 4 / 256, 256>>>(k_w, kwh, kwl, 256 * DM / 4);
    f32_to_hl<<<256 * DM / 4 / 256, 256>>>(v_w, vwh, vwl, 256 * DM / 4);
    f32_to_hl<<<DM * DM / 4 / 256, 256>>>(o_w, owh, owl, DM * DM / 4);

    // QKV projections (HMMA)
    gemm_mma_hl<<<dim3(DM / 128, TT / 128), 256, GEMM_SMEM_BYTES>>>(xh, xl, qwh, qwl, pq, DM, DM);
    gemm_mma_hl<<<dim3(256 / 128, TT / 128), 256, GEMM_SMEM_BYTES>>>(xh, xl, kwh, kwl, pk, 256, DM);
    gemm_mma_hl<<<dim3(256 / 128, TT / 128), 256, GEMM_SMEM_BYTES>>>(xh, xl, vwh, vwl, pv, 256, DM);

    // RMSNorm + RoPE + q0/k0 + per-head norms
    rms_rope_kernel<<<TT * (NH + NKV) / 8, 256>>>(pq, pk, pq0, pk0, pqn, curv);

    // Hyperbolic causal attention (flash, fp32, bf16 hi/lo out)
    flash_attn_kernel<<<dim3(TT / BQ, NH), 256, FA_SMEM_BYTES>>>(
        pq, pk, pv, pq0, pk0, temp, curv, ah, al);

    // Output projection (HMMA)
    gemm_mma_hl<<<dim3(DM / 128, TT / 128), 256, GEMM_SMEM_BYTES>>>(ah, al, owh, owl, out, DM, DM);

    // spatial_norm scalar
    norm_reduce_kernel<<<1, 256>>>(pqn, out + (out_size - 1));
}

// round 6
// speedup vs baseline: 3.7243x; 1.3331x over previous
#include <cuda_runtime.h>
#include <cuda_bf16.h>
#include <math.h>
#include <stdint.h>

// Problem constants
#define TT    2048
#define DM    1024
#define NH    16
#define NKV   4
#define HD    64
#define EPSN  1e-6f

// ---------------------------------------------------------------------------
// Device scratch (no cudaMalloc allowed)
// ---------------------------------------------------------------------------
__device__ float g_q[TT * NH * HD];
__device__ float g_k[TT * NKV * HD];
__device__ float g_v[TT * NKV * HD];
__device__ float g_q0[TT * NH];
__device__ float g_k0[TT * NKV];
__device__ float g_qn[TT * NH];

// bf16 hi/lo split storage (uint4 for alignment; cast to bytes)
__device__ uint4 g_xh[TT * DM / 8],  g_xl[TT * DM / 8];
__device__ uint4 g_qwh[DM * DM / 8], g_qwl[DM * DM / 8];
__device__ uint4 g_kwh[256 * DM / 8], g_kwl[256 * DM / 8];
__device__ uint4 g_vwh[256 * DM / 8], g_vwl[256 * DM / 8];
__device__ uint4 g_owh[DM * DM / 8], g_owl[DM * DM / 8];
__device__ uint4 g_ah[TT * DM / 8],  g_al[TT * DM / 8];
// bf16 q/k/v for attention
__device__ uint4 g_qbh[TT * NH * HD / 8],  g_qbl[TT * NH * HD / 8];
__device__ uint4 g_kbh[TT * NKV * HD / 8], g_kbl[TT * NKV * HD / 8];
__device__ uint4 g_vbh[TT * NKV * HD / 8], g_vbl[TT * NKV * HD / 8];

// ---------------------------------------------------------------------------
// mma.sync helpers (baseline PTX — no sm_103a-gated instructions)
// ---------------------------------------------------------------------------
__device__ __forceinline__ uint32_t smem_u32(const void* p) {
    uint32_t a;
    asm("{ .reg .u64 t; cvta.to.shared.u64 t, %1; cvt.u32.u64 %0, t; }" : "=r"(a) : "l"(p));
    return a;
}
__device__ __forceinline__ void ldsm_x4(uint32_t* r, uint32_t addr) {
    asm volatile("ldmatrix.sync.aligned.m8n8.x4.shared.b16 {%0,%1,%2,%3}, [%4];"
                 : "=r"(r[0]), "=r"(r[1]), "=r"(r[2]), "=r"(r[3]) : "r"(addr));
}
__device__ __forceinline__ void ldsm_x4_t(uint32_t* r, uint32_t addr) {
    asm volatile("ldmatrix.sync.aligned.m8n8.x4.trans.shared.b16 {%0,%1,%2,%3}, [%4];"
                 : "=r"(r[0]), "=r"(r[1]), "=r"(r[2]), "=r"(r[3]) : "r"(addr));
}
__device__ __forceinline__ void mma16816(float* c, const uint32_t* a, uint32_t b0, uint32_t b1) {
    asm volatile("mma.sync.aligned.m16n8k16.row.col.f32.bf16.bf16.f32 "
                 "{%0,%1,%2,%3}, {%4,%5,%6,%7}, {%8,%9}, {%0,%1,%2,%3};"
                 : "+f"(c[0]), "+f"(c[1]), "+f"(c[2]), "+f"(c[3])
                 : "r"(a[0]), "r"(a[1]), "r"(a[2]), "r"(a[3]), "r"(b0), "r"(b1));
}
__device__ __forceinline__ void sts128(uint32_t addr, uint4 v) {
    asm volatile("st.shared.v4.b32 [%0], {%1,%2,%3,%4};"
                 :: "r"(addr), "r"(v.x), "r"(v.y), "r"(v.z), "r"(v.w) : "memory");
}
#define SW128(o) ((o) ^ (((o) >> 3) & 0x70))

__device__ __forceinline__ uint16_t bf_hi(float f, float& rem) {
    __nv_bfloat16 h = __float2bfloat16(f);
    rem = f - __bfloat162float(h);
    union { __nv_bfloat16 b; uint16_t u; } cv; cv.b = h;
    return cv.u;
}
__device__ __forceinline__ uint16_t bf_of(float f) {
    union { __nv_bfloat16 b; uint16_t u; } cv; cv.b = __float2bfloat16(f);
    return cv.u;
}

// ---------------------------------------------------------------------------
// fp32 -> bf16 hi/lo split conversion (4 floats per thread)
// ---------------------------------------------------------------------------
__global__ __launch_bounds__(256) void f32_to_hl(const float* __restrict__ in,
                                                 char* __restrict__ hi,
                                                 char* __restrict__ lo, int n4) {
    int i = blockIdx.x * 256 + threadIdx.x;
    if (i >= n4) return;
    float4 v = ((const float4*)in)[i];
    union { __nv_bfloat16 b[4]; uint2 u; } h, l;
    float f[4] = {v.x, v.y, v.z, v.w};
#pragma unroll
    for (int j = 0; j < 4; j++) {
        h.b[j] = __float2bfloat16(f[j]);
        l.b[j] = __float2bfloat16(f[j] - __bfloat162float(h.b[j]));
    }
    ((uint2*)hi)[i] = h.u;
    ((uint2*)lo)[i] = l.u;
}

// ---------------------------------------------------------------------------
// HMMA bf16 hi/lo-split GEMM: C[M,N] = A[M,K] * B[N,K]^T  (fp32 out)
// ---------------------------------------------------------------------------
#define BKG 64
#define TILE_B 16384
#define GEMM_SMEM_BYTES (4 * TILE_B + 1024)

__global__ __launch_bounds__(256) void gemm_mma_hl(
    const char* __restrict__ Ah, const char* __restrict__ Al,
    const char* __restrict__ Bh, const char* __restrict__ Bl,
    float* __restrict__ C, int Ntot, int K) {
    extern __shared__ __align__(16) char sm[];
    uint32_t ts = (smem_u32(sm) + 1023) & ~1023u;

    const int tid = threadIdx.x;
    const int lane = tid & 31;
    const int wid = tid >> 5;
    const int wm = wid >> 1;
    const int wn = wid & 1;
    const int m0 = blockIdx.y * 128;
    const int n0 = blockIdx.x * 128;
    const size_t K2 = (size_t)K * 2;

    const uint32_t tAh = ts, tAl = ts + TILE_B, tBh = ts + 2 * TILE_B, tBl = ts + 3 * TILE_B;

    const char* srcs[4] = { Ah + (size_t)m0 * K2, Al + (size_t)m0 * K2,
                            Bh + (size_t)n0 * K2, Bl + (size_t)n0 * K2 };

    const int u = tid & 7;
    const int r0 = tid >> 3;

    float acc[2][8][4];
#pragma unroll
    for (int a = 0; a < 2; a++)
#pragma unroll
        for (int b = 0; b < 8; b++)
#pragma unroll
            for (int cc = 0; cc < 4; cc++) acc[a][b][cc] = 0.f;

    const int amat = lane >> 3, arow = lane & 7;

    const int nchunks = K / BKG;
    for (int ch = 0; ch < nchunks; ch++) {
        __syncthreads();
        const size_t koff = (size_t)ch * 128 + u * 16;
#pragma unroll
        for (int t = 0; t < 4; t++) {
            const char* src = srcs[t] + koff;
            const uint32_t tb = ts + t * TILE_B;
#pragma unroll
            for (int it = 0; it < 4; it++) {
                const int row = it * 32 + r0;
                uint4 v = *(const uint4*)(src + (size_t)row * K2);
                uint32_t off = row * 128 + u * 16;
                sts128(tb + SW128(off), v);
            }
        }
        __syncthreads();

#pragma unroll
        for (int ks = 0; ks < 4; ks++) {
            uint32_t ah[2][4], al[2][4], bh[4][4], bl[4][4];
#pragma unroll
            for (int mb = 0; mb < 2; mb++) {
                int m = wm * 32 + mb * 16 + (amat & 1) * 8 + arow;
                int kb = ks * 32 + (amat >> 1) * 16;
                uint32_t off = SW128((uint32_t)(m * 128 + kb));
                ldsm_x4(ah[mb], tAh + off);
                ldsm_x4(al[mb], tAl + off);
            }
#pragma unroll
            for (int p = 0; p < 4; p++) {
                int n = wn * 64 + p * 16 + (amat >> 1) * 8 + arow;
                int kb = ks * 32 + (amat & 1) * 16;
                uint32_t off = SW128((uint32_t)(n * 128 + kb));
                ldsm_x4(bh[p], tBh + off);
                ldsm_x4(bl[p], tBl + off);
            }
#pragma unroll
            for (int mb = 0; mb < 2; mb++)
#pragma unroll
                for (int p = 0; p < 4; p++) {
                    mma16816(acc[mb][2 * p],     ah[mb], bh[p][0], bh[p][1]);
                    mma16816(acc[mb][2 * p + 1], ah[mb], bh[p][2], bh[p][3]);
                    mma16816(acc[mb][2 * p],     ah[mb], bl[p][0], bl[p][1]);
                    mma16816(acc[mb][2 * p + 1], ah[mb], bl[p][2], bl[p][3]);
                    mma16816(acc[mb][2 * p],     al[mb], bh[p][0], bh[p][1]);
                    mma16816(acc[mb][2 * p + 1], al[mb], bh[p][2], bh[p][3]);
                }
        }
    }

    const int crow = lane >> 2;
    const int ccol = (lane & 3) * 2;
#pragma unroll
    for (int mb = 0; mb < 2; mb++) {
#pragma unroll
        for (int nb = 0; nb < 8; nb++) {
            int m = m0 + wm * 32 + mb * 16 + crow;
            int n = n0 + wn * 64 + nb * 8 + ccol;
            *(float2*)&C[(size_t)m * Ntot + n]       = make_float2(acc[mb][nb][0], acc[mb][nb][1]);
            *(float2*)&C[(size_t)(m + 8) * Ntot + n] = make_float2(acc[mb][nb][2], acc[mb][nb][3]);
        }
    }
}

// ---------------------------------------------------------------------------
// RMSNorm + RoPE (warp per vector); writes bf16 hi/lo q/k, q0/k0, |q|.
// ---------------------------------------------------------------------------
__global__ __launch_bounds__(256) void rms_rope_kernel(
    const float* __restrict__ qf, const float* __restrict__ kf,
    char* __restrict__ qbh, char* __restrict__ qbl,
    char* __restrict__ kbh, char* __restrict__ kbl,
    float* __restrict__ q0, float* __restrict__ k0,
    float* __restrict__ qn, const float* __restrict__ curv) {
    const int wid = threadIdx.x >> 5;
    const int lane = threadIdx.x & 31;
    const int vi = blockIdx.x * 8 + wid;
    const int t = vi & 2047;
    const int hh = vi >> 11;

    const float* vec;
    size_t obase;
    char *oh, *ol;
    if (hh < NH) {
        size_t idx = (size_t)t * NH + hh;
        vec = qf + idx * HD; obase = idx * HD; oh = qbh; ol = qbl;
    } else {
        size_t idx = (size_t)t * NKV + (hh - NH);
        vec = kf + idx * HD; obase = idx * HD; oh = kbh; ol = kbl;
    }
    float x1 = vec[lane], x2 = vec[lane + 32];
    float ss = x1 * x1 + x2 * x2;
#pragma unroll
    for (int o = 16; o >= 1; o >>= 1) ss += __shfl_xor_sync(0xffffffffu, ss, o);

    float inv = rsqrtf(ss * (1.0f / 64.0f) + EPSN);
    x1 *= inv; x2 *= inv;

    float invf = expf(-(float)lane * 0.28782313662425572f);
    float ang = (float)t * invf;
    float sv, cv;
    sincosf(ang, &sv, &cv);
    float o1 = fmaf(x1, cv, x2 * sv);
    float o2 = fmaf(-x1, sv, x2 * cv);

    float r1, r2;
    uint16_t h1 = bf_hi(o1, r1), h2 = bf_hi(o2, r2);
    ((uint16_t*)oh)[obase + lane]      = h1;
    ((uint16_t*)oh)[obase + lane + 32] = h2;
    ((uint16_t*)ol)[obase + lane]      = bf_of(r1);
    ((uint16_t*)ol)[obase + lane + 32] = bf_of(r2);

    if (lane == 0) {
        float sum2 = ss * inv * inv;
        float c = *curv;
        float h0 = sqrtf(1.0f / c + sum2);
        if (hh < NH) {
            q0[t * NH + hh] = h0;
            qn[t * NH + hh] = sqrtf(sum2);
        } else {
            k0[t * NKV + (hh - NH)] = h0;
        }
    }
}

// ---------------------------------------------------------------------------
// Tensor-core flash hyperbolic attention.
// Block = 64 queries x 1 head, 128 threads (4 warps, 16 q-rows each).
// S = QK^T 3-term bf16 hi/lo mma; max-free softmax (w = z^-s in (0,1]);
// P repacked in registers; O += P V 3-term mma.
// ---------------------------------------------------------------------------
struct FaSmem {
    char kh[8192], kl[8192], vh[8192], vl[8192];
    float q0s[64], k0s[64];
};

__global__ __launch_bounds__(128) void flash_attn_mma(
    const char* __restrict__ Qh, const char* __restrict__ Ql,
    const char* __restrict__ Kh, const char* __restrict__ Kl,
    const char* __restrict__ Vh, const char* __restrict__ Vl,
    const float* __restrict__ q0a, const float* __restrict__ k0a,
    const float* __restrict__ temp, const float* __restrict__ curv,
    char* __restrict__ ah, char* __restrict__ al) {
    __shared__ __align__(1024) FaSmem s;

    const int tid = threadIdx.x;
    const int lane = tid & 31;
    const int wp = tid >> 5;
    const int h = blockIdx.y;
    const int t0 = ((int)gridDim.x - 1 - (int)blockIdx.x) * 64;
    const int kvh = h >> 2;

    const float c = *curv;
    const float sscale = rsqrtf(c) / temp[h];
    const float lo = 1.0f + 1e-5f;

    const uint32_t sKh = smem_u32(s.kh), sKl = smem_u32(s.kl);
    const uint32_t sVh = smem_u32(s.vh), sVl = smem_u32(s.vl);

    // ---- stage Q tile (hi/lo) into kh/kl buffers ----
    {
        const char* qs[2] = { Qh, Ql };
        const uint32_t db[2] = { sKh, sKl };
        for (int idx = tid; idx < 1024; idx += 128) {
            int mtx = idx >> 9, rem = idx & 511, row = rem >> 3, u = rem & 7;
            const char* src = qs[mtx] + ((size_t)(t0 + row) * NH + h) * 128 + u * 16;
            sts128(db[mtx] + SW128((uint32_t)(row * 128 + u * 16)), *(const uint4*)src);
        }
        if (tid < 64) s.q0s[tid] = q0a[(t0 + tid) * NH + h];
    }
    __syncthreads();

    // ---- Q fragments to registers ----
    uint32_t qa_h[4][4], qa_l[4][4];
    {
        const int g = lane >> 3, lr = lane & 7;
        const int row = 16 * wp + (g & 1) * 8 + lr;
#pragma unroll
        for (int ks = 0; ks < 4; ks++) {
            uint32_t off = SW128((uint32_t)(row * 128 + ks * 32 + (g >> 1) * 16));
            ldsm_x4(qa_h[ks], sKh + off);
            ldsm_x4(qa_l[ks], sKl + off);
        }
    }
    const int r = lane >> 2;
    const int colb = (lane & 3) * 2;
    const float q0r0 = s.q0s[16 * wp + r];
    const float q0r1 = s.q0s[16 * wp + 8 + r];
    __syncthreads();

    float o[8][4];
#pragma unroll
    for (int i = 0; i < 8; i++)
#pragma unroll
        for (int j = 0; j < 4; j++) o[i][j] = 0.f;
    float lsum0 = 0.f, lsum1 = 0.f;

    const char* kvsrc[4] = { Kh + kvh * 128, Kl + kvh * 128, Vh + kvh * 128, Vl + kvh * 128 };
    const uint32_t kvdst[4] = { sKh, sKl, sVh, sVl };

    for (int c0 = 0; c0 <= t0; c0 += 64) {
        // ---- producer: K/V tiles hi/lo ----
        for (int idx = tid; idx < 2048; idx += 128) {
            int mtx = idx >> 9, rem = idx & 511, row = rem >> 3, u = rem & 7;
            const char* src = kvsrc[mtx] + (size_t)(c0 + row) * 512 + u * 16;
            sts128(kvdst[mtx] + SW128((uint32_t)(row * 128 + u * 16)), *(const uint4*)src);
        }
        if (tid < 64) s.k0s[tid] = k0a[(c0 + tid) * NKV + kvh];
        __syncthreads();

        // ---- S = Q K^T (3-term) ----
        float sc[8][4];
#pragma unroll
        for (int i = 0; i < 8; i++)
#pragma unroll
            for (int j = 0; j < 4; j++) sc[i][j] = 0.f;
        {
            const int g = lane >> 3, lr = lane & 7;
#pragma unroll
            for (int ks = 0; ks < 4; ks++) {
                const int dby = ks * 32 + (g >> 1) * 16;
#pragma unroll
                for (int p = 0; p < 4; p++) {
                    const int row = p * 16 + (g & 1) * 8 + lr;
                    uint32_t off = SW128((uint32_t)(row * 128 + dby));
                    uint32_t bh[4], bl[4];
                    ldsm_x4(bh, sKh + off);
                    ldsm_x4(bl, sKl + off);
                    mma16816(sc[2 * p],     qa_h[ks], bh[0], bh[2]);
                    mma16816(sc[2 * p + 1], qa_h[ks], bh[1], bh[3]);
                    mma16816(sc[2 * p],     qa_h[ks], bl[0], bl[2]);
                    mma16816(sc[2 * p + 1], qa_h[ks], bl[1], bl[3]);
                    mma16816(sc[2 * p],     qa_l[ks], bh[0], bh[2]);
                    mma16816(sc[2 * p + 1], qa_l[ks], bh[1], bh[3]);
                }
            }
        }

        // ---- hyperbolic transform -> weights in (0,1]; pack P hi/lo ----
        const bool diag = (c0 == t0);
        const int rl0 = 16 * wp + r, rl1 = rl0 + 8;
        uint32_t ph[4][4], pl[4][4];
#pragma unroll
        for (int nb = 0; nb < 8; nb++) {
            float k00 = s.k0s[nb * 8 + colb];
            float k01 = s.k0s[nb * 8 + colb + 1];
            float w0, w1, w2, w3;
            {
                float tt = fmaf(q0r0, k00, -sc[nb][0]);
                float arg = fmaxf(c * tt, lo);
                float z = arg + __fsqrt_rn(fmaf(arg, arg, -1.f));
                w0 = __expf(-sscale * __logf(z));
            }
            {
                float tt = fmaf(q0r0, k01, -sc[nb][1]);
                float arg = fmaxf(c * tt, lo);
                float z = arg + __fsqrt_rn(fmaf(arg, arg, -1.f));
                w1 = __expf(-sscale * __logf(z));
            }
            {
                float tt = fmaf(q0r1, k00, -sc[nb][2]);
                float arg = fmaxf(c * tt, lo);
                float z = arg + __fsqrt_rn(fmaf(arg, arg, -1.f));
                w2 = __expf(-sscale * __logf(z));
            }
            {
                float tt = fmaf(q0r1, k01, -sc[nb][3]);
                float arg = fmaxf(c * tt, lo);
                float z = arg + __fsqrt_rn(fmaf(arg, arg, -1.f));
                w3 = __expf(-sscale * __logf(z));
            }
            if (diag) {
                int cl0 = nb * 8 + colb, cl1 = cl0 + 1;
                if (cl0 > rl0) w0 = 0.f;
                if (cl1 > rl0) w1 = 0.f;
                if (cl0 > rl1) w2 = 0.f;
                if (cl1 > rl1) w3 = 0.f;
            }
            lsum0 += w0 + w1;
            lsum1 += w2 + w3;
            float r0f, r1f, r2f, r3f;
            uint32_t h01 = (uint32_t)bf_hi(w0, r0f) | ((uint32_t)bf_hi(w1, r1f) << 16);
            uint32_t h23 = (uint32_t)bf_hi(w2, r2f) | ((uint32_t)bf_hi(w3, r3f) << 16);
            uint32_t l01 = (uint32_t)bf_of(r0f) | ((uint32_t)bf_of(r1f) << 16);
            uint32_t l23 = (uint32_t)bf_of(r2f) | ((uint32_t)bf_of(r3f) << 16);
            int ks = nb >> 1, ix = (nb & 1) * 2;
            ph[ks][ix] = h01; ph[ks][ix + 1] = h23;
            pl[ks][ix] = l01; pl[ks][ix + 1] = l23;
        }

        // ---- O += P V (3-term) ----
        {
            const int g = lane >> 3, lr = lane & 7;
#pragma unroll
            for (int ks = 0; ks < 4; ks++) {
                const int rowv = ks * 16 + (g & 1) * 8 + lr;
#pragma unroll
                for (int dp = 0; dp < 4; dp++) {
                    uint32_t off = SW128((uint32_t)(rowv * 128 + dp * 32 + (g >> 1) * 16));
                    uint32_t bvh[4], bvl[4];
                    ldsm_x4_t(bvh, sVh + off);
                    ldsm_x4_t(bvl, sVl + off);
                    mma16816(o[2 * dp],     ph[ks], bvh[0], bvh[1]);
                    mma16816(o[2 * dp + 1], ph[ks], bvh[2], bvh[3]);
                    mma16816(o[2 * dp],     ph[ks], bvl[0], bvl[1]);
                    mma16816(o[2 * dp + 1], ph[ks], bvl[2], bvl[3]);
                    mma16816(o[2 * dp],     pl[ks], bvh[0], bvh[1]);
                    mma16816(o[2 * dp + 1], pl[ks], bvh[2], bvh[3]);
                }
            }
        }
        __syncthreads();
    }

    // ---- epilogue ----
    lsum0 += __shfl_xor_sync(0xffffffffu, lsum0, 1);
    lsum0 += __shfl_xor_sync(0xffffffffu, lsum0, 2);
    lsum1 += __shfl_xor_sync(0xffffffffu, lsum1, 1);
    lsum1 += __shfl_xor_sync(0xffffffffu, lsum1, 2);
    const float inv0 = 1.f / lsum0, inv1 = 1.f / lsum1;

    const int row0 = t0 + 16 * wp + r;
#pragma unroll
    for (int nb = 0; nb < 8; nb++) {
        int col = h * 64 + nb * 8 + colb;
        float a0 = o[nb][0] * inv0, a1 = o[nb][1] * inv0;
        float a2 = o[nb][2] * inv1, a3 = o[nb][3] * inv1;
        float r0f, r1f, r2f, r3f;
        uint32_t h01 = (uint32_t)bf_hi(a0, r0f) | ((uint32_t)bf_hi(a1, r1f) << 16);
        uint32_t h23 = (uint32_t)bf_hi(a2, r2f) | ((uint32_t)bf_hi(a3, r3f) << 16);
        uint32_t l01 = (uint32_t)bf_of(r0f) | ((uint32_t)bf_of(r1f) << 16);
        uint32_t l23 = (uint32_t)bf_of(r2f) | ((uint32_t)bf_of(r3f) << 16);
        size_t i0 = (size_t)row0 * DM + col;
        size_t i1 = (size_t)(row0 + 8) * DM + col;
        *(uint32_t*)(ah + i0 * 2) = h01;
        *(uint32_t*)(al + i0 * 2) = l01;
        *(uint32_t*)(ah + i1 * 2) = h23;
        *(uint32_t*)(al + i1 * 2) = l23;
    }
}

// ---------------------------------------------------------------------------
// spatial_norm = mean over (t,h) of |q|
// ---------------------------------------------------------------------------
__global__ __launch_bounds__(256) void norm_reduce_kernel(const float* __restrict__ qn,
                                                          float* __restrict__ out_scalar) {
    __shared__ float red[256];
    int tid = threadIdx.x;
    float s = 0.f;
    for (int i = tid; i < TT * NH; i += 256) s += qn[i];
    red[tid] = s;
    __syncthreads();
#pragma unroll
    for (int k = 128; k > 0; k >>= 1) {
        if (tid < k) red[tid] += red[tid + k];
        __syncthreads();
    }
    if (tid == 0) *out_scalar = red[0] * (1.0f / (float)(TT * NH));
}

// ---------------------------------------------------------------------------
// Launch
// ---------------------------------------------------------------------------
extern "C" void kernel_launch(void* const* d_in, const int* in_sizes, int n_in,
                              void* d_out, int out_size) {
    const float* x    = (const float*)d_in[0];
    const float* q_w  = (const float*)d_in[1];
    const float* k_w  = (const float*)d_in[2];
    const float* v_w  = (const float*)d_in[3];
    const float* o_w  = (const float*)d_in[4];
    const float* temp = (const float*)d_in[5];
    const float* curv = (const float*)d_in[6];
    float* out = (float*)d_out;

    float *pq, *pk, *pv, *pq0, *pk0, *pqn;
    char *xh, *xl, *qwh, *qwl, *kwh, *kwl, *vwh, *vwl, *owh, *owl, *ah, *al;
    char *qbh, *qbl, *kbh, *kbl, *vbh, *vbl;
    cudaGetSymbolAddress((void**)&pq, g_q);
    cudaGetSymbolAddress((void**)&pk, g_k);
    cudaGetSymbolAddress((void**)&pv, g_v);
    cudaGetSymbolAddress((void**)&pq0, g_q0);
    cudaGetSymbolAddress((void**)&pk0, g_k0);
    cudaGetSymbolAddress((void**)&pqn, g_qn);
    cudaGetSymbolAddress((void**)&xh, g_xh);
    cudaGetSymbolAddress((void**)&xl, g_xl);
    cudaGetSymbolAddress((void**)&qwh, g_qwh);
    cudaGetSymbolAddress((void**)&qwl, g_qwl);
    cudaGetSymbolAddress((void**)&kwh, g_kwh);
    cudaGetSymbolAddress((void**)&kwl, g_kwl);
    cudaGetSymbolAddress((void**)&vwh, g_vwh);
    cudaGetSymbolAddress((void**)&vwl, g_vwl);
    cudaGetSymbolAddress((void**)&owh, g_owh);
    cudaGetSymbolAddress((void**)&owl, g_owl);
    cudaGetSymbolAddress((void**)&ah, g_ah);
    cudaGetSymbolAddress((void**)&al, g_al);
    cudaGetSymbolAddress((void**)&qbh, g_qbh);
    cudaGetSymbolAddress((void**)&qbl, g_qbl);
    cudaGetSymbolAddress((void**)&kbh, g_kbh);
    cudaGetSymbolAddress((void**)&kbl, g_kbl);
    cudaGetSymbolAddress((void**)&vbh, g_vbh);
    cudaGetSymbolAddress((void**)&vbl, g_vbl);

    cudaFuncSetAttribute(gemm_mma_hl, cudaFuncAttributeMaxDynamicSharedMemorySize,
                         GEMM_SMEM_BYTES);

    // fp32 -> bf16 hi/lo conversions
    f32_to_hl<<<TT * DM / 4 / 256, 256>>>(x, xh, xl, TT * DM / 4);
    f32_to_hl<<<DM * DM / 4 / 256, 256>>>(q_w, qwh, qwl, DM * DM / 4);
    f32_to_hl<<<256 * DM / 4 / 256, 256>>>(k_w, kwh, kwl, 256 * DM / 4);
    f32_to_hl<<<256 * DM / 4 / 256, 256>>>(v_w, vwh, vwl, 256 * DM / 4);
    f32_to_hl<<<DM * DM / 4 / 256, 256>>>(o_w, owh, owl, DM * DM / 4);

    // QKV projections (HMMA)
    gemm_mma_hl<<<dim3(DM / 128, TT / 128), 256, GEMM_SMEM_BYTES>>>(xh, xl, qwh, qwl, pq, DM, DM);
    gemm_mma_hl<<<dim3(256 / 128, TT / 128), 256, GEMM_SMEM_BYTES>>>(xh, xl, kwh, kwl, pk, 256, DM);
    gemm_mma_hl<<<dim3(256 / 128, TT / 128), 256, GEMM_SMEM_BYTES>>>(xh, xl, vwh, vwl, pv, 256, DM);

    // RMSNorm + RoPE -> bf16 hi/lo q/k + q0/k0 + per-head norms
    rms_rope_kernel<<<TT * (NH + NKV) / 8, 256>>>(pq, pk, qbh, qbl, kbh, kbl,
                                                  pq0, pk0, pqn, curv);
    // V -> bf16 hi/lo
    f32_to_hl<<<TT * NKV * HD / 4 / 256, 256>>>(pv, vbh, vbl, TT * NKV * HD / 4);

    // Tensor-core hyperbolic flash attention
    flash_attn_mma<<<dim3(TT / 64, NH), 128>>>(qbh, qbl, kbh, kbl, vbh, vbl,
                                               pq0, pk0, temp, curv, ah, al);

    // Output projection (HMMA)
    gemm_mma_hl<<<dim3(DM / 128, TT / 128), 256, GEMM_SMEM_BYTES>>>(ah, al, owh, owl, out, DM, DM);

    // spatial_norm scalar
    norm_reduce_kernel<<<1, 256>>>(pqn, out + (out_size - 1));
}

// round 7
// speedup vs baseline: 5.0823x; 1.3646x over previous
#include <cuda_runtime.h>
#include <cuda_bf16.h>
#include <math.h>
#include <stdint.h>

// Problem constants
#define TT    2048
#define DM    1024
#define NH    16
#define NKV   4
#define HD    64
#define EPSN  1e-6f

// ---------------------------------------------------------------------------
// Device scratch (no cudaMalloc allowed)
// ---------------------------------------------------------------------------
__device__ float g_q[TT * NH * HD];
__device__ float g_k[TT * NKV * HD];
__device__ float g_v[TT * NKV * HD];
__device__ float g_q0[TT * NH];
__device__ float g_k0[TT * NKV];
__device__ float g_qn[TT * NH];
__device__ float g_part[64];

// bf16 hi/lo split storage
__device__ uint4 g_xh[TT * DM / 8],  g_xl[TT * DM / 8];
__device__ uint4 g_qwh[DM * DM / 8], g_qwl[DM * DM / 8];
__device__ uint4 g_kwh[256 * DM / 8], g_kwl[256 * DM / 8];
__device__ uint4 g_vwh[256 * DM / 8], g_vwl[256 * DM / 8];
__device__ uint4 g_owh[DM * DM / 8], g_owl[DM * DM / 8];
__device__ uint4 g_ah[TT * DM / 8],  g_al[TT * DM / 8];
__device__ uint4 g_qbh[TT * NH * HD / 8],  g_qbl[TT * NH * HD / 8];
__device__ uint4 g_kbh[TT * NKV * HD / 8], g_kbl[TT * NKV * HD / 8];
__device__ uint4 g_vbh[TT * NKV * HD / 8], g_vbl[TT * NKV * HD / 8];

// ---------------------------------------------------------------------------
// PTX helpers (baseline ISA only)
// ---------------------------------------------------------------------------
__device__ __forceinline__ uint32_t smem_u32(const void* p) {
    uint32_t a;
    asm("{ .reg .u64 t; cvta.to.shared.u64 t, %1; cvt.u32.u64 %0, t; }" : "=r"(a) : "l"(p));
    return a;
}
__device__ __forceinline__ void ldsm_x4(uint32_t* r, uint32_t addr) {
    asm volatile("ldmatrix.sync.aligned.m8n8.x4.shared.b16 {%0,%1,%2,%3}, [%4];"
                 : "=r"(r[0]), "=r"(r[1]), "=r"(r[2]), "=r"(r[3]) : "r"(addr));
}
__device__ __forceinline__ void ldsm_x4_t(uint32_t* r, uint32_t addr) {
    asm volatile("ldmatrix.sync.aligned.m8n8.x4.trans.shared.b16 {%0,%1,%2,%3}, [%4];"
                 : "=r"(r[0]), "=r"(r[1]), "=r"(r[2]), "=r"(r[3]) : "r"(addr));
}
__device__ __forceinline__ void mma16816(float* c, const uint32_t* a, uint32_t b0, uint32_t b1) {
    asm volatile("mma.sync.aligned.m16n8k16.row.col.f32.bf16.bf16.f32 "
                 "{%0,%1,%2,%3}, {%4,%5,%6,%7}, {%8,%9}, {%0,%1,%2,%3};"
                 : "+f"(c[0]), "+f"(c[1]), "+f"(c[2]), "+f"(c[3])
                 : "r"(a[0]), "r"(a[1]), "r"(a[2]), "r"(a[3]), "r"(b0), "r"(b1));
}
__device__ __forceinline__ void sts128(uint32_t addr, uint4 v) {
    asm volatile("st.shared.v4.b32 [%0], {%1,%2,%3,%4};"
                 :: "r"(addr), "r"(v.x), "r"(v.y), "r"(v.z), "r"(v.w) : "memory");
}
__device__ __forceinline__ void cpasync16(uint32_t dst, const void* src) {
    asm volatile("cp.async.cg.shared.global [%0], [%1], 16;" :: "r"(dst), "l"(src));
}
__device__ __forceinline__ void cpasync_commit() {
    asm volatile("cp.async.commit_group;" ::: "memory");
}
template <int N>
__device__ __forceinline__ void cpasync_wait() {
    asm volatile("cp.async.wait_group %0;" :: "n"(N) : "memory");
}
#define SW128(o) ((o) ^ (((o) >> 3) & 0x70))

__device__ __forceinline__ uint16_t bf_hi(float f, float& rem) {
    __nv_bfloat16 h = __float2bfloat16(f);
    rem = f - __bfloat162float(h);
    union { __nv_bfloat16 b; uint16_t u; } cv; cv.b = h;
    return cv.u;
}
__device__ __forceinline__ uint16_t bf_of(float f) {
    union { __nv_bfloat16 b; uint16_t u; } cv; cv.b = __float2bfloat16(f);
    return cv.u;
}

// ---------------------------------------------------------------------------
// Merged fp32 -> bf16 hi/lo conversion for all 5 tensors.
// ---------------------------------------------------------------------------
#define N4_X  (TT * DM / 4)
#define N4_QW (DM * DM / 4)
#define N4_KW (256 * DM / 4)
#define N4_VW (256 * DM / 4)
#define N4_OW (DM * DM / 4)
#define N4_TOT (N4_X + N4_QW + N4_KW + N4_VW + N4_OW)

__global__ __launch_bounds__(256) void conv_all(
    const float* __restrict__ x, const float* __restrict__ qw,
    const float* __restrict__ kw, const float* __restrict__ vw,
    const float* __restrict__ ow,
    char* xh, char* xl, char* qwh, char* qwl, char* kwh, char* kwl,
    char* vwh, char* vwl, char* owh, char* owl) {
    int i = blockIdx.x * 256 + threadIdx.x;
    if (i >= N4_TOT) return;
    const float* in; char* hi; char* lo; int base;
    if (i < N4_X)                          { in = x;  hi = xh;  lo = xl;  base = 0; }
    else if (i < N4_X + N4_QW)             { in = qw; hi = qwh; lo = qwl; base = N4_X; }
    else if (i < N4_X + N4_QW + N4_KW)     { in = kw; hi = kwh; lo = kwl; base = N4_X + N4_QW; }
    else if (i < N4_X + N4_QW + N4_KW + N4_VW)
                                           { in = vw; hi = vwh; lo = vwl; base = N4_X + N4_QW + N4_KW; }
    else                                   { in = ow; hi = owh; lo = owl; base = N4_X + N4_QW + N4_KW + N4_VW; }
    int j4 = i - base;
    float4 v = ((const float4*)in)[j4];
    union { __nv_bfloat16 b[4]; uint2 u; } h, l;
    float f[4] = {v.x, v.y, v.z, v.w};
#pragma unroll
    for (int j = 0; j < 4; j++) {
        h.b[j] = __float2bfloat16(f[j]);
        l.b[j] = __float2bfloat16(f[j] - __bfloat162float(h.b[j]));
    }
    ((uint2*)hi)[j4] = h.u;
    ((uint2*)lo)[j4] = l.u;
}

__global__ __launch_bounds__(256) void f32_to_hl(const float* __restrict__ in,
                                                 char* __restrict__ hi,
                                                 char* __restrict__ lo, int n4) {
    int i = blockIdx.x * 256 + threadIdx.x;
    if (i >= n4) return;
    float4 v = ((const float4*)in)[i];
    union { __nv_bfloat16 b[4]; uint2 u; } h, l;
    float f[4] = {v.x, v.y, v.z, v.w};
#pragma unroll
    for (int j = 0; j < 4; j++) {
        h.b[j] = __float2bfloat16(f[j]);
        l.b[j] = __float2bfloat16(f[j] - __bfloat162float(h.b[j]));
    }
    ((uint2*)hi)[i] = h.u;
    ((uint2*)lo)[i] = l.u;
}

// ---------------------------------------------------------------------------
// HMMA bf16 hi/lo-split GEMM with cp.async 2-stage pipeline.
// C[M,N] = A[M,K] * B[N,K]^T  (fp32 out), tile 128x128, BK=64.
// ---------------------------------------------------------------------------
#define TILE_B 16384
#define STAGE_B (4 * TILE_B)
#define GEMM_SMEM_BYTES (2 * STAGE_B + 1024)

__global__ __launch_bounds__(256) void gemm_mma_hl(
    const char* __restrict__ Ah, const char* __restrict__ Al,
    const char* __restrict__ Bh, const char* __restrict__ Bl,
    float* __restrict__ C, int Ntot, int K) {
    extern __shared__ __align__(16) char sm[];
    uint32_t ts = (smem_u32(sm) + 1023) & ~1023u;
    const uint32_t stage[2] = { ts, ts + STAGE_B };

    const int tid = threadIdx.x;
    const int lane = tid & 31;
    const int wid = tid >> 5;
    const int wm = wid >> 1;
    const int wn = wid & 1;
    const int m0 = blockIdx.y * 128;
    const int n0 = blockIdx.x * 128;
    const size_t K2 = (size_t)K * 2;

    const char* srcs[4] = { Ah + (size_t)m0 * K2, Al + (size_t)m0 * K2,
                            Bh + (size_t)n0 * K2, Bl + (size_t)n0 * K2 };

    const int u = tid & 7;
    const int r0 = tid >> 3;

    auto load_chunk = [&](int ch, uint32_t sb) {
        const size_t koff = (size_t)ch * 128 + u * 16;
#pragma unroll
        for (int t = 0; t < 4; t++) {
            const char* src = srcs[t] + koff;
            const uint32_t tb = sb + t * TILE_B;
#pragma unroll
            for (int it = 0; it < 4; it++) {
                const int row = it * 32 + r0;
                uint32_t off = row * 128 + u * 16;
                cpasync16(tb + SW128(off), src + (size_t)row * K2);
            }
        }
    };

    float acc[2][8][4];
#pragma unroll
    for (int a = 0; a < 2; a++)
#pragma unroll
        for (int b = 0; b < 8; b++)
#pragma unroll
            for (int cc = 0; cc < 4; cc++) acc[a][b][cc] = 0.f;

    const int amat = lane >> 3, arow = lane & 7;
    const int nch = K / 64;

    load_chunk(0, stage[0]);
    cpasync_commit();

    for (int ch = 0; ch < nch; ch++) {
        if (ch + 1 < nch) {
            load_chunk(ch + 1, stage[(ch + 1) & 1]);
            cpasync_commit();
            cpasync_wait<1>();
        } else {
            cpasync_wait<0>();
        }
        __syncthreads();

        const uint32_t sb = stage[ch & 1];
        const uint32_t tAh = sb, tAl = sb + TILE_B, tBh = sb + 2 * TILE_B, tBl = sb + 3 * TILE_B;
#pragma unroll
        for (int ks = 0; ks < 4; ks++) {
            uint32_t ah[2][4], al[2][4], bh[4][4], bl[4][4];
#pragma unroll
            for (int mb = 0; mb < 2; mb++) {
                int m = wm * 32 + mb * 16 + (amat & 1) * 8 + arow;
                int kb = ks * 32 + (amat >> 1) * 16;
                uint32_t off = SW128((uint32_t)(m * 128 + kb));
                ldsm_x4(ah[mb], tAh + off);
                ldsm_x4(al[mb], tAl + off);
            }
#pragma unroll
            for (int p = 0; p < 4; p++) {
                int n = wn * 64 + p * 16 + (amat >> 1) * 8 + arow;
                int kb = ks * 32 + (amat & 1) * 16;
                uint32_t off = SW128((uint32_t)(n * 128 + kb));
                ldsm_x4(bh[p], tBh + off);
                ldsm_x4(bl[p], tBl + off);
            }
#pragma unroll
            for (int mb = 0; mb < 2; mb++)
#pragma unroll
                for (int p = 0; p < 4; p++) {
                    mma16816(acc[mb][2 * p],     ah[mb], bh[p][0], bh[p][1]);
                    mma16816(acc[mb][2 * p + 1], ah[mb], bh[p][2], bh[p][3]);
                    mma16816(acc[mb][2 * p],     ah[mb], bl[p][0], bl[p][1]);
                    mma16816(acc[mb][2 * p + 1], ah[mb], bl[p][2], bl[p][3]);
                    mma16816(acc[mb][2 * p],     al[mb], bh[p][0], bh[p][1]);
                    mma16816(acc[mb][2 * p + 1], al[mb], bh[p][2], bh[p][3]);
                }
        }
        __syncthreads();
    }

    const int crow = lane >> 2;
    const int ccol = (lane & 3) * 2;
#pragma unroll
    for (int mb = 0; mb < 2; mb++) {
#pragma unroll
        for (int nb = 0; nb < 8; nb++) {
            int m = m0 + wm * 32 + mb * 16 + crow;
            int n = n0 + wn * 64 + nb * 8 + ccol;
            *(float2*)&C[(size_t)m * Ntot + n]       = make_float2(acc[mb][nb][0], acc[mb][nb][1]);
            *(float2*)&C[(size_t)(m + 8) * Ntot + n] = make_float2(acc[mb][nb][2], acc[mb][nb][3]);
        }
    }
}

// ---------------------------------------------------------------------------
// RMSNorm + RoPE (warp per vector); writes bf16 hi/lo q/k, q0/k0, |q|.
// ---------------------------------------------------------------------------
__global__ __launch_bounds__(256) void rms_rope_kernel(
    const float* __restrict__ qf, const float* __restrict__ kf,
    char* __restrict__ qbh, char* __restrict__ qbl,
    char* __restrict__ kbh, char* __restrict__ kbl,
    float* __restrict__ q0, float* __restrict__ k0,
    float* __restrict__ qn, const float* __restrict__ curv) {
    const int wid = threadIdx.x >> 5;
    const int lane = threadIdx.x & 31;
    const int vi = blockIdx.x * 8 + wid;
    const int t = vi & 2047;
    const int hh = vi >> 11;

    const float* vec;
    size_t obase;
    char *oh, *ol;
    if (hh < NH) {
        size_t idx = (size_t)t * NH + hh;
        vec = qf + idx * HD; obase = idx * HD; oh = qbh; ol = qbl;
    } else {
        size_t idx = (size_t)t * NKV + (hh - NH);
        vec = kf + idx * HD; obase = idx * HD; oh = kbh; ol = kbl;
    }
    float x1 = vec[lane], x2 = vec[lane + 32];
    float ss = x1 * x1 + x2 * x2;
#pragma unroll
    for (int o = 16; o >= 1; o >>= 1) ss += __shfl_xor_sync(0xffffffffu, ss, o);

    float inv = rsqrtf(ss * (1.0f / 64.0f) + EPSN);
    x1 *= inv; x2 *= inv;

    float invf = expf(-(float)lane * 0.28782313662425572f);
    float ang = (float)t * invf;
    float sv, cv;
    sincosf(ang, &sv, &cv);
    float o1 = fmaf(x1, cv, x2 * sv);
    float o2 = fmaf(-x1, sv, x2 * cv);

    float r1, r2;
    uint16_t h1 = bf_hi(o1, r1), h2 = bf_hi(o2, r2);
    ((uint16_t*)oh)[obase + lane]      = h1;
    ((uint16_t*)oh)[obase + lane + 32] = h2;
    ((uint16_t*)ol)[obase + lane]      = bf_of(r1);
    ((uint16_t*)ol)[obase + lane + 32] = bf_of(r2);

    if (lane == 0) {
        float sum2 = ss * inv * inv;
        float c = *curv;
        float h0 = sqrtf(1.0f / c + sum2);
        if (hh < NH) {
            q0[t * NH + hh] = h0;
            qn[t * NH + hh] = sqrtf(sum2);
        } else {
            k0[t * NKV + (hh - NH)] = h0;
        }
    }
}

// ---------------------------------------------------------------------------
// Tensor-core flash hyperbolic attention with cp.async 2-stage KV pipeline.
// ---------------------------------------------------------------------------
#define FA_STAGE_B 32768                 // kh/kl/vh/vl of 8KB each
#define FA_SMEM_BYTES (2 * FA_STAGE_B + 1024)

__global__ __launch_bounds__(128) void flash_attn_mma(
    const char* __restrict__ Qh, const char* __restrict__ Ql,
    const char* __restrict__ Kh, const char* __restrict__ Kl,
    const char* __restrict__ Vh, const char* __restrict__ Vl,
    const float* __restrict__ q0a, const float* __restrict__ k0a,
    const float* __restrict__ temp, const float* __restrict__ curv,
    char* __restrict__ ah, char* __restrict__ al) {
    extern __shared__ __align__(16) char smraw[];
    const uint32_t sb0 = (smem_u32(smraw) + 1023) & ~1023u;
    const uint32_t stg[2] = { sb0, sb0 + FA_STAGE_B };
    float* q0s = (float*)(smraw + (2 * FA_STAGE_B + 1024 - 768 - ((smem_u32(smraw) + 1023 - smem_u32(smraw)) & 0)));
    // simpler: place scalars right after stages relative to sb0
    q0s = (float*)(smraw) + ((sb0 - smem_u32(smraw)) >> 2) + (2 * FA_STAGE_B >> 2);
    float* k0st0 = q0s + 64;
    float* k0st1 = k0st0 + 64;

    const int tid = threadIdx.x;
    const int lane = tid & 31;
    const int wp = tid >> 5;
    const int h = blockIdx.y;
    const int t0 = ((int)gridDim.x - 1 - (int)blockIdx.x) * 64;
    const int kvh = h >> 2;

    const float c = *curv;
    const float sscale = rsqrtf(c) / temp[h];
    const float lo = 1.0f + 1e-5f;

    // ---- stage Q tile (hi/lo) into stage0 kh/kl ----
    {
        const char* qs[2] = { Qh, Ql };
        for (int idx = tid; idx < 1024; idx += 128) {
            int mtx = idx >> 9, rem = idx & 511, row = rem >> 3, u = rem & 7;
            const char* src = qs[mtx] + ((size_t)(t0 + row) * NH + h) * 128 + u * 16;
            sts128(stg[0] + mtx * 8192 + SW128((uint32_t)(row * 128 + u * 16)), *(const uint4*)src);
        }
        if (tid < 64) q0s[tid] = q0a[(t0 + tid) * NH + h];
    }
    __syncthreads();

    // ---- Q fragments to registers ----
    uint32_t qa_h[4][4], qa_l[4][4];
    {
        const int g = lane >> 3, lr = lane & 7;
        const int row = 16 * wp + (g & 1) * 8 + lr;
#pragma unroll
        for (int ks = 0; ks < 4; ks++) {
            uint32_t off = SW128((uint32_t)(row * 128 + ks * 32 + (g >> 1) * 16));
            ldsm_x4(qa_h[ks], stg[0] + off);
            ldsm_x4(qa_l[ks], stg[0] + 8192 + off);
        }
    }
    const int r = lane >> 2;
    const int colb = (lane & 3) * 2;
    const float q0r0 = q0s[16 * wp + r];
    const float q0r1 = q0s[16 * wp + 8 + r];
    __syncthreads();

    float o[8][4];
#pragma unroll
    for (int i = 0; i < 8; i++)
#pragma unroll
        for (int j = 0; j < 4; j++) o[i][j] = 0.f;
    float lsum0 = 0.f, lsum1 = 0.f;

    const char* kvsrc[4] = { Kh + kvh * 128, Kl + kvh * 128, Vh + kvh * 128, Vl + kvh * 128 };

    auto kv_load = [&](int c0, uint32_t sbase, float* k0dst) {
        for (int idx = tid; idx < 2048; idx += 128) {
            int mtx = idx >> 9, rem = idx & 511, row = rem >> 3, u = rem & 7;
            const char* src = kvsrc[mtx] + (size_t)(c0 + row) * 512 + u * 16;
            cpasync16(sbase + mtx * 8192 + SW128((uint32_t)(row * 128 + u * 16)), src);
        }
        if (tid < 64) k0dst[tid] = k0a[(c0 + tid) * NKV + kvh];
    };

    const int nt = t0 / 64 + 1;
    kv_load(0, stg[0], k0st0);
    cpasync_commit();

    for (int ch = 0; ch < nt; ch++) {
        if (ch + 1 < nt) {
            kv_load((ch + 1) * 64, stg[(ch + 1) & 1], ((ch + 1) & 1) ? k0st1 : k0st0);
            cpasync_commit();
            cpasync_wait<1>();
        } else {
            cpasync_wait<0>();
        }
        __syncthreads();

        const uint32_t sKh = stg[ch & 1], sKl = sKh + 8192, sVh = sKh + 16384, sVl = sKh + 24576;
        const float* k0s = (ch & 1) ? k0st1 : k0st0;

        // ---- S = Q K^T (3-term) ----
        float sc[8][4];
#pragma unroll
        for (int i = 0; i < 8; i++)
#pragma unroll
            for (int j = 0; j < 4; j++) sc[i][j] = 0.f;
        {
            const int g = lane >> 3, lr = lane & 7;
#pragma unroll
            for (int ks = 0; ks < 4; ks++) {
                const int dby = ks * 32 + (g >> 1) * 16;
#pragma unroll
                for (int p = 0; p < 4; p++) {
                    const int row = p * 16 + (g & 1) * 8 + lr;
                    uint32_t off = SW128((uint32_t)(row * 128 + dby));
                    uint32_t bh[4], bl[4];
                    ldsm_x4(bh, sKh + off);
                    ldsm_x4(bl, sKl + off);
                    mma16816(sc[2 * p],     qa_h[ks], bh[0], bh[2]);
                    mma16816(sc[2 * p + 1], qa_h[ks], bh[1], bh[3]);
                    mma16816(sc[2 * p],     qa_h[ks], bl[0], bl[2]);
                    mma16816(sc[2 * p + 1], qa_h[ks], bl[1], bl[3]);
                    mma16816(sc[2 * p],     qa_l[ks], bh[0], bh[2]);
                    mma16816(sc[2 * p + 1], qa_l[ks], bh[1], bh[3]);
                }
            }
        }

        // ---- hyperbolic transform -> weights; pack P hi/lo ----
        const bool diag = (ch == nt - 1);
        const int rl0 = 16 * wp + r, rl1 = rl0 + 8;
        uint32_t ph[4][4], pl[4][4];
#pragma unroll
        for (int nb = 0; nb < 8; nb++) {
            float k00 = k0s[nb * 8 + colb];
            float k01 = k0s[nb * 8 + colb + 1];
            float w0, w1, w2, w3;
            {
                float tt = fmaf(q0r0, k00, -sc[nb][0]);
                float arg = fmaxf(c * tt, lo);
                float z = arg + __fsqrt_rn(fmaf(arg, arg, -1.f));
                w0 = __expf(-sscale * __logf(z));
            }
            {
                float tt = fmaf(q0r0, k01, -sc[nb][1]);
                float arg = fmaxf(c * tt, lo);
                float z = arg + __fsqrt_rn(fmaf(arg, arg, -1.f));
                w1 = __expf(-sscale * __logf(z));
            }
            {
                float tt = fmaf(q0r1, k00, -sc[nb][2]);
                float arg = fmaxf(c * tt, lo);
                float z = arg + __fsqrt_rn(fmaf(arg, arg, -1.f));
                w2 = __expf(-sscale * __logf(z));
            }
            {
                float tt = fmaf(q0r1, k01, -sc[nb][3]);
                float arg = fmaxf(c * tt, lo);
                float z = arg + __fsqrt_rn(fmaf(arg, arg, -1.f));
                w3 = __expf(-sscale * __logf(z));
            }
            if (diag) {
                int cl0 = nb * 8 + colb, cl1 = cl0 + 1;
                if (cl0 > rl0) w0 = 0.f;
                if (cl1 > rl0) w1 = 0.f;
                if (cl0 > rl1) w2 = 0.f;
                if (cl1 > rl1) w3 = 0.f;
            }
            lsum0 += w0 + w1;
            lsum1 += w2 + w3;
            float r0f, r1f, r2f, r3f;
            uint32_t h01 = (uint32_t)bf_hi(w0, r0f) | ((uint32_t)bf_hi(w1, r1f) << 16);
            uint32_t h23 = (uint32_t)bf_hi(w2, r2f) | ((uint32_t)bf_hi(w3, r3f) << 16);
            uint32_t l01 = (uint32_t)bf_of(r0f) | ((uint32_t)bf_of(r1f) << 16);
            uint32_t l23 = (uint32_t)bf_of(r2f) | ((uint32_t)bf_of(r3f) << 16);
            int ks = nb >> 1, ix = (nb & 1) * 2;
            ph[ks][ix] = h01; ph[ks][ix + 1] = h23;
            pl[ks][ix] = l01; pl[ks][ix + 1] = l23;
        }

        // ---- O += P V (3-term) ----
        {
            const int g = lane >> 3, lr = lane & 7;
#pragma unroll
            for (int ks = 0; ks < 4; ks++) {
                const int rowv = ks * 16 + (g & 1) * 8 + lr;
#pragma unroll
                for (int dp = 0; dp < 4; dp++) {
                    uint32_t off = SW128((uint32_t)(rowv * 128 + dp * 32 + (g >> 1) * 16));
                    uint32_t bvh[4], bvl[4];
                    ldsm_x4_t(bvh, sVh + off);
                    ldsm_x4_t(bvl, sVl + off);
                    mma16816(o[2 * dp],     ph[ks], bvh[0], bvh[1]);
                    mma16816(o[2 * dp + 1], ph[ks], bvh[2], bvh[3]);
                    mma16816(o[2 * dp],     ph[ks], bvl[0], bvl[1]);
                    mma16816(o[2 * dp + 1], ph[ks], bvl[2], bvl[3]);
                    mma16816(o[2 * dp],     pl[ks], bvh[0], bvh[1]);
                    mma16816(o[2 * dp + 1], pl[ks], bvh[2], bvh[3]);
                }
            }
        }
        __syncthreads();
    }

    // ---- epilogue ----
    lsum0 += __shfl_xor_sync(0xffffffffu, lsum0, 1);
    lsum0 += __shfl_xor_sync(0xffffffffu, lsum0, 2);
    lsum1 += __shfl_xor_sync(0xffffffffu, lsum1, 1);
    lsum1 += __shfl_xor_sync(0xffffffffu, lsum1, 2);
    const float inv0 = 1.f / lsum0, inv1 = 1.f / lsum1;

    const int row0 = t0 + 16 * wp + r;
#pragma unroll
    for (int nb = 0; nb < 8; nb++) {
        int col = h * 64 + nb * 8 + colb;
        float a0 = o[nb][0] * inv0, a1 = o[nb][1] * inv0;
        float a2 = o[nb][2] * inv1, a3 = o[nb][3] * inv1;
        float r0f, r1f, r2f, r3f;
        uint32_t h01 = (uint32_t)bf_hi(a0, r0f) | ((uint32_t)bf_hi(a1, r1f) << 16);
        uint32_t h23 = (uint32_t)bf_hi(a2, r2f) | ((uint32_t)bf_hi(a3, r3f) << 16);
        uint32_t l01 = (uint32_t)bf_of(r0f) | ((uint32_t)bf_of(r1f) << 16);
        uint32_t l23 = (uint32_t)bf_of(r2f) | ((uint32_t)bf_of(r3f) << 16);
        size_t i0 = (size_t)row0 * DM + col;
        size_t i1 = (size_t)(row0 + 8) * DM + col;
        *(uint32_t*)(ah + i0 * 2) = h01;
        *(uint32_t*)(al + i0 * 2) = l01;
        *(uint32_t*)(ah + i1 * 2) = h23;
        *(uint32_t*)(al + i1 * 2) = l23;
    }
}

// ---------------------------------------------------------------------------
// spatial_norm: two-stage reduction
// ---------------------------------------------------------------------------
__global__ __launch_bounds__(256) void norm_partial(const float* __restrict__ qn,
                                                    float* __restrict__ part) {
    __shared__ float red[256];
    int tid = threadIdx.x;
    float s = 0.f;
    for (int i = blockIdx.x * 256 + tid; i < TT * NH; i += 64 * 256) s += qn[i];
    red[tid] = s;
    __syncthreads();
#pragma unroll
    for (int k = 128; k > 0; k >>= 1) {
        if (tid < k) red[tid] += red[tid + k];
        __syncthreads();
    }
    if (tid == 0) part[blockIdx.x] = red[0];
}
__global__ __launch_bounds__(64) void norm_final(const float* __restrict__ part,
                                                 float* __restrict__ out_scalar) {
    int tid = threadIdx.x;
    float s = part[tid];
#pragma unroll
    for (int o = 16; o >= 1; o >>= 1) s += __shfl_xor_sync(0xffffffffu, s, o);
    __shared__ float w0;
    if (tid == 0) w0 = s;
    __syncthreads();
    if (tid == 32 && (threadIdx.x & 31) == 0) {}
    if (tid == 32) { /* lane0 of warp1 */ }
    if (tid == 0) { /* combined below */ }
    // combine two warps
    __shared__ float w1s;
    if (tid == 32) w1s = s;
    __syncthreads();
    if (tid == 0) *out_scalar = (w0 + w1s) * (1.0f / (float)(TT * NH));
}

// ---------------------------------------------------------------------------
// Launch
// ---------------------------------------------------------------------------
extern "C" void kernel_launch(void* const* d_in, const int* in_sizes, int n_in,
                              void* d_out, int out_size) {
    const float* x    = (const float*)d_in[0];
    const float* q_w  = (const float*)d_in[1];
    const float* k_w  = (const float*)d_in[2];
    const float* v_w  = (const float*)d_in[3];
    const float* o_w  = (const float*)d_in[4];
    const float* temp = (const float*)d_in[5];
    const float* curv = (const float*)d_in[6];
    float* out = (float*)d_out;

    float *pq, *pk, *pv, *pq0, *pk0, *pqn, *ppart;
    char *xh, *xl, *qwh, *qwl, *kwh, *kwl, *vwh, *vwl, *owh, *owl, *ah, *al;
    char *qbh, *qbl, *kbh, *kbl, *vbh, *vbl;
    cudaGetSymbolAddress((void**)&pq, g_q);
    cudaGetSymbolAddress((void**)&pk, g_k);
    cudaGetSymbolAddress((void**)&pv, g_v);
    cudaGetSymbolAddress((void**)&pq0, g_q0);
    cudaGetSymbolAddress((void**)&pk0, g_k0);
    cudaGetSymbolAddress((void**)&pqn, g_qn);
    cudaGetSymbolAddress((void**)&ppart, g_part);
    cudaGetSymbolAddress((void**)&xh, g_xh);
    cudaGetSymbolAddress((void**)&xl, g_xl);
    cudaGetSymbolAddress((void**)&qwh, g_qwh);
    cudaGetSymbolAddress((void**)&qwl, g_qwl);
    cudaGetSymbolAddress((void**)&kwh, g_kwh);
    cudaGetSymbolAddress((void**)&kwl, g_kwl);
    cudaGetSymbolAddress((void**)&vwh, g_vwh);
    cudaGetSymbolAddress((void**)&vwl, g_vwl);
    cudaGetSymbolAddress((void**)&owh, g_owh);
    cudaGetSymbolAddress((void**)&owl, g_owl);
    cudaGetSymbolAddress((void**)&ah, g_ah);
    cudaGetSymbolAddress((void**)&al, g_al);
    cudaGetSymbolAddress((void**)&qbh, g_qbh);
    cudaGetSymbolAddress((void**)&qbl, g_qbl);
    cudaGetSymbolAddress((void**)&kbh, g_kbh);
    cudaGetSymbolAddress((void**)&kbl, g_kbl);
    cudaGetSymbolAddress((void**)&vbh, g_vbh);
    cudaGetSymbolAddress((void**)&vbl, g_vbl);

    cudaFuncSetAttribute(gemm_mma_hl, cudaFuncAttributeMaxDynamicSharedMemorySize,
                         GEMM_SMEM_BYTES);
    cudaFuncSetAttribute(flash_attn_mma, cudaFuncAttributeMaxDynamicSharedMemorySize,
                         FA_SMEM_BYTES);

    // merged fp32 -> bf16 hi/lo conversions
    conv_all<<<(N4_TOT + 255) / 256, 256>>>(x, q_w, k_w, v_w, o_w,
                                            xh, xl, qwh, qwl, kwh, kwl,
                                            vwh, vwl, owh, owl);

    // QKV projections (HMMA, pipelined)
    gemm_mma_hl<<<dim3(DM / 128, TT / 128), 256, GEMM_SMEM_BYTES>>>(xh, xl, qwh, qwl, pq, DM, DM);
    gemm_mma_hl<<<dim3(256 / 128, TT / 128), 256, GEMM_SMEM_BYTES>>>(xh, xl, kwh, kwl, pk, 256, DM);
    gemm_mma_hl<<<dim3(256 / 128, TT / 128), 256, GEMM_SMEM_BYTES>>>(xh, xl, vwh, vwl, pv, 256, DM);

    // RMSNorm + RoPE -> bf16 hi/lo q/k + q0/k0 + per-head norms
    rms_rope_kernel<<<TT * (NH + NKV) / 8, 256>>>(pq, pk, qbh, qbl, kbh, kbl,
                                                  pq0, pk0, pqn, curv);
    // V -> bf16 hi/lo
    f32_to_hl<<<TT * NKV * HD / 4 / 256, 256>>>(pv, vbh, vbl, TT * NKV * HD / 4);

    // Tensor-core hyperbolic flash attention (pipelined KV)
    flash_attn_mma<<<dim3(TT / 64, NH), 128, FA_SMEM_BYTES>>>(
        qbh, qbl, kbh, kbl, vbh, vbl, pq0, pk0, temp, curv, ah, al);

    // Output projection (HMMA, pipelined)
    gemm_mma_hl<<<dim3(DM / 128, TT / 128), 256, GEMM_SMEM_BYTES>>>(ah, al, owh, owl, out, DM, DM);

    // spatial_norm scalar
    norm_partial<<<64, 256>>>(pqn, ppart);
    norm_final<<<1, 64>>>(ppart, out + (out_size - 1));
}

// round 8
// speedup vs baseline: 6.6450x; 1.3075x over previous
#include <cuda_runtime.h>
#include <cuda_bf16.h>
#include <math.h>
#include <stdint.h>

// Problem constants
#define TT    2048
#define DM    1024
#define NH    16
#define NKV   4
#define HD    64
#define EPSN  1e-6f
#define NQKV  1536   // fused projection width: 1024 q + 256 k + 256 v

// ---------------------------------------------------------------------------
// Device scratch (no cudaMalloc allowed)
// ---------------------------------------------------------------------------
__device__ float g_qkv[TT * NQKV];      // fused projection output (fp32)
__device__ float g_q0[TT * NH];
__device__ float g_k0[TT * NKV];
__device__ float g_qn[TT * NH];
__device__ float g_part[32];

// bf16 hi/lo split storage
__device__ uint4 g_xh[TT * DM / 8],   g_xl[TT * DM / 8];
__device__ uint4 g_wh[NQKV * DM / 8], g_wl[NQKV * DM / 8];   // concat q_w|k_w|v_w
__device__ uint4 g_owh[DM * DM / 8],  g_owl[DM * DM / 8];
__device__ uint4 g_ah[TT * DM / 8],   g_al[TT * DM / 8];
__device__ uint4 g_qbh[TT * NH * HD / 8],  g_qbl[TT * NH * HD / 8];
__device__ uint4 g_kbh[TT * NKV * HD / 8], g_kbl[TT * NKV * HD / 8];
__device__ uint4 g_vbh[TT * NKV * HD / 8], g_vbl[TT * NKV * HD / 8];

// ---------------------------------------------------------------------------
// PTX helpers (baseline ISA only)
// ---------------------------------------------------------------------------
__device__ __forceinline__ uint32_t smem_u32(const void* p) {
    uint32_t a;
    asm("{ .reg .u64 t; cvta.to.shared.u64 t, %1; cvt.u32.u64 %0, t; }" : "=r"(a) : "l"(p));
    return a;
}
__device__ __forceinline__ void ldsm_x4(uint32_t* r, uint32_t addr) {
    asm volatile("ldmatrix.sync.aligned.m8n8.x4.shared.b16 {%0,%1,%2,%3}, [%4];"
                 : "=r"(r[0]), "=r"(r[1]), "=r"(r[2]), "=r"(r[3]) : "r"(addr));
}
__device__ __forceinline__ void ldsm_x4_t(uint32_t* r, uint32_t addr) {
    asm volatile("ldmatrix.sync.aligned.m8n8.x4.trans.shared.b16 {%0,%1,%2,%3}, [%4];"
                 : "=r"(r[0]), "=r"(r[1]), "=r"(r[2]), "=r"(r[3]) : "r"(addr));
}
__device__ __forceinline__ void mma16816(float* c, const uint32_t* a, uint32_t b0, uint32_t b1) {
    asm volatile("mma.sync.aligned.m16n8k16.row.col.f32.bf16.bf16.f32 "
                 "{%0,%1,%2,%3}, {%4,%5,%6,%7}, {%8,%9}, {%0,%1,%2,%3};"
                 : "+f"(c[0]), "+f"(c[1]), "+f"(c[2]), "+f"(c[3])
                 : "r"(a[0]), "r"(a[1]), "r"(a[2]), "r"(a[3]), "r"(b0), "r"(b1));
}
__device__ __forceinline__ void sts128(uint32_t addr, uint4 v) {
    asm volatile("st.shared.v4.b32 [%0], {%1,%2,%3,%4};"
                 :: "r"(addr), "r"(v.x), "r"(v.y), "r"(v.z), "r"(v.w) : "memory");
}
__device__ __forceinline__ void cpasync16(uint32_t dst, const void* src) {
    asm volatile("cp.async.cg.shared.global [%0], [%1], 16;" :: "r"(dst), "l"(src));
}
__device__ __forceinline__ void cpasync_commit() {
    asm volatile("cp.async.commit_group;" ::: "memory");
}
template <int N>
__device__ __forceinline__ void cpasync_wait() {
    asm volatile("cp.async.wait_group %0;" :: "n"(N) : "memory");
}
__device__ __forceinline__ float fsqrt_ap(float x) {
    float r;
    asm("sqrt.approx.f32 %0, %1;" : "=f"(r) : "f"(x));
    return r;
}
#define SW128(o) ((o) ^ (((o) >> 3) & 0x70))

__device__ __forceinline__ uint16_t bf_hi(float f, float& rem) {
    __nv_bfloat16 h = __float2bfloat16(f);
    rem = f - __bfloat162float(h);
    union { __nv_bfloat16 b; uint16_t u; } cv; cv.b = h;
    return cv.u;
}
__device__ __forceinline__ uint16_t bf_of(float f) {
    union { __nv_bfloat16 b; uint16_t u; } cv; cv.b = __float2bfloat16(f);
    return cv.u;
}

// ---------------------------------------------------------------------------
// Merged fp32 -> bf16 hi/lo conversion for all 5 input tensors.
// Weight outputs point into the concatenated g_wh/g_wl buffer.
// ---------------------------------------------------------------------------
#define N4_X  (TT * DM / 4)
#define N4_QW (DM * DM / 4)
#define N4_KW (256 * DM / 4)
#define N4_VW (256 * DM / 4)
#define N4_OW (DM * DM / 4)
#define N4_TOT (N4_X + N4_QW + N4_KW + N4_VW + N4_OW)

__global__ __launch_bounds__(256) void conv_all(
    const float* __restrict__ x, const float* __restrict__ qw,
    const float* __restrict__ kw, const float* __restrict__ vw,
    const float* __restrict__ ow,
    char* xh, char* xl, char* qwh, char* qwl, char* kwh, char* kwl,
    char* vwh, char* vwl, char* owh, char* owl) {
    int i = blockIdx.x * 256 + threadIdx.x;
    if (i >= N4_TOT) return;
    const float* in; char* hi; char* lo; int base;
    if (i < N4_X)                          { in = x;  hi = xh;  lo = xl;  base = 0; }
    else if (i < N4_X + N4_QW)             { in = qw; hi = qwh; lo = qwl; base = N4_X; }
    else if (i < N4_X + N4_QW + N4_KW)     { in = kw; hi = kwh; lo = kwl; base = N4_X + N4_QW; }
    else if (i < N4_X + N4_QW + N4_KW + N4_VW)
                                           { in = vw; hi = vwh; lo = vwl; base = N4_X + N4_QW + N4_KW; }
    else                                   { in = ow; hi = owh; lo = owl; base = N4_X + N4_QW + N4_KW + N4_VW; }
    int j4 = i - base;
    float4 v = ((const float4*)in)[j4];
    union { __nv_bfloat16 b[4]; uint2 u; } h, l;
    float f[4] = {v.x, v.y, v.z, v.w};
#pragma unroll
    for (int j = 0; j < 4; j++) {
        h.b[j] = __float2bfloat16(f[j]);
        l.b[j] = __float2bfloat16(f[j] - __bfloat162float(h.b[j]));
    }
    ((uint2*)hi)[j4] = h.u;
    ((uint2*)lo)[j4] = l.u;
}

// ---------------------------------------------------------------------------
// HMMA bf16 hi/lo-split GEMM with cp.async 3-stage pipeline.
// C[M,N] = A[M,K] * B[N,K]^T  (fp32 out), tile 128x128, BK=64.
// ---------------------------------------------------------------------------
#define TILE_B 16384
#define STAGE_B (4 * TILE_B)
#define GEMM_SMEM_BYTES (3 * STAGE_B + 1024)

__global__ __launch_bounds__(256) void gemm_mma_hl(
    const char* __restrict__ Ah, const char* __restrict__ Al,
    const char* __restrict__ Bh, const char* __restrict__ Bl,
    float* __restrict__ C, int Ntot, int K) {
    extern __shared__ __align__(16) char sm[];
    uint32_t ts = (smem_u32(sm) + 1023) & ~1023u;
    const uint32_t stage[3] = { ts, ts + STAGE_B, ts + 2 * STAGE_B };

    const int tid = threadIdx.x;
    const int lane = tid & 31;
    const int wid = tid >> 5;
    const int wm = wid >> 1;
    const int wn = wid & 1;
    const int m0 = blockIdx.y * 128;
    const int n0 = blockIdx.x * 128;
    const size_t K2 = (size_t)K * 2;

    const char* srcs[4] = { Ah + (size_t)m0 * K2, Al + (size_t)m0 * K2,
                            Bh + (size_t)n0 * K2, Bl + (size_t)n0 * K2 };

    const int u = tid & 7;
    const int r0 = tid >> 3;

    auto load_chunk = [&](int ch, uint32_t sb) {
        const size_t koff = (size_t)ch * 128 + u * 16;
#pragma unroll
        for (int t = 0; t < 4; t++) {
            const char* src = srcs[t] + koff;
            const uint32_t tb = sb + t * TILE_B;
#pragma unroll
            for (int it = 0; it < 4; it++) {
                const int row = it * 32 + r0;
                uint32_t off = row * 128 + u * 16;
                cpasync16(tb + SW128(off), src + (size_t)row * K2);
            }
        }
    };

    float acc[2][8][4];
#pragma unroll
    for (int a = 0; a < 2; a++)
#pragma unroll
        for (int b = 0; b < 8; b++)
#pragma unroll
            for (int cc = 0; cc < 4; cc++) acc[a][b][cc] = 0.f;

    const int amat = lane >> 3, arow = lane & 7;
    const int nch = K / 64;

    load_chunk(0, stage[0]);
    cpasync_commit();
    if (nch > 1) {
        load_chunk(1, stage[1]);
        cpasync_commit();
    }

    for (int ch = 0; ch < nch; ch++) {
        if (ch + 2 < nch) {
            load_chunk(ch + 2, stage[(ch + 2) % 3]);
            cpasync_commit();
            cpasync_wait<2>();
        } else if (ch + 1 < nch) {
            cpasync_wait<1>();
        } else {
            cpasync_wait<0>();
        }
        __syncthreads();

        const uint32_t sb = stage[ch % 3];
        const uint32_t tAh = sb, tAl = sb + TILE_B, tBh = sb + 2 * TILE_B, tBl = sb + 3 * TILE_B;
#pragma unroll
        for (int ks = 0; ks < 4; ks++) {
            uint32_t ah[2][4], al[2][4], bh[4][4], bl[4][4];
#pragma unroll
            for (int mb = 0; mb < 2; mb++) {
                int m = wm * 32 + mb * 16 + (amat & 1) * 8 + arow;
                int kb = ks * 32 + (amat >> 1) * 16;
                uint32_t off = SW128((uint32_t)(m * 128 + kb));
                ldsm_x4(ah[mb], tAh + off);
                ldsm_x4(al[mb], tAl + off);
            }
#pragma unroll
            for (int p = 0; p < 4; p++) {
                int n = wn * 64 + p * 16 + (amat >> 1) * 8 + arow;
                int kb = ks * 32 + (amat & 1) * 16;
                uint32_t off = SW128((uint32_t)(n * 128 + kb));
                ldsm_x4(bh[p], tBh + off);
                ldsm_x4(bl[p], tBl + off);
            }
#pragma unroll
            for (int mb = 0; mb < 2; mb++)
#pragma unroll
                for (int p = 0; p < 4; p++) {
                    mma16816(acc[mb][2 * p],     ah[mb], bh[p][0], bh[p][1]);
                    mma16816(acc[mb][2 * p + 1], ah[mb], bh[p][2], bh[p][3]);
                    mma16816(acc[mb][2 * p],     ah[mb], bl[p][0], bl[p][1]);
                    mma16816(acc[mb][2 * p + 1], ah[mb], bl[p][2], bl[p][3]);
                    mma16816(acc[mb][2 * p],     al[mb], bh[p][0], bh[p][1]);
                    mma16816(acc[mb][2 * p + 1], al[mb], bh[p][2], bh[p][3]);
                }
        }
        __syncthreads();
    }

    const int crow = lane >> 2;
    const int ccol = (lane & 3) * 2;
#pragma unroll
    for (int mb = 0; mb < 2; mb++) {
#pragma unroll
        for (int nb = 0; nb < 8; nb++) {
            int m = m0 + wm * 32 + mb * 16 + crow;
            int n = n0 + wn * 64 + nb * 8 + ccol;
            *(float2*)&C[(size_t)m * Ntot + n]       = make_float2(acc[mb][nb][0], acc[mb][nb][1]);
            *(float2*)&C[(size_t)(m + 8) * Ntot + n] = make_float2(acc[mb][nb][2], acc[mb][nb][3]);
        }
    }
}

// ---------------------------------------------------------------------------
// RMSNorm + RoPE (warp per vector) reading the fused QKV buffer;
// writes bf16 hi/lo q/k, q0/k0, |q|.
// ---------------------------------------------------------------------------
__global__ __launch_bounds__(256) void rms_rope_kernel(
    const float* __restrict__ qkv,
    char* __restrict__ qbh, char* __restrict__ qbl,
    char* __restrict__ kbh, char* __restrict__ kbl,
    float* __restrict__ q0, float* __restrict__ k0,
    float* __restrict__ qn, const float* __restrict__ curv) {
    const int wid = threadIdx.x >> 5;
    const int lane = threadIdx.x & 31;
    const int vi = blockIdx.x * 8 + wid;
    const int t = vi & 2047;
    const int hh = vi >> 11;

    const float* vec;
    size_t obase;
    char *oh, *ol;
    if (hh < NH) {
        vec = qkv + (size_t)t * NQKV + hh * HD;
        obase = ((size_t)t * NH + hh) * HD; oh = qbh; ol = qbl;
    } else {
        vec = qkv + (size_t)t * NQKV + 1024 + (hh - NH) * HD;
        obase = ((size_t)t * NKV + (hh - NH)) * HD; oh = kbh; ol = kbl;
    }
    float x1 = vec[lane], x2 = vec[lane + 32];
    float ss = x1 * x1 + x2 * x2;
#pragma unroll
    for (int o = 16; o >= 1; o >>= 1) ss += __shfl_xor_sync(0xffffffffu, ss, o);

    float inv = rsqrtf(ss * (1.0f / 64.0f) + EPSN);
    x1 *= inv; x2 *= inv;

    float invf = expf(-(float)lane * 0.28782313662425572f);
    float ang = (float)t * invf;
    float sv, cv;
    sincosf(ang, &sv, &cv);
    float o1 = fmaf(x1, cv, x2 * sv);
    float o2 = fmaf(-x1, sv, x2 * cv);

    float r1, r2;
    uint16_t h1 = bf_hi(o1, r1), h2 = bf_hi(o2, r2);
    ((uint16_t*)oh)[obase + lane]      = h1;
    ((uint16_t*)oh)[obase + lane + 32] = h2;
    ((uint16_t*)ol)[obase + lane]      = bf_of(r1);
    ((uint16_t*)ol)[obase + lane + 32] = bf_of(r2);

    if (lane == 0) {
        float sum2 = ss * inv * inv;
        float c = *curv;
        float h0 = sqrtf(1.0f / c + sum2);
        if (hh < NH) {
            q0[t * NH + hh] = h0;
            qn[t * NH + hh] = sqrtf(sum2);
        } else {
            k0[t * NKV + (hh - NH)] = h0;
        }
    }
}

// ---------------------------------------------------------------------------
// V slice conversion from fused buffer: fp32 [t][1280+j] -> bf16 hi/lo [t*256+j]
// ---------------------------------------------------------------------------
__global__ __launch_bounds__(256) void v_conv(const float* __restrict__ qkv,
                                              char* __restrict__ vbh,
                                              char* __restrict__ vbl) {
    int i = blockIdx.x * 256 + threadIdx.x;     // TT*64 float4's
    if (i >= TT * 64) return;
    int t = i >> 6, j = i & 63;
    float4 v = *(const float4*)&qkv[(size_t)t * NQKV + 1280 + j * 4];
    union { __nv_bfloat16 b[4]; uint2 u; } h, l;
    float f[4] = {v.x, v.y, v.z, v.w};
#pragma unroll
    for (int jj = 0; jj < 4; jj++) {
        h.b[jj] = __float2bfloat16(f[jj]);
        l.b[jj] = __float2bfloat16(f[jj] - __bfloat162float(h.b[jj]));
    }
    ((uint2*)vbh)[t * 64 + j] = h.u;
    ((uint2*)vbl)[t * 64 + j] = l.u;
}

// ---------------------------------------------------------------------------
// Tensor-core flash hyperbolic attention with cp.async 2-stage KV pipeline.
// ---------------------------------------------------------------------------
#define FA_STAGE_B 32768                 // kh/kl/vh/vl of 8KB each
#define FA_SMEM_BYTES (2 * FA_STAGE_B + 2048)

__global__ __launch_bounds__(128) void flash_attn_mma(
    const char* __restrict__ Qh, const char* __restrict__ Ql,
    const char* __restrict__ Kh, const char* __restrict__ Kl,
    const char* __restrict__ Vh, const char* __restrict__ Vl,
    const float* __restrict__ q0a, const float* __restrict__ k0a,
    const float* __restrict__ temp, const float* __restrict__ curv,
    char* __restrict__ ah, char* __restrict__ al) {
    extern __shared__ __align__(16) char smraw[];
    const uint32_t sb0 = (smem_u32(smraw) + 1023) & ~1023u;
    const uint32_t stg[2] = { sb0, sb0 + FA_STAGE_B };
    float* q0s = (float*)(smraw + (sb0 - smem_u32(smraw)) + 2 * FA_STAGE_B);
    float* k0st0 = q0s + 64;
    float* k0st1 = k0st0 + 64;

    const int tid = threadIdx.x;
    const int lane = tid & 31;
    const int wp = tid >> 5;
    const int h = blockIdx.y;
    const int t0 = ((int)gridDim.x - 1 - (int)blockIdx.x) * 64;
    const int kvh = h >> 2;

    const float c = *curv;
    const float sscale = rsqrtf(c) / temp[h];
    const float lo = 1.0f + 1e-5f;

    // ---- stage Q tile (hi/lo) into stage0 kh/kl ----
    {
        const char* qs[2] = { Qh, Ql };
        for (int idx = tid; idx < 1024; idx += 128) {
            int mtx = idx >> 9, rem = idx & 511, row = rem >> 3, u = rem & 7;
            const char* src = qs[mtx] + ((size_t)(t0 + row) * NH + h) * 128 + u * 16;
            sts128(stg[0] + mtx * 8192 + SW128((uint32_t)(row * 128 + u * 16)), *(const uint4*)src);
        }
        if (tid < 64) q0s[tid] = q0a[(t0 + tid) * NH + h];
    }
    __syncthreads();

    // ---- Q fragments to registers ----
    uint32_t qa_h[4][4], qa_l[4][4];
    {
        const int g = lane >> 3, lr = lane & 7;
        const int row = 16 * wp + (g & 1) * 8 + lr;
#pragma unroll
        for (int ks = 0; ks < 4; ks++) {
            uint32_t off = SW128((uint32_t)(row * 128 + ks * 32 + (g >> 1) * 16));
            ldsm_x4(qa_h[ks], stg[0] + off);
            ldsm_x4(qa_l[ks], stg[0] + 8192 + off);
        }
    }
    const int r = lane >> 2;
    const int colb = (lane & 3) * 2;
    const float q0r0 = q0s[16 * wp + r];
    const float q0r1 = q0s[16 * wp + 8 + r];
    __syncthreads();

    float o[8][4];
#pragma unroll
    for (int i = 0; i < 8; i++)
#pragma unroll
        for (int j = 0; j < 4; j++) o[i][j] = 0.f;
    float lsum0 = 0.f, lsum1 = 0.f;

    const char* kvsrc[4] = { Kh + kvh * 128, Kl + kvh * 128, Vh + kvh * 128, Vl + kvh * 128 };

    auto kv_load = [&](int c0, uint32_t sbase, float* k0dst) {
        for (int idx = tid; idx < 2048; idx += 128) {
            int mtx = idx >> 9, rem = idx & 511, row = rem >> 3, u = rem & 7;
            const char* src = kvsrc[mtx] + (size_t)(c0 + row) * 512 + u * 16;
            cpasync16(sbase + mtx * 8192 + SW128((uint32_t)(row * 128 + u * 16)), src);
        }
        if (tid < 64) k0dst[tid] = k0a[(c0 + tid) * NKV + kvh];
    };

    const int nt = t0 / 64 + 1;
    kv_load(0, stg[0], k0st0);
    cpasync_commit();

    for (int ch = 0; ch < nt; ch++) {
        if (ch + 1 < nt) {
            kv_load((ch + 1) * 64, stg[(ch + 1) & 1], ((ch + 1) & 1) ? k0st1 : k0st0);
            cpasync_commit();
            cpasync_wait<1>();
        } else {
            cpasync_wait<0>();
        }
        __syncthreads();

        const uint32_t sKh = stg[ch & 1], sKl = sKh + 8192, sVh = sKh + 16384, sVl = sKh + 24576;
        const float* k0s = (ch & 1) ? k0st1 : k0st0;

        // ---- S = Q K^T (3-term) ----
        float sc[8][4];
#pragma unroll
        for (int i = 0; i < 8; i++)
#pragma unroll
            for (int j = 0; j < 4; j++) sc[i][j] = 0.f;
        {
            const int g = lane >> 3, lr = lane & 7;
#pragma unroll
            for (int ks = 0; ks < 4; ks++) {
                const int dby = ks * 32 + (g >> 1) * 16;
#pragma unroll
                for (int p = 0; p < 4; p++) {
                    const int row = p * 16 + (g & 1) * 8 + lr;
                    uint32_t off = SW128((uint32_t)(row * 128 + dby));
                    uint32_t bh[4], bl[4];
                    ldsm_x4(bh, sKh + off);
                    ldsm_x4(bl, sKl + off);
                    mma16816(sc[2 * p],     qa_h[ks], bh[0], bh[2]);
                    mma16816(sc[2 * p + 1], qa_h[ks], bh[1], bh[3]);
                    mma16816(sc[2 * p],     qa_h[ks], bl[0], bl[2]);
                    mma16816(sc[2 * p + 1], qa_h[ks], bl[1], bl[3]);
                    mma16816(sc[2 * p],     qa_l[ks], bh[0], bh[2]);
                    mma16816(sc[2 * p + 1], qa_l[ks], bh[1], bh[3]);
                }
            }
        }

        // ---- hyperbolic transform -> weights; pack P hi/lo ----
        const bool diag = (ch == nt - 1);
        const int rl0 = 16 * wp + r, rl1 = rl0 + 8;
        uint32_t ph[4][4], pl[4][4];
#pragma unroll
        for (int nb = 0; nb < 8; nb++) {
            float k00 = k0s[nb * 8 + colb];
            float k01 = k0s[nb * 8 + colb + 1];
            float w0, w1, w2, w3;
            {
                float tt = fmaf(q0r0, k00, -sc[nb][0]);
                float arg = fmaxf(c * tt, lo);
                float z = arg + fsqrt_ap(fmaf(arg, arg, -1.f));
                w0 = __expf(-sscale * __logf(z));
            }
            {
                float tt = fmaf(q0r0, k01, -sc[nb][1]);
                float arg = fmaxf(c * tt, lo);
                float z = arg + fsqrt_ap(fmaf(arg, arg, -1.f));
                w1 = __expf(-sscale * __logf(z));
            }
            {
                float tt = fmaf(q0r1, k00, -sc[nb][2]);
                float arg = fmaxf(c * tt, lo);
                float z = arg + fsqrt_ap(fmaf(arg, arg, -1.f));
                w2 = __expf(-sscale * __logf(z));
            }
            {
                float tt = fmaf(q0r1, k01, -sc[nb][3]);
                float arg = fmaxf(c * tt, lo);
                float z = arg + fsqrt_ap(fmaf(arg, arg, -1.f));
                w3 = __expf(-sscale * __logf(z));
            }
            if (diag) {
                int cl0 = nb * 8 + colb, cl1 = cl0 + 1;
                if (cl0 > rl0) w0 = 0.f;
                if (cl1 > rl0) w1 = 0.f;
                if (cl0 > rl1) w2 = 0.f;
                if (cl1 > rl1) w3 = 0.f;
            }
            lsum0 += w0 + w1;
            lsum1 += w2 + w3;
            float r0f, r1f, r2f, r3f;
            uint32_t h01 = (uint32_t)bf_hi(w0, r0f) | ((uint32_t)bf_hi(w1, r1f) << 16);
            uint32_t h23 = (uint32_t)bf_hi(w2, r2f) | ((uint32_t)bf_hi(w3, r3f) << 16);
            uint32_t l01 = (uint32_t)bf_of(r0f) | ((uint32_t)bf_of(r1f) << 16);
            uint32_t l23 = (uint32_t)bf_of(r2f) | ((uint32_t)bf_of(r3f) << 16);
            int ks = nb >> 1, ix = (nb & 1) * 2;
            ph[ks][ix] = h01; ph[ks][ix + 1] = h23;
            pl[ks][ix] = l01; pl[ks][ix + 1] = l23;
        }

        // ---- O += P V (3-term) ----
        {
            const int g = lane >> 3, lr = lane & 7;
#pragma unroll
            for (int ks = 0; ks < 4; ks++) {
                const int rowv = ks * 16 + (g & 1) * 8 + lr;
#pragma unroll
                for (int dp = 0; dp < 4; dp++) {
                    uint32_t off = SW128((uint32_t)(rowv * 128 + dp * 32 + (g >> 1) * 16));
                    uint32_t bvh[4], bvl[4];
                    ldsm_x4_t(bvh, sVh + off);
                    ldsm_x4_t(bvl, sVl + off);
                    mma16816(o[2 * dp],     ph[ks], bvh[0], bvh[1]);
                    mma16816(o[2 * dp + 1], ph[ks], bvh[2], bvh[3]);
                    mma16816(o[2 * dp],     ph[ks], bvl[0], bvl[1]);
                    mma16816(o[2 * dp + 1], ph[ks], bvl[2], bvl[3]);
                    mma16816(o[2 * dp],     pl[ks], bvh[0], bvh[1]);
                    mma16816(o[2 * dp + 1], pl[ks], bvh[2], bvh[3]);
                }
            }
        }
        __syncthreads();
    }

    // ---- epilogue ----
    lsum0 += __shfl_xor_sync(0xffffffffu, lsum0, 1);
    lsum0 += __shfl_xor_sync(0xffffffffu, lsum0, 2);
    lsum1 += __shfl_xor_sync(0xffffffffu, lsum1, 1);
    lsum1 += __shfl_xor_sync(0xffffffffu, lsum1, 2);
    const float inv0 = 1.f / lsum0, inv1 = 1.f / lsum1;

    const int row0 = t0 + 16 * wp + r;
#pragma unroll
    for (int nb = 0; nb < 8; nb++) {
        int col = h * 64 + nb * 8 + colb;
        float a0 = o[nb][0] * inv0, a1 = o[nb][1] * inv0;
        float a2 = o[nb][2] * inv1, a3 = o[nb][3] * inv1;
        float r0f, r1f, r2f, r3f;
        uint32_t h01 = (uint32_t)bf_hi(a0, r0f) | ((uint32_t)bf_hi(a1, r1f) << 16);
        uint32_t h23 = (uint32_t)bf_hi(a2, r2f) | ((uint32_t)bf_hi(a3, r3f) << 16);
        uint32_t l01 = (uint32_t)bf_of(r0f) | ((uint32_t)bf_of(r1f) << 16);
        uint32_t l23 = (uint32_t)bf_of(r2f) | ((uint32_t)bf_of(r3f) << 16);
        size_t i0 = (size_t)row0 * DM + col;
        size_t i1 = (size_t)(row0 + 8) * DM + col;
        *(uint32_t*)(ah + i0 * 2) = h01;
        *(uint32_t*)(al + i0 * 2) = l01;
        *(uint32_t*)(ah + i1 * 2) = h23;
        *(uint32_t*)(al + i1 * 2) = l23;
    }
}

// ---------------------------------------------------------------------------
// spatial_norm: two-stage reduction
// ---------------------------------------------------------------------------
__global__ __launch_bounds__(256) void norm_partial(const float* __restrict__ qn,
                                                    float* __restrict__ part) {
    __shared__ float red[256];
    int tid = threadIdx.x;
    float s = 0.f;
    for (int i = blockIdx.x * 256 + tid; i < TT * NH; i += 32 * 256) s += qn[i];
    red[tid] = s;
    __syncthreads();
#pragma unroll
    for (int k = 128; k > 0; k >>= 1) {
        if (tid < k) red[tid] += red[tid + k];
        __syncthreads();
    }
    if (tid == 0) part[blockIdx.x] = red[0];
}
__global__ __launch_bounds__(32) void norm_final(const float* __restrict__ part,
                                                 float* __restrict__ out_scalar) {
    int tid = threadIdx.x;
    float s = part[tid];
#pragma unroll
    for (int o = 16; o >= 1; o >>= 1) s += __shfl_xor_sync(0xffffffffu, s, o);
    if (tid == 0) *out_scalar = s * (1.0f / (float)(TT * NH));
}

// ---------------------------------------------------------------------------
// Launch
// ---------------------------------------------------------------------------
extern "C" void kernel_launch(void* const* d_in, const int* in_sizes, int n_in,
                              void* d_out, int out_size) {
    const float* x    = (const float*)d_in[0];
    const float* q_w  = (const float*)d_in[1];
    const float* k_w  = (const float*)d_in[2];
    const float* v_w  = (const float*)d_in[3];
    const float* o_w  = (const float*)d_in[4];
    const float* temp = (const float*)d_in[5];
    const float* curv = (const float*)d_in[6];
    float* out = (float*)d_out;

    float *pqkv, *pq0, *pk0, *pqn, *ppart;
    char *xh, *xl, *wh, *wl, *owh, *owl, *ah, *al;
    char *qbh, *qbl, *kbh, *kbl, *vbh, *vbl;
    cudaGetSymbolAddress((void**)&pqkv, g_qkv);
    cudaGetSymbolAddress((void**)&pq0, g_q0);
    cudaGetSymbolAddress((void**)&pk0, g_k0);
    cudaGetSymbolAddress((void**)&pqn, g_qn);
    cudaGetSymbolAddress((void**)&ppart, g_part);
    cudaGetSymbolAddress((void**)&xh, g_xh);
    cudaGetSymbolAddress((void**)&xl, g_xl);
    cudaGetSymbolAddress((void**)&wh, g_wh);
    cudaGetSymbolAddress((void**)&wl, g_wl);
    cudaGetSymbolAddress((void**)&owh, g_owh);
    cudaGetSymbolAddress((void**)&owl, g_owl);
    cudaGetSymbolAddress((void**)&ah, g_ah);
    cudaGetSymbolAddress((void**)&al, g_al);
    cudaGetSymbolAddress((void**)&qbh, g_qbh);
    cudaGetSymbolAddress((void**)&qbl, g_qbl);
    cudaGetSymbolAddress((void**)&kbh, g_kbh);
    cudaGetSymbolAddress((void**)&kbl, g_kbl);
    cudaGetSymbolAddress((void**)&vbh, g_vbh);
    cudaGetSymbolAddress((void**)&vbl, g_vbl);

    cudaFuncSetAttribute(gemm_mma_hl, cudaFuncAttributeMaxDynamicSharedMemorySize,
                         GEMM_SMEM_BYTES);
    cudaFuncSetAttribute(flash_attn_mma, cudaFuncAttributeMaxDynamicSharedMemorySize,
                         FA_SMEM_BYTES);

    // weight hi/lo pointers into the concatenated buffer [q_w | k_w | v_w]
    char* qwh = wh;                         char* qwl = wl;
    char* kwh = wh + (size_t)1024 * DM * 2; char* kwl = wl + (size_t)1024 * DM * 2;
    char* vwh = wh + (size_t)1280 * DM * 2; char* vwl = wl + (size_t)1280 * DM * 2;

    // merged fp32 -> bf16 hi/lo conversions
    conv_all<<<(N4_TOT + 255) / 256, 256>>>(x, q_w, k_w, v_w, o_w,
                                            xh, xl, qwh, qwl, kwh, kwl,
                                            vwh, vwl, owh, owl);

    // Fused QKV projection (HMMA, 3-stage pipeline): [2048,1536]
    gemm_mma_hl<<<dim3(NQKV / 128, TT / 128), 256, GEMM_SMEM_BYTES>>>(
        xh, xl, wh, wl, pqkv, NQKV, DM);

    // RMSNorm + RoPE -> bf16 hi/lo q/k + q0/k0 + per-head norms
    rms_rope_kernel<<<TT * (NH + NKV) / 8, 256>>>(pqkv, qbh, qbl, kbh, kbl,
                                                  pq0, pk0, pqn, curv);
    // V slice -> bf16 hi/lo
    v_conv<<<(TT * 64 + 255) / 256, 256>>>(pqkv, vbh, vbl);

    // Tensor-core hyperbolic flash attention (pipelined KV)
    flash_attn_mma<<<dim3(TT / 64, NH), 128, FA_SMEM_BYTES>>>(
        qbh, qbl, kbh, kbl, vbh, vbl, pq0, pk0, temp, curv, ah, al);

    // Output projection (HMMA, pipelined)
    gemm_mma_hl<<<dim3(DM / 128, TT / 128), 256, GEMM_SMEM_BYTES>>>(
        ah, al, owh, owl, out, DM, DM);

    // spatial_norm scalar
    norm_partial<<<32, 256>>>(pqn, ppart);
    norm_final<<<1, 32>>>(ppart, out + (out_size - 1));
}

// round 9
// speedup vs baseline: 7.0194x; 1.0564x over previous
#include <cuda_runtime.h>
#include <cuda_bf16.h>
#include <math.h>
#include <stdint.h>

// Problem constants
#define TT    2048
#define DM    1024
#define NH    16
#define NKV   4
#define HD    64
#define EPSN  1e-6f
#define NQKV  1536   // fused projection width: 1024 q + 256 k + 256 v

// ---------------------------------------------------------------------------
// Device scratch (no cudaMalloc allowed)
// ---------------------------------------------------------------------------
__device__ float g_qkv[TT * NQKV];      // fused projection output (fp32)
__device__ float g_q0[TT * NH];
__device__ float g_k0[TT * NKV];
__device__ float g_qn[TT * NH];
__device__ float g_part[32];
// attention partial accumulators (unnormalized O, weight sums)
__device__ float g_oacc1[TT * DM], g_oacc2[TT * DM];
__device__ float g_lacc1[TT * NH], g_lacc2[TT * NH];

// bf16 hi/lo split storage
__device__ uint4 g_xh[TT * DM / 8],   g_xl[TT * DM / 8];
__device__ uint4 g_wh[NQKV * DM / 8], g_wl[NQKV * DM / 8];   // concat q_w|k_w|v_w
__device__ uint4 g_owh[DM * DM / 8],  g_owl[DM * DM / 8];
__device__ uint4 g_ah[TT * DM / 8],   g_al[TT * DM / 8];
__device__ uint4 g_qbh[TT * NH * HD / 8],  g_qbl[TT * NH * HD / 8];
__device__ uint4 g_kbh[TT * NKV * HD / 8], g_kbl[TT * NKV * HD / 8];
__device__ uint4 g_vbh[TT * NKV * HD / 8], g_vbl[TT * NKV * HD / 8];

// ---------------------------------------------------------------------------
// PTX helpers (baseline ISA only)
// ---------------------------------------------------------------------------
__device__ __forceinline__ uint32_t smem_u32(const void* p) {
    uint32_t a;
    asm("{ .reg .u64 t; cvta.to.shared.u64 t, %1; cvt.u32.u64 %0, t; }" : "=r"(a) : "l"(p));
    return a;
}
__device__ __forceinline__ void ldsm_x4(uint32_t* r, uint32_t addr) {
    asm volatile("ldmatrix.sync.aligned.m8n8.x4.shared.b16 {%0,%1,%2,%3}, [%4];"
                 : "=r"(r[0]), "=r"(r[1]), "=r"(r[2]), "=r"(r[3]) : "r"(addr));
}
__device__ __forceinline__ void ldsm_x4_t(uint32_t* r, uint32_t addr) {
    asm volatile("ldmatrix.sync.aligned.m8n8.x4.trans.shared.b16 {%0,%1,%2,%3}, [%4];"
                 : "=r"(r[0]), "=r"(r[1]), "=r"(r[2]), "=r"(r[3]) : "r"(addr));
}
__device__ __forceinline__ void mma16816(float* c, const uint32_t* a, uint32_t b0, uint32_t b1) {
    asm volatile("mma.sync.aligned.m16n8k16.row.col.f32.bf16.bf16.f32 "
                 "{%0,%1,%2,%3}, {%4,%5,%6,%7}, {%8,%9}, {%0,%1,%2,%3};"
                 : "+f"(c[0]), "+f"(c[1]), "+f"(c[2]), "+f"(c[3])
                 : "r"(a[0]), "r"(a[1]), "r"(a[2]), "r"(a[3]), "r"(b0), "r"(b1));
}
__device__ __forceinline__ void sts128(uint32_t addr, uint4 v) {
    asm volatile("st.shared.v4.b32 [%0], {%1,%2,%3,%4};"
                 :: "r"(addr), "r"(v.x), "r"(v.y), "r"(v.z), "r"(v.w) : "memory");
}
__device__ __forceinline__ void cpasync16(uint32_t dst, const void* src) {
    asm volatile("cp.async.cg.shared.global [%0], [%1], 16;" :: "r"(dst), "l"(src));
}
__device__ __forceinline__ void cpasync_commit() {
    asm volatile("cp.async.commit_group;" ::: "memory");
}
template <int N>
__device__ __forceinline__ void cpasync_wait() {
    asm volatile("cp.async.wait_group %0;" :: "n"(N) : "memory");
}
__device__ __forceinline__ float fsqrt_ap(float x) {
    float r;
    asm("sqrt.approx.f32 %0, %1;" : "=f"(r) : "f"(x));
    return r;
}
__device__ __forceinline__ float flg2(float x) {
    float r;
    asm("lg2.approx.f32 %0, %1;" : "=f"(r) : "f"(x));
    return r;
}
__device__ __forceinline__ float fex2(float x) {
    float r;
    asm("ex2.approx.f32 %0, %1;" : "=f"(r) : "f"(x));
    return r;
}
#define SW128(o) ((o) ^ (((o) >> 3) & 0x70))

__device__ __forceinline__ uint16_t bf_hi(float f, float& rem) {
    __nv_bfloat16 h = __float2bfloat16(f);
    rem = f - __bfloat162float(h);
    union { __nv_bfloat16 b; uint16_t u; } cv; cv.b = h;
    return cv.u;
}
__device__ __forceinline__ uint16_t bf_of(float f) {
    union { __nv_bfloat16 b; uint16_t u; } cv; cv.b = __float2bfloat16(f);
    return cv.u;
}

// ---------------------------------------------------------------------------
// Merged fp32 -> bf16 hi/lo conversion for all 5 input tensors.
// ---------------------------------------------------------------------------
#define N4_X  (TT * DM / 4)
#define N4_QW (DM * DM / 4)
#define N4_KW (256 * DM / 4)
#define N4_VW (256 * DM / 4)
#define N4_OW (DM * DM / 4)
#define N4_TOT (N4_X + N4_QW + N4_KW + N4_VW + N4_OW)

__global__ __launch_bounds__(256) void conv_all(
    const float* __restrict__ x, const float* __restrict__ qw,
    const float* __restrict__ kw, const float* __restrict__ vw,
    const float* __restrict__ ow,
    char* xh, char* xl, char* qwh, char* qwl, char* kwh, char* kwl,
    char* vwh, char* vwl, char* owh, char* owl) {
    int i = blockIdx.x * 256 + threadIdx.x;
    if (i >= N4_TOT) return;
    const float* in; char* hi; char* lo; int base;
    if (i < N4_X)                          { in = x;  hi = xh;  lo = xl;  base = 0; }
    else if (i < N4_X + N4_QW)             { in = qw; hi = qwh; lo = qwl; base = N4_X; }
    else if (i < N4_X + N4_QW + N4_KW)     { in = kw; hi = kwh; lo = kwl; base = N4_X + N4_QW; }
    else if (i < N4_X + N4_QW + N4_KW + N4_VW)
                                           { in = vw; hi = vwh; lo = vwl; base = N4_X + N4_QW + N4_KW; }
    else                                   { in = ow; hi = owh; lo = owl; base = N4_X + N4_QW + N4_KW + N4_VW; }
    int j4 = i - base;
    float4 v = ((const float4*)in)[j4];
    union { __nv_bfloat16 b[4]; uint2 u; } h, l;
    float f[4] = {v.x, v.y, v.z, v.w};
#pragma unroll
    for (int j = 0; j < 4; j++) {
        h.b[j] = __float2bfloat16(f[j]);
        l.b[j] = __float2bfloat16(f[j] - __bfloat162float(h.b[j]));
    }
    ((uint2*)hi)[j4] = h.u;
    ((uint2*)lo)[j4] = l.u;
}

// ---------------------------------------------------------------------------
// HMMA bf16 hi/lo-split GEMM with cp.async 3-stage pipeline.
// ---------------------------------------------------------------------------
#define TILE_B 16384
#define STAGE_B (4 * TILE_B)
#define GEMM_SMEM_BYTES (3 * STAGE_B + 1024)

__global__ __launch_bounds__(256) void gemm_mma_hl(
    const char* __restrict__ Ah, const char* __restrict__ Al,
    const char* __restrict__ Bh, const char* __restrict__ Bl,
    float* __restrict__ C, int Ntot, int K) {
    extern __shared__ __align__(16) char sm[];
    uint32_t ts = (smem_u32(sm) + 1023) & ~1023u;
    const uint32_t stage[3] = { ts, ts + STAGE_B, ts + 2 * STAGE_B };

    const int tid = threadIdx.x;
    const int lane = tid & 31;
    const int wid = tid >> 5;
    const int wm = wid >> 1;
    const int wn = wid & 1;
    const int m0 = blockIdx.y * 128;
    const int n0 = blockIdx.x * 128;
    const size_t K2 = (size_t)K * 2;

    const char* srcs[4] = { Ah + (size_t)m0 * K2, Al + (size_t)m0 * K2,
                            Bh + (size_t)n0 * K2, Bl + (size_t)n0 * K2 };

    const int u = tid & 7;
    const int r0 = tid >> 3;

    auto load_chunk = [&](int ch, uint32_t sb) {
        const size_t koff = (size_t)ch * 128 + u * 16;
#pragma unroll
        for (int t = 0; t < 4; t++) {
            const char* src = srcs[t] + koff;
            const uint32_t tb = sb + t * TILE_B;
#pragma unroll
            for (int it = 0; it < 4; it++) {
                const int row = it * 32 + r0;
                uint32_t off = row * 128 + u * 16;
                cpasync16(tb + SW128(off), src + (size_t)row * K2);
            }
        }
    };

    float acc[2][8][4];
#pragma unroll
    for (int a = 0; a < 2; a++)
#pragma unroll
        for (int b = 0; b < 8; b++)
#pragma unroll
            for (int cc = 0; cc < 4; cc++) acc[a][b][cc] = 0.f;

    const int amat = lane >> 3, arow = lane & 7;
    const int nch = K / 64;

    load_chunk(0, stage[0]);
    cpasync_commit();
    if (nch > 1) {
        load_chunk(1, stage[1]);
        cpasync_commit();
    }

    for (int ch = 0; ch < nch; ch++) {
        if (ch + 2 < nch) {
            load_chunk(ch + 2, stage[(ch + 2) % 3]);
            cpasync_commit();
            cpasync_wait<2>();
        } else if (ch + 1 < nch) {
            cpasync_wait<1>();
        } else {
            cpasync_wait<0>();
        }
        __syncthreads();

        const uint32_t sb = stage[ch % 3];
        const uint32_t tAh = sb, tAl = sb + TILE_B, tBh = sb + 2 * TILE_B, tBl = sb + 3 * TILE_B;
#pragma unroll
        for (int ks = 0; ks < 4; ks++) {
            uint32_t ah[2][4], al[2][4], bh[4][4], bl[4][4];
#pragma unroll
            for (int mb = 0; mb < 2; mb++) {
                int m = wm * 32 + mb * 16 + (amat & 1) * 8 + arow;
                int kb = ks * 32 + (amat >> 1) * 16;
                uint32_t off = SW128((uint32_t)(m * 128 + kb));
                ldsm_x4(ah[mb], tAh + off);
                ldsm_x4(al[mb], tAl + off);
            }
#pragma unroll
            for (int p = 0; p < 4; p++) {
                int n = wn * 64 + p * 16 + (amat >> 1) * 8 + arow;
                int kb = ks * 32 + (amat & 1) * 16;
                uint32_t off = SW128((uint32_t)(n * 128 + kb));
                ldsm_x4(bh[p], tBh + off);
                ldsm_x4(bl[p], tBl + off);
            }
#pragma unroll
            for (int mb = 0; mb < 2; mb++)
#pragma unroll
                for (int p = 0; p < 4; p++) {
                    mma16816(acc[mb][2 * p],     ah[mb], bh[p][0], bh[p][1]);
                    mma16816(acc[mb][2 * p + 1], ah[mb], bh[p][2], bh[p][3]);
                    mma16816(acc[mb][2 * p],     ah[mb], bl[p][0], bl[p][1]);
                    mma16816(acc[mb][2 * p + 1], ah[mb], bl[p][2], bl[p][3]);
                    mma16816(acc[mb][2 * p],     al[mb], bh[p][0], bh[p][1]);
                    mma16816(acc[mb][2 * p + 1], al[mb], bh[p][2], bh[p][3]);
                }
        }
        __syncthreads();
    }

    const int crow = lane >> 2;
    const int ccol = (lane & 3) * 2;
#pragma unroll
    for (int mb = 0; mb < 2; mb++) {
#pragma unroll
        for (int nb = 0; nb < 8; nb++) {
            int m = m0 + wm * 32 + mb * 16 + crow;
            int n = n0 + wn * 64 + nb * 8 + ccol;
            *(float2*)&C[(size_t)m * Ntot + n]       = make_float2(acc[mb][nb][0], acc[mb][nb][1]);
            *(float2*)&C[(size_t)(m + 8) * Ntot + n] = make_float2(acc[mb][nb][2], acc[mb][nb][3]);
        }
    }
}

// ---------------------------------------------------------------------------
// RMSNorm + RoPE; q/k additionally scaled by sqrt(c) so attention needs no
// per-score curvature multiply. q0/k0 store sqrt(1 + c*|v|^2).
// ---------------------------------------------------------------------------
__global__ __launch_bounds__(256) void rms_rope_kernel(
    const float* __restrict__ qkv,
    char* __restrict__ qbh, char* __restrict__ qbl,
    char* __restrict__ kbh, char* __restrict__ kbl,
    float* __restrict__ q0, float* __restrict__ k0,
    float* __restrict__ qn, const float* __restrict__ curv) {
    const int wid = threadIdx.x >> 5;
    const int lane = threadIdx.x & 31;
    const int vi = blockIdx.x * 8 + wid;
    const int t = vi & 2047;
    const int hh = vi >> 11;

    const float* vec;
    size_t obase;
    char *oh, *ol;
    if (hh < NH) {
        vec = qkv + (size_t)t * NQKV + hh * HD;
        obase = ((size_t)t * NH + hh) * HD; oh = qbh; ol = qbl;
    } else {
        vec = qkv + (size_t)t * NQKV + 1024 + (hh - NH) * HD;
        obase = ((size_t)t * NKV + (hh - NH)) * HD; oh = kbh; ol = kbl;
    }
    float x1 = vec[lane], x2 = vec[lane + 32];
    float ss = x1 * x1 + x2 * x2;
#pragma unroll
    for (int o = 16; o >= 1; o >>= 1) ss += __shfl_xor_sync(0xffffffffu, ss, o);

    float inv = rsqrtf(ss * (1.0f / 64.0f) + EPSN);
    x1 *= inv; x2 *= inv;

    float invf = expf(-(float)lane * 0.28782313662425572f);
    float ang = (float)t * invf;
    float sv, cv;
    sincosf(ang, &sv, &cv);
    float c = *curv;
    float sqc = sqrtf(c);
    float o1 = fmaf(x1, cv, x2 * sv) * sqc;
    float o2 = fmaf(-x1, sv, x2 * cv) * sqc;

    float r1, r2;
    uint16_t h1 = bf_hi(o1, r1), h2 = bf_hi(o2, r2);
    ((uint16_t*)oh)[obase + lane]      = h1;
    ((uint16_t*)oh)[obase + lane + 32] = h2;
    ((uint16_t*)ol)[obase + lane]      = bf_of(r1);
    ((uint16_t*)ol)[obase + lane + 32] = bf_of(r2);

    if (lane == 0) {
        float sum2 = ss * inv * inv;
        float h0 = sqrtf(1.0f + c * sum2);   // sqrt(c)*sqrt(1/c + |v|^2)
        if (hh < NH) {
            q0[t * NH + hh] = h0;
            qn[t * NH + hh] = sqrtf(sum2);
        } else {
            k0[t * NKV + (hh - NH)] = h0;
        }
    }
}

// ---------------------------------------------------------------------------
// V slice conversion from fused buffer
// ---------------------------------------------------------------------------
__global__ __launch_bounds__(256) void v_conv(const float* __restrict__ qkv,
                                              char* __restrict__ vbh,
                                              char* __restrict__ vbl) {
    int i = blockIdx.x * 256 + threadIdx.x;
    if (i >= TT * 64) return;
    int t = i >> 6, j = i & 63;
    float4 v = *(const float4*)&qkv[(size_t)t * NQKV + 1280 + j * 4];
    union { __nv_bfloat16 b[4]; uint2 u; } h, l;
    float f[4] = {v.x, v.y, v.z, v.w};
#pragma unroll
    for (int jj = 0; jj < 4; jj++) {
        h.b[jj] = __float2bfloat16(f[jj]);
        l.b[jj] = __float2bfloat16(f[jj] - __bfloat162float(h.b[jj]));
    }
    ((uint2*)vbh)[t * 64 + j] = h.u;
    ((uint2*)vbl)[t * 64 + j] = l.u;
}

// ---------------------------------------------------------------------------
// Tensor-core flash hyperbolic attention; split-K for load balance.
// Grid (NH, 48): c<32 -> split halves of qtiles 31..16; c>=32 -> qtiles 15..0.
// Partials (unnormalized O, weight sums) -> oacc1/lacc1 (first half) or
// oacc2/lacc2 (second half). merge_norm combines.
// ---------------------------------------------------------------------------
#define FA_STAGE_B 32768
#define FA_SMEM_BYTES (2 * FA_STAGE_B + 2048)

__global__ __launch_bounds__(128) void flash_attn_mma(
    const char* __restrict__ Qh, const char* __restrict__ Ql,
    const char* __restrict__ Kh, const char* __restrict__ Kl,
    const char* __restrict__ Vh, const char* __restrict__ Vl,
    const float* __restrict__ q0a, const float* __restrict__ k0a,
    const float* __restrict__ temp, const float* __restrict__ curv,
    float* __restrict__ oacc1, float* __restrict__ oacc2,
    float* __restrict__ lacc1, float* __restrict__ lacc2) {
    extern __shared__ __align__(16) char smraw[];
    const uint32_t sb0 = (smem_u32(smraw) + 1023) & ~1023u;
    const uint32_t stg[2] = { sb0, sb0 + FA_STAGE_B };
    float* q0s = (float*)(smraw + (sb0 - smem_u32(smraw)) + 2 * FA_STAGE_B);
    float* k0st0 = q0s + 64;
    float* k0st1 = k0st0 + 64;

    const int tid = threadIdx.x;
    const int lane = tid & 31;
    const int wp = tid >> 5;
    const int h = blockIdx.x;
    const int cidx = blockIdx.y;

    int qt, tl0, tl1;
    if (cidx < 32) {
        qt = 31 - (cidx >> 1);
        int nt = qt + 1, mid = nt >> 1;
        if (cidx & 1) { tl0 = mid; tl1 = nt; }
        else          { tl0 = 0;   tl1 = mid; }
    } else {
        qt = 47 - cidx;
        tl0 = 0; tl1 = qt + 1;
    }
    const int t0 = qt * 64;
    const int kvh = h >> 2;

    float* ob = (tl0 == 0) ? oacc1 : oacc2;
    float* lb = (tl0 == 0) ? lacc1 : lacc2;

    const float sscale = rsqrtf(*curv) / temp[h];
    const float loclamp = 1.0f + 1e-5f;

    // ---- stage Q tile (hi/lo) into stage0 ----
    {
        const char* qs[2] = { Qh, Ql };
        for (int idx = tid; idx < 1024; idx += 128) {
            int mtx = idx >> 9, rem = idx & 511, row = rem >> 3, u = rem & 7;
            const char* src = qs[mtx] + ((size_t)(t0 + row) * NH + h) * 128 + u * 16;
            sts128(stg[0] + mtx * 8192 + SW128((uint32_t)(row * 128 + u * 16)), *(const uint4*)src);
        }
        if (tid < 64) q0s[tid] = q0a[(t0 + tid) * NH + h];
    }
    __syncthreads();

    // ---- Q fragments to registers ----
    uint32_t qa_h[4][4], qa_l[4][4];
    {
        const int g = lane >> 3, lr = lane & 7;
        const int row = 16 * wp + (g & 1) * 8 + lr;
#pragma unroll
        for (int ks = 0; ks < 4; ks++) {
            uint32_t off = SW128((uint32_t)(row * 128 + ks * 32 + (g >> 1) * 16));
            ldsm_x4(qa_h[ks], stg[0] + off);
            ldsm_x4(qa_l[ks], stg[0] + 8192 + off);
        }
    }
    const int r = lane >> 2;
    const int colb = (lane & 3) * 2;
    const float q0r0 = q0s[16 * wp + r];
    const float q0r1 = q0s[16 * wp + 8 + r];
    __syncthreads();

    float o[8][4];
#pragma unroll
    for (int i = 0; i < 8; i++)
#pragma unroll
        for (int j = 0; j < 4; j++) o[i][j] = 0.f;
    float lsum0 = 0.f, lsum1 = 0.f;

    const char* kvsrc[4] = { Kh + kvh * 128, Kl + kvh * 128, Vh + kvh * 128, Vl + kvh * 128 };

    auto kv_load = [&](int c0, uint32_t sbase, float* k0dst) {
        for (int idx = tid; idx < 2048; idx += 128) {
            int mtx = idx >> 9, rem = idx & 511, row = rem >> 3, u = rem & 7;
            const char* src = kvsrc[mtx] + (size_t)(c0 + row) * 512 + u * 16;
            cpasync16(sbase + mtx * 8192 + SW128((uint32_t)(row * 128 + u * 16)), src);
        }
        if (tid < 64) k0dst[tid] = k0a[(c0 + tid) * NKV + kvh];
    };

    kv_load(tl0 * 64, stg[tl0 & 1], (tl0 & 1) ? k0st1 : k0st0);
    cpasync_commit();

    for (int ch = tl0; ch < tl1; ch++) {
        if (ch + 1 < tl1) {
            kv_load((ch + 1) * 64, stg[(ch + 1) & 1], ((ch + 1) & 1) ? k0st1 : k0st0);
            cpasync_commit();
            cpasync_wait<1>();
        } else {
            cpasync_wait<0>();
        }
        __syncthreads();

        const uint32_t sKh = stg[ch & 1], sKl = sKh + 8192, sVh = sKh + 16384, sVl = sKh + 24576;
        const float* k0s = (ch & 1) ? k0st1 : k0st0;

        // ---- S = Q K^T (3-term) ----
        float sc[8][4];
#pragma unroll
        for (int i = 0; i < 8; i++)
#pragma unroll
            for (int j = 0; j < 4; j++) sc[i][j] = 0.f;
        {
            const int g = lane >> 3, lr = lane & 7;
#pragma unroll
            for (int ks = 0; ks < 4; ks++) {
                const int dby = ks * 32 + (g >> 1) * 16;
#pragma unroll
                for (int p = 0; p < 4; p++) {
                    const int row = p * 16 + (g & 1) * 8 + lr;
                    uint32_t off = SW128((uint32_t)(row * 128 + dby));
                    uint32_t bh[4], bl[4];
                    ldsm_x4(bh, sKh + off);
                    ldsm_x4(bl, sKl + off);
                    mma16816(sc[2 * p],     qa_h[ks], bh[0], bh[2]);
                    mma16816(sc[2 * p + 1], qa_h[ks], bh[1], bh[3]);
                    mma16816(sc[2 * p],     qa_h[ks], bl[0], bl[2]);
                    mma16816(sc[2 * p + 1], qa_h[ks], bl[1], bl[3]);
                    mma16816(sc[2 * p],     qa_l[ks], bh[0], bh[2]);
                    mma16816(sc[2 * p + 1], qa_l[ks], bh[1], bh[3]);
                }
            }
        }

        // ---- hyperbolic transform -> weights; pack P hi/lo ----
        const bool diag = (ch == qt);
        const int rl0 = 16 * wp + r, rl1 = rl0 + 8;
        uint32_t ph[4][4], pl[4][4];
#pragma unroll
        for (int nb = 0; nb < 8; nb++) {
            float k00 = k0s[nb * 8 + colb];
            float k01 = k0s[nb * 8 + colb + 1];
            float w0, w1, w2, w3;
            {
                float arg = fmaxf(fmaf(q0r0, k00, -sc[nb][0]), loclamp);
                float z = arg + fsqrt_ap(fmaf(arg, arg, -1.f));
                w0 = fex2(-sscale * flg2(z));
            }
            {
                float arg = fmaxf(fmaf(q0r0, k01, -sc[nb][1]), loclamp);
                float z = arg + fsqrt_ap(fmaf(arg, arg, -1.f));
                w1 = fex2(-sscale * flg2(z));
            }
            {
                float arg = fmaxf(fmaf(q0r1, k00, -sc[nb][2]), loclamp);
                float z = arg + fsqrt_ap(fmaf(arg, arg, -1.f));
                w2 = fex2(-sscale * flg2(z));
            }
            {
                float arg = fmaxf(fmaf(q0r1, k01, -sc[nb][3]), loclamp);
                float z = arg + fsqrt_ap(fmaf(arg, arg, -1.f));
                w3 = fex2(-sscale * flg2(z));
            }
            if (diag) {
                int cl0 = nb * 8 + colb, cl1 = cl0 + 1;
                if (cl0 > rl0) w0 = 0.f;
                if (cl1 > rl0) w1 = 0.f;
                if (cl0 > rl1) w2 = 0.f;
                if (cl1 > rl1) w3 = 0.f;
            }
            lsum0 += w0 + w1;
            lsum1 += w2 + w3;
            float r0f, r1f, r2f, r3f;
            uint32_t h01 = (uint32_t)bf_hi(w0, r0f) | ((uint32_t)bf_hi(w1, r1f) << 16);
            uint32_t h23 = (uint32_t)bf_hi(w2, r2f) | ((uint32_t)bf_hi(w3, r3f) << 16);
            uint32_t l01 = (uint32_t)bf_of(r0f) | ((uint32_t)bf_of(r1f) << 16);
            uint32_t l23 = (uint32_t)bf_of(r2f) | ((uint32_t)bf_of(r3f) << 16);
            int ks = nb >> 1, ix = (nb & 1) * 2;
            ph[ks][ix] = h01; ph[ks][ix + 1] = h23;
            pl[ks][ix] = l01; pl[ks][ix + 1] = l23;
        }

        // ---- O += P V (3-term) ----
        {
            const int g = lane >> 3, lr = lane & 7;
#pragma unroll
            for (int ks = 0; ks < 4; ks++) {
                const int rowv = ks * 16 + (g & 1) * 8 + lr;
#pragma unroll
                for (int dp = 0; dp < 4; dp++) {
                    uint32_t off = SW128((uint32_t)(rowv * 128 + dp * 32 + (g >> 1) * 16));
                    uint32_t bvh[4], bvl[4];
                    ldsm_x4_t(bvh, sVh + off);
                    ldsm_x4_t(bvl, sVl + off);
                    mma16816(o[2 * dp],     ph[ks], bvh[0], bvh[1]);
                    mma16816(o[2 * dp + 1], ph[ks], bvh[2], bvh[3]);
                    mma16816(o[2 * dp],     ph[ks], bvl[0], bvl[1]);
                    mma16816(o[2 * dp + 1], ph[ks], bvl[2], bvl[3]);
                    mma16816(o[2 * dp],     pl[ks], bvh[0], bvh[1]);
                    mma16816(o[2 * dp + 1], pl[ks], bvh[2], bvh[3]);
                }
            }
        }
        __syncthreads();
    }

    // ---- epilogue: store unnormalized partials ----
    lsum0 += __shfl_xor_sync(0xffffffffu, lsum0, 1);
    lsum0 += __shfl_xor_sync(0xffffffffu, lsum0, 2);
    lsum1 += __shfl_xor_sync(0xffffffffu, lsum1, 1);
    lsum1 += __shfl_xor_sync(0xffffffffu, lsum1, 2);

    const int row0 = t0 + 16 * wp + r;
#pragma unroll
    for (int nb = 0; nb < 8; nb++) {
        int col = h * 64 + nb * 8 + colb;
        *(float2*)&ob[(size_t)row0 * DM + col]       = make_float2(o[nb][0], o[nb][1]);
        *(float2*)&ob[(size_t)(row0 + 8) * DM + col] = make_float2(o[nb][2], o[nb][3]);
    }
    if ((lane & 3) == 0) {
        lb[row0 * NH + h] = lsum0;
        lb[(row0 + 8) * NH + h] = lsum1;
    }
}

// ---------------------------------------------------------------------------
// merge split partials, normalize, emit bf16 hi/lo attn output.
// qtiles >= 16 (t >= 1024) have two partials.
// ---------------------------------------------------------------------------
__global__ __launch_bounds__(256) void merge_norm(
    const float* __restrict__ oacc1, const float* __restrict__ oacc2,
    const float* __restrict__ lacc1, const float* __restrict__ lacc2,
    char* __restrict__ ah, char* __restrict__ al) {
    int j = threadIdx.x;
    int rowid = blockIdx.x * 16 + (j >> 4);       // (t,h) index: t*16+h
    int t = rowid >> 4;
    int hh = rowid & 15;
    int dd = (j & 15) * 4;
    bool two = (t >= 1024);

    float l = lacc1[rowid] + (two ? lacc2[rowid] : 0.f);
    size_t base = (size_t)t * DM + hh * 64 + dd;
    float4 ov = *(const float4*)&oacc1[base];
    if (two) {
        float4 o2 = *(const float4*)&oacc2[base];
        ov.x += o2.x; ov.y += o2.y; ov.z += o2.z; ov.w += o2.w;
    }
    float invl = 1.0f / l;
    float f[4] = {ov.x * invl, ov.y * invl, ov.z * invl, ov.w * invl};
    union { uint16_t u[4]; uint2 v; } hb, lb2;
#pragma unroll
    for (int k = 0; k < 4; k++) {
        float rem;
        hb.u[k] = bf_hi(f[k], rem);
        lb2.u[k] = bf_of(rem);
    }
    *(uint2*)(ah + base * 2) = hb.v;
    *(uint2*)(al + base * 2) = lb2.v;
}

// ---------------------------------------------------------------------------
// spatial_norm: two-stage reduction
// ---------------------------------------------------------------------------
__global__ __launch_bounds__(256) void norm_partial(const float* __restrict__ qn,
                                                    float* __restrict__ part) {
    __shared__ float red[256];
    int tid = threadIdx.x;
    float s = 0.f;
    for (int i = blockIdx.x * 256 + tid; i < TT * NH; i += 32 * 256) s += qn[i];
    red[tid] = s;
    __syncthreads();
#pragma unroll
    for (int k = 128; k > 0; k >>= 1) {
        if (tid < k) red[tid] += red[tid + k];
        __syncthreads();
    }
    if (tid == 0) part[blockIdx.x] = red[0];
}
__global__ __launch_bounds__(32) void norm_final(const float* __restrict__ part,
                                                 float* __restrict__ out_scalar) {
    int tid = threadIdx.x;
    float s = part[tid];
#pragma unroll
    for (int o = 16; o >= 1; o >>= 1) s += __shfl_xor_sync(0xffffffffu, s, o);
    if (tid == 0) *out_scalar = s * (1.0f / (float)(TT * NH));
}

// ---------------------------------------------------------------------------
// Launch
// ---------------------------------------------------------------------------
extern "C" void kernel_launch(void* const* d_in, const int* in_sizes, int n_in,
                              void* d_out, int out_size) {
    const float* x    = (const float*)d_in[0];
    const float* q_w  = (const float*)d_in[1];
    const float* k_w  = (const float*)d_in[2];
    const float* v_w  = (const float*)d_in[3];
    const float* o_w  = (const float*)d_in[4];
    const float* temp = (const float*)d_in[5];
    const float* curv = (const float*)d_in[6];
    float* out = (float*)d_out;

    float *pqkv, *pq0, *pk0, *pqn, *ppart, *po1, *po2, *pl1, *pl2;
    char *xh, *xl, *wh, *wl, *owh, *owl, *ah, *al;
    char *qbh, *qbl, *kbh, *kbl, *vbh, *vbl;
    cudaGetSymbolAddress((void**)&pqkv, g_qkv);
    cudaGetSymbolAddress((void**)&pq0, g_q0);
    cudaGetSymbolAddress((void**)&pk0, g_k0);
    cudaGetSymbolAddress((void**)&pqn, g_qn);
    cudaGetSymbolAddress((void**)&ppart, g_part);
    cudaGetSymbolAddress((void**)&po1, g_oacc1);
    cudaGetSymbolAddress((void**)&po2, g_oacc2);
    cudaGetSymbolAddress((void**)&pl1, g_lacc1);
    cudaGetSymbolAddress((void**)&pl2, g_lacc2);
    cudaGetSymbolAddress((void**)&xh, g_xh);
    cudaGetSymbolAddress((void**)&xl, g_xl);
    cudaGetSymbolAddress((void**)&wh, g_wh);
    cudaGetSymbolAddress((void**)&wl, g_wl);
    cudaGetSymbolAddress((void**)&owh, g_owh);
    cudaGetSymbolAddress((void**)&owl, g_owl);
    cudaGetSymbolAddress((void**)&ah, g_ah);
    cudaGetSymbolAddress((void**)&al, g_al);
    cudaGetSymbolAddress((void**)&qbh, g_qbh);
    cudaGetSymbolAddress((void**)&qbl, g_qbl);
    cudaGetSymbolAddress((void**)&kbh, g_kbh);
    cudaGetSymbolAddress((void**)&kbl, g_kbl);
    cudaGetSymbolAddress((void**)&vbh, g_vbh);
    cudaGetSymbolAddress((void**)&vbl, g_vbl);

    cudaFuncSetAttribute(gemm_mma_hl, cudaFuncAttributeMaxDynamicSharedMemorySize,
                         GEMM_SMEM_BYTES);
    cudaFuncSetAttribute(flash_attn_mma, cudaFuncAttributeMaxDynamicSharedMemorySize,
                         FA_SMEM_BYTES);

    // weight hi/lo pointers into the concatenated buffer [q_w | k_w | v_w]
    char* qwh = wh;                         char* qwl = wl;
    char* kwh = wh + (size_t)1024 * DM * 2; char* kwl = wl + (size_t)1024 * DM * 2;
    char* vwh = wh + (size_t)1280 * DM * 2; char* vwl = wl + (size_t)1280 * DM * 2;

    // merged fp32 -> bf16 hi/lo conversions
    conv_all<<<(N4_TOT + 255) / 256, 256>>>(x, q_w, k_w, v_w, o_w,
                                            xh, xl, qwh, qwl, kwh, kwl,
                                            vwh, vwl, owh, owl);

    // Fused QKV projection (HMMA, 3-stage pipeline)
    gemm_mma_hl<<<dim3(NQKV / 128, TT / 128), 256, GEMM_SMEM_BYTES>>>(
        xh, xl, wh, wl, pqkv, NQKV, DM);

    // RMSNorm + RoPE (+ sqrt(c) prescale) -> bf16 hi/lo q/k + q0/k0 + norms
    rms_rope_kernel<<<TT * (NH + NKV) / 8, 256>>>(pqkv, qbh, qbl, kbh, kbl,
                                                  pq0, pk0, pqn, curv);
    // V slice -> bf16 hi/lo
    v_conv<<<(TT * 64 + 255) / 256, 256>>>(pqkv, vbh, vbl);

    // Split-K tensor-core hyperbolic flash attention
    flash_attn_mma<<<dim3(NH, 48), 128, FA_SMEM_BYTES>>>(
        qbh, qbl, kbh, kbl, vbh, vbl, pq0, pk0, temp, curv,
        po1, po2, pl1, pl2);

    // merge + normalize -> bf16 hi/lo attn
    merge_norm<<<TT * NH / 16, 256>>>(po1, po2, pl1, pl2, ah, al);

    // Output projection (HMMA, pipelined)
    gemm_mma_hl<<<dim3(DM / 128, TT / 128), 256, GEMM_SMEM_BYTES>>>(
        ah, al, owh, owl, out, DM, DM);

    // spatial_norm scalar
    norm_partial<<<32, 256>>>(pqn, ppart);
    norm_final<<<1, 32>>>(ppart, out + (out_size - 1));
}

// round 11
// speedup vs baseline: 7.2992x; 1.0399x over previous
#include <cuda_runtime.h>
#include <cuda_bf16.h>
#include <math.h>
#include <stdint.h>

// Problem constants
#define TT    2048
#define DM    1024
#define NH    16
#define NKV   4
#define HD    64
#define EPSN  1e-6f
#define NQKV  1536   // fused projection width: 1024 q + 256 k + 256 v

// ---------------------------------------------------------------------------
// Device scratch (no cudaMalloc allowed)
// ---------------------------------------------------------------------------
__device__ float g_qkv[TT * NQKV];
__device__ float g_q0[TT * NH];
__device__ float g_k0[TT * NKV];
__device__ float g_qn[TT * NH];
__device__ float g_part[32];
__device__ float g_oacc1[TT * DM], g_oacc2[TT * DM];
__device__ float g_lacc1[TT * NH], g_lacc2[TT * NH];

// bf16 hi/lo split storage
__device__ uint4 g_xh[TT * DM / 8],   g_xl[TT * DM / 8];
__device__ uint4 g_wh[NQKV * DM / 8], g_wl[NQKV * DM / 8];
__device__ uint4 g_owh[DM * DM / 8],  g_owl[DM * DM / 8];
__device__ uint4 g_ah[TT * DM / 8],   g_al[TT * DM / 8];
__device__ uint4 g_qbh[TT * NH * HD / 8],  g_qbl[TT * NH * HD / 8];
__device__ uint4 g_kbh[TT * NKV * HD / 8], g_kbl[TT * NKV * HD / 8];
__device__ uint4 g_vbh[TT * NKV * HD / 8], g_vbl[TT * NKV * HD / 8];

// attention work-item schedule (heavy first): (block b, tile range [t0,t1))
__constant__ int c_ib[24]  = {15,15, 7,14,14,13,13, 6,12,12,11,11, 5,10,10, 9, 9, 4, 8, 8, 3, 2, 1, 0};
__constant__ int c_it0[24] = { 0,16, 0, 0,15, 0,14, 0, 0,13, 0,12, 0, 0,11, 0,10, 0, 0, 9, 0, 0, 0, 0};
__constant__ int c_it1[24] = {16,32,16,15,30,14,28,14,13,26,12,24,12,11,22,10,20,10, 9,18, 8, 6, 4, 2};

// ---------------------------------------------------------------------------
// PTX helpers (baseline ISA only)
// ---------------------------------------------------------------------------
__device__ __forceinline__ uint32_t smem_u32(const void* p) {
    uint32_t a;
    asm("{ .reg .u64 t; cvta.to.shared.u64 t, %1; cvt.u32.u64 %0, t; }" : "=r"(a) : "l"(p));
    return a;
}
__device__ __forceinline__ void ldsm_x4(uint32_t* r, uint32_t addr) {
    asm volatile("ldmatrix.sync.aligned.m8n8.x4.shared.b16 {%0,%1,%2,%3}, [%4];"
                 : "=r"(r[0]), "=r"(r[1]), "=r"(r[2]), "=r"(r[3]) : "r"(addr));
}
__device__ __forceinline__ void ldsm_x4_t(uint32_t* r, uint32_t addr) {
    asm volatile("ldmatrix.sync.aligned.m8n8.x4.trans.shared.b16 {%0,%1,%2,%3}, [%4];"
                 : "=r"(r[0]), "=r"(r[1]), "=r"(r[2]), "=r"(r[3]) : "r"(addr));
}
__device__ __forceinline__ void mma16816(float* c, const uint32_t* a, uint32_t b0, uint32_t b1) {
    asm volatile("mma.sync.aligned.m16n8k16.row.col.f32.bf16.bf16.f32 "
                 "{%0,%1,%2,%3}, {%4,%5,%6,%7}, {%8,%9}, {%0,%1,%2,%3};"
                 : "+f"(c[0]), "+f"(c[1]), "+f"(c[2]), "+f"(c[3])
                 : "r"(a[0]), "r"(a[1]), "r"(a[2]), "r"(a[3]), "r"(b0), "r"(b1));
}
__device__ __forceinline__ void sts128(uint32_t addr, uint4 v) {
    asm volatile("st.shared.v4.b32 [%0], {%1,%2,%3,%4};"
                 :: "r"(addr), "r"(v.x), "r"(v.y), "r"(v.z), "r"(v.w) : "memory");
}
__device__ __forceinline__ void cpasync16(uint32_t dst, const void* src) {
    asm volatile("cp.async.cg.shared.global [%0], [%1], 16;" :: "r"(dst), "l"(src));
}
__device__ __forceinline__ void cpasync_commit() {
    asm volatile("cp.async.commit_group;" ::: "memory");
}
template <int N>
__device__ __forceinline__ void cpasync_wait() {
    asm volatile("cp.async.wait_group %0;" :: "n"(N) : "memory");
}
__device__ __forceinline__ float fsqrt_ap(float x) {
    float r; asm("sqrt.approx.f32 %0, %1;" : "=f"(r) : "f"(x)); return r;
}
__device__ __forceinline__ float flg2(float x) {
    float r; asm("lg2.approx.f32 %0, %1;" : "=f"(r) : "f"(x)); return r;
}
__device__ __forceinline__ float fex2(float x) {
    float r; asm("ex2.approx.f32 %0, %1;" : "=f"(r) : "f"(x)); return r;
}
#define SW128(o) ((o) ^ (((o) >> 3) & 0x70))

__device__ __forceinline__ uint16_t bf_hi(float f, float& rem) {
    __nv_bfloat16 h = __float2bfloat16(f);
    rem = f - __bfloat162float(h);
    union { __nv_bfloat16 b; uint16_t u; } cv; cv.b = h;
    return cv.u;
}
__device__ __forceinline__ uint16_t bf_of(float f) {
    union { __nv_bfloat16 b; uint16_t u; } cv; cv.b = __float2bfloat16(f);
    return cv.u;
}

// ---------------------------------------------------------------------------
// Merged fp32 -> bf16 hi/lo conversion for all 5 input tensors.
// ---------------------------------------------------------------------------
#define N4_X  (TT * DM / 4)
#define N4_QW (DM * DM / 4)
#define N4_KW (256 * DM / 4)
#define N4_VW (256 * DM / 4)
#define N4_OW (DM * DM / 4)
#define N4_TOT (N4_X + N4_QW + N4_KW + N4_VW + N4_OW)

__global__ __launch_bounds__(256) void conv_all(
    const float* __restrict__ x, const float* __restrict__ qw,
    const float* __restrict__ kw, const float* __restrict__ vw,
    const float* __restrict__ ow,
    char* xh, char* xl, char* qwh, char* qwl, char* kwh, char* kwl,
    char* vwh, char* vwl, char* owh, char* owl) {
    int i = blockIdx.x * 256 + threadIdx.x;
    if (i >= N4_TOT) return;
    const float* in; char* hi; char* lo; int base;
    if (i < N4_X)                          { in = x;  hi = xh;  lo = xl;  base = 0; }
    else if (i < N4_X + N4_QW)             { in = qw; hi = qwh; lo = qwl; base = N4_X; }
    else if (i < N4_X + N4_QW + N4_KW)     { in = kw; hi = kwh; lo = kwl; base = N4_X + N4_QW; }
    else if (i < N4_X + N4_QW + N4_KW + N4_VW)
                                           { in = vw; hi = vwh; lo = vwl; base = N4_X + N4_QW + N4_KW; }
    else                                   { in = ow; hi = owh; lo = owl; base = N4_X + N4_QW + N4_KW + N4_VW; }
    int j4 = i - base;
    float4 v = ((const float4*)in)[j4];
    union { __nv_bfloat16 b[4]; uint2 u; } h, l;
    float f[4] = {v.x, v.y, v.z, v.w};
#pragma unroll
    for (int j = 0; j < 4; j++) {
        h.b[j] = __float2bfloat16(f[j]);
        l.b[j] = __float2bfloat16(f[j] - __bfloat162float(h.b[j]));
    }
    ((uint2*)hi)[j4] = h.u;
    ((uint2*)lo)[j4] = l.u;
}

// ---------------------------------------------------------------------------
// HMMA bf16 hi/lo-split GEMM with cp.async 3-stage pipeline.
// ---------------------------------------------------------------------------
#define TILE_B 16384
#define STAGE_B (4 * TILE_B)
#define GEMM_SMEM_BYTES (3 * STAGE_B + 1024)

__global__ __launch_bounds__(256) void gemm_mma_hl(
    const char* __restrict__ Ah, const char* __restrict__ Al,
    const char* __restrict__ Bh, const char* __restrict__ Bl,
    float* __restrict__ C, int Ntot, int K) {
    extern __shared__ __align__(16) char sm[];
    uint32_t ts = (smem_u32(sm) + 1023) & ~1023u;
    const uint32_t stage[3] = { ts, ts + STAGE_B, ts + 2 * STAGE_B };

    const int tid = threadIdx.x;
    const int lane = tid & 31;
    const int wid = tid >> 5;
    const int wm = wid >> 1;
    const int wn = wid & 1;
    const int m0 = blockIdx.y * 128;
    const int n0 = blockIdx.x * 128;
    const size_t K2 = (size_t)K * 2;

    const char* srcs[4] = { Ah + (size_t)m0 * K2, Al + (size_t)m0 * K2,
                            Bh + (size_t)n0 * K2, Bl + (size_t)n0 * K2 };

    const int u = tid & 7;
    const int r0 = tid >> 3;

    auto load_chunk = [&](int ch, uint32_t sb) {
        const size_t koff = (size_t)ch * 128 + u * 16;
#pragma unroll
        for (int t = 0; t < 4; t++) {
            const char* src = srcs[t] + koff;
            const uint32_t tb = sb + t * TILE_B;
#pragma unroll
            for (int it = 0; it < 4; it++) {
                const int row = it * 32 + r0;
                uint32_t off = row * 128 + u * 16;
                cpasync16(tb + SW128(off), src + (size_t)row * K2);
            }
        }
    };

    float acc[2][8][4];
#pragma unroll
    for (int a = 0; a < 2; a++)
#pragma unroll
        for (int b = 0; b < 8; b++)
#pragma unroll
            for (int cc = 0; cc < 4; cc++) acc[a][b][cc] = 0.f;

    const int amat = lane >> 3, arow = lane & 7;
    const int nch = K / 64;

    load_chunk(0, stage[0]);
    cpasync_commit();
    if (nch > 1) {
        load_chunk(1, stage[1]);
        cpasync_commit();
    }

    for (int ch = 0; ch < nch; ch++) {
        if (ch + 2 < nch) {
            load_chunk(ch + 2, stage[(ch + 2) % 3]);
            cpasync_commit();
            cpasync_wait<2>();
        } else if (ch + 1 < nch) {
            cpasync_wait<1>();
        } else {
            cpasync_wait<0>();
        }
        __syncthreads();

        const uint32_t sb = stage[ch % 3];
        const uint32_t tAh = sb, tAl = sb + TILE_B, tBh = sb + 2 * TILE_B, tBl = sb + 3 * TILE_B;
#pragma unroll
        for (int ks = 0; ks < 4; ks++) {
            uint32_t ah[2][4], al[2][4], bh[4][4], bl[4][4];
#pragma unroll
            for (int mb = 0; mb < 2; mb++) {
                int m = wm * 32 + mb * 16 + (amat & 1) * 8 + arow;
                int kb = ks * 32 + (amat >> 1) * 16;
                uint32_t off = SW128((uint32_t)(m * 128 + kb));
                ldsm_x4(ah[mb], tAh + off);
                ldsm_x4(al[mb], tAl + off);
            }
#pragma unroll
            for (int p = 0; p < 4; p++) {
                int n = wn * 64 + p * 16 + (amat >> 1) * 8 + arow;
                int kb = ks * 32 + (amat & 1) * 16;
                uint32_t off = SW128((uint32_t)(n * 128 + kb));
                ldsm_x4(bh[p], tBh + off);
                ldsm_x4(bl[p], tBl + off);
            }
#pragma unroll
            for (int mb = 0; mb < 2; mb++)
#pragma unroll
                for (int p = 0; p < 4; p++) {
                    mma16816(acc[mb][2 * p],     ah[mb], bh[p][0], bh[p][1]);
                    mma16816(acc[mb][2 * p + 1], ah[mb], bh[p][2], bh[p][3]);
                    mma16816(acc[mb][2 * p],     ah[mb], bl[p][0], bl[p][1]);
                    mma16816(acc[mb][2 * p + 1], ah[mb], bl[p][2], bl[p][3]);
                    mma16816(acc[mb][2 * p],     al[mb], bh[p][0], bh[p][1]);
                    mma16816(acc[mb][2 * p + 1], al[mb], bh[p][2], bh[p][3]);
                }
        }
        __syncthreads();
    }

    const int crow = lane >> 2;
    const int ccol = (lane & 3) * 2;
#pragma unroll
    for (int mb = 0; mb < 2; mb++) {
#pragma unroll
        for (int nb = 0; nb < 8; nb++) {
            int m = m0 + wm * 32 + mb * 16 + crow;
            int n = n0 + wn * 64 + nb * 8 + ccol;
            *(float2*)&C[(size_t)m * Ntot + n]       = make_float2(acc[mb][nb][0], acc[mb][nb][1]);
            *(float2*)&C[(size_t)(m + 8) * Ntot + n] = make_float2(acc[mb][nb][2], acc[mb][nb][3]);
        }
    }
}

// ---------------------------------------------------------------------------
// RMSNorm + RoPE (+ sqrt(c) prescale); q0/k0 = sqrt(1 + c|v|^2).
// ---------------------------------------------------------------------------
__global__ __launch_bounds__(256) void rms_rope_kernel(
    const float* __restrict__ qkv,
    char* __restrict__ qbh, char* __restrict__ qbl,
    char* __restrict__ kbh, char* __restrict__ kbl,
    float* __restrict__ q0, float* __restrict__ k0,
    float* __restrict__ qn, const float* __restrict__ curv) {
    const int wid = threadIdx.x >> 5;
    const int lane = threadIdx.x & 31;
    const int vi = blockIdx.x * 8 + wid;
    const int t = vi & 2047;
    const int hh = vi >> 11;

    const float* vec;
    size_t obase;
    char *oh, *ol;
    if (hh < NH) {
        vec = qkv + (size_t)t * NQKV + hh * HD;
        obase = ((size_t)t * NH + hh) * HD; oh = qbh; ol = qbl;
    } else {
        vec = qkv + (size_t)t * NQKV + 1024 + (hh - NH) * HD;
        obase = ((size_t)t * NKV + (hh - NH)) * HD; oh = kbh; ol = kbl;
    }
    float x1 = vec[lane], x2 = vec[lane + 32];
    float ss = x1 * x1 + x2 * x2;
#pragma unroll
    for (int o = 16; o >= 1; o >>= 1) ss += __shfl_xor_sync(0xffffffffu, ss, o);

    float inv = rsqrtf(ss * (1.0f / 64.0f) + EPSN);
    x1 *= inv; x2 *= inv;

    float invf = expf(-(float)lane * 0.28782313662425572f);
    float ang = (float)t * invf;
    float sv, cv;
    sincosf(ang, &sv, &cv);
    float c = *curv;
    float sqc = sqrtf(c);
    float o1 = fmaf(x1, cv, x2 * sv) * sqc;
    float o2 = fmaf(-x1, sv, x2 * cv) * sqc;

    float r1, r2;
    uint16_t h1 = bf_hi(o1, r1), h2 = bf_hi(o2, r2);
    ((uint16_t*)oh)[obase + lane]      = h1;
    ((uint16_t*)oh)[obase + lane + 32] = h2;
    ((uint16_t*)ol)[obase + lane]      = bf_of(r1);
    ((uint16_t*)ol)[obase + lane + 32] = bf_of(r2);

    if (lane == 0) {
        float sum2 = ss * inv * inv;
        float h0 = sqrtf(1.0f + c * sum2);
        if (hh < NH) {
            q0[t * NH + hh] = h0;
            qn[t * NH + hh] = sqrtf(sum2);
        } else {
            k0[t * NKV + (hh - NH)] = h0;
        }
    }
}

// ---------------------------------------------------------------------------
// V slice conversion from fused buffer
// ---------------------------------------------------------------------------
__global__ __launch_bounds__(256) void v_conv(const float* __restrict__ qkv,
                                              char* __restrict__ vbh,
                                              char* __restrict__ vbl) {
    int i = blockIdx.x * 256 + threadIdx.x;
    if (i >= TT * 64) return;
    int t = i >> 6, j = i & 63;
    float4 v = *(const float4*)&qkv[(size_t)t * NQKV + 1280 + j * 4];
    union { __nv_bfloat16 b[4]; uint2 u; } h, l;
    float f[4] = {v.x, v.y, v.z, v.w};
#pragma unroll
    for (int jj = 0; jj < 4; jj++) {
        h.b[jj] = __float2bfloat16(f[jj]);
        l.b[jj] = __float2bfloat16(f[jj] - __bfloat162float(h.b[jj]));
    }
    ((uint2*)vbh)[t * 64 + j] = h.u;
    ((uint2*)vbl)[t * 64 + j] = l.u;
}

// ---------------------------------------------------------------------------
// Tensor-core flash hyperbolic attention.
// CTA = 128 q-rows x 1 head, 8 warps (2 CTAs/SM). Split-K via 24-item table.
// 3-term S=QK^T, 3-term PV (P hi/lo restored).
// ---------------------------------------------------------------------------
#define FA_STAGE_B 32768
#define FA_SMEM_BYTES (2 * FA_STAGE_B + 2560)

__global__ void __launch_bounds__(256, 2) flash_attn_mma(
    const char* __restrict__ Qh, const char* __restrict__ Ql,
    const char* __restrict__ Kh, const char* __restrict__ Kl,
    const char* __restrict__ Vh, const char* __restrict__ Vl,
    const float* __restrict__ q0a, const float* __restrict__ k0a,
    const float* __restrict__ temp, const float* __restrict__ curv,
    float* __restrict__ oacc1, float* __restrict__ oacc2,
    float* __restrict__ lacc1, float* __restrict__ lacc2) {
    extern __shared__ __align__(16) char smraw[];
    const uint32_t sb0 = (smem_u32(smraw) + 1023) & ~1023u;
    const uint32_t stg[2] = { sb0, sb0 + FA_STAGE_B };
    float* q0s = (float*)(smraw + (sb0 - smem_u32(smraw)) + 2 * FA_STAGE_B);
    float* k0st0 = q0s + 128;
    float* k0st1 = k0st0 + 64;

    const int tid = threadIdx.x;
    const int lane = tid & 31;
    const int wp = tid >> 5;                  // 0..7
    const int h = blockIdx.x;
    const int cidx = blockIdx.y;

    const int b   = c_ib[cidx];
    const int tl0 = c_it0[cidx];
    const int tl1 = c_it1[cidx];
    const int t0 = b * 128;
    const int kvh = h >> 2;

    float* ob = (tl0 == 0) ? oacc1 : oacc2;
    float* lb = (tl0 == 0) ? lacc1 : lacc2;

    const float sscale = rsqrtf(*curv) / temp[h];
    const float loclamp = 1.0f + 1e-5f;

    // ---- stage Q tile (128 rows, hi/lo) into stage0 ----
    {
        const char* qs[2] = { Qh, Ql };
        for (int idx = tid; idx < 2048; idx += 256) {
            int mtx = idx >> 10, rem = idx & 1023, row = rem >> 3, u = rem & 7;
            const char* src = qs[mtx] + ((size_t)(t0 + row) * NH + h) * 128 + u * 16;
            sts128(stg[0] + mtx * 16384 + SW128((uint32_t)(row * 128 + u * 16)), *(const uint4*)src);
        }
        if (tid < 128) q0s[tid] = q0a[(t0 + tid) * NH + h];
    }
    __syncthreads();

    // ---- Q fragments to registers (warp wp: rows 16wp..16wp+15) ----
    uint32_t qa_h[4][4], qa_l[4][4];
    {
        const int g = lane >> 3, lr = lane & 7;
        const int row = 16 * wp + (g & 1) * 8 + lr;
#pragma unroll
        for (int ks = 0; ks < 4; ks++) {
            uint32_t off = SW128((uint32_t)(row * 128 + ks * 32 + (g >> 1) * 16));
            ldsm_x4(qa_h[ks], stg[0] + off);
            ldsm_x4(qa_l[ks], stg[0] + 16384 + off);
        }
    }
    const int r = lane >> 2;
    const int colb = (lane & 3) * 2;
    const float q0r0 = q0s[16 * wp + r];
    const float q0r1 = q0s[16 * wp + 8 + r];
    const int rl0 = t0 + 16 * wp + r;
    const int rl1 = rl0 + 8;
    __syncthreads();

    float o[8][4];
#pragma unroll
    for (int i = 0; i < 8; i++)
#pragma unroll
        for (int j = 0; j < 4; j++) o[i][j] = 0.f;
    float lsum0 = 0.f, lsum1 = 0.f;

    const char* kvsrc[4] = { Kh + kvh * 128, Kl + kvh * 128, Vh + kvh * 128, Vl + kvh * 128 };

    auto kv_load = [&](int c0, uint32_t sbase, float* k0dst) {
        for (int idx = tid; idx < 2048; idx += 256) {
            int mtx = idx >> 9, rem = idx & 511, row = rem >> 3, u = rem & 7;
            const char* src = kvsrc[mtx] + (size_t)(c0 + row) * 512 + u * 16;
            cpasync16(sbase + mtx * 8192 + SW128((uint32_t)(row * 128 + u * 16)), src);
        }
        if (tid < 64) k0dst[tid] = k0a[(c0 + tid) * NKV + kvh];
    };

    kv_load(tl0 * 64, stg[tl0 & 1], (tl0 & 1) ? k0st1 : k0st0);
    cpasync_commit();

    for (int ch = tl0; ch < tl1; ch++) {
        if (ch + 1 < tl1) {
            kv_load((ch + 1) * 64, stg[(ch + 1) & 1], ((ch + 1) & 1) ? k0st1 : k0st0);
            cpasync_commit();
            cpasync_wait<1>();
        } else {
            cpasync_wait<0>();
        }
        __syncthreads();

        const uint32_t sKh = stg[ch & 1], sKl = sKh + 8192, sVh = sKh + 16384, sVl = sKh + 24576;
        const float* k0s = (ch & 1) ? k0st1 : k0st0;
        const int cbase = ch * 64;

        // ---- S = Q K^T (3-term) ----
        float sc[8][4];
#pragma unroll
        for (int i = 0; i < 8; i++)
#pragma unroll
            for (int j = 0; j < 4; j++) sc[i][j] = 0.f;
        {
            const int g = lane >> 3, lr = lane & 7;
#pragma unroll
            for (int ks = 0; ks < 4; ks++) {
                const int dby = ks * 32 + (g >> 1) * 16;
#pragma unroll
                for (int p = 0; p < 4; p++) {
                    const int row = p * 16 + (g & 1) * 8 + lr;
                    uint32_t off = SW128((uint32_t)(row * 128 + dby));
                    uint32_t bh[4], bl[4];
                    ldsm_x4(bh, sKh + off);
                    ldsm_x4(bl, sKl + off);
                    mma16816(sc[2 * p],     qa_h[ks], bh[0], bh[2]);
                    mma16816(sc[2 * p + 1], qa_h[ks], bh[1], bh[3]);
                    mma16816(sc[2 * p],     qa_h[ks], bl[0], bl[2]);
                    mma16816(sc[2 * p + 1], qa_h[ks], bl[1], bl[3]);
                    mma16816(sc[2 * p],     qa_l[ks], bh[0], bh[2]);
                    mma16816(sc[2 * p + 1], qa_l[ks], bh[1], bh[3]);
                }
            }
        }

        // ---- hyperbolic transform -> weights; pack P hi/lo ----
        uint32_t ph[4][4], pl[4][4];
#pragma unroll
        for (int nb = 0; nb < 8; nb++) {
            float k00 = k0s[nb * 8 + colb];
            float k01 = k0s[nb * 8 + colb + 1];
            const int cl0 = cbase + nb * 8 + colb, cl1 = cl0 + 1;
            float w0, w1, w2, w3;
            {
                float arg = fmaxf(fmaf(q0r0, k00, -sc[nb][0]), loclamp);
                float z = arg + fsqrt_ap(fmaf(arg, arg, -1.f));
                w0 = fex2(-sscale * flg2(z));
            }
            {
                float arg = fmaxf(fmaf(q0r0, k01, -sc[nb][1]), loclamp);
                float z = arg + fsqrt_ap(fmaf(arg, arg, -1.f));
                w1 = fex2(-sscale * flg2(z));
            }
            {
                float arg = fmaxf(fmaf(q0r1, k00, -sc[nb][2]), loclamp);
                float z = arg + fsqrt_ap(fmaf(arg, arg, -1.f));
                w2 = fex2(-sscale * flg2(z));
            }
            {
                float arg = fmaxf(fmaf(q0r1, k01, -sc[nb][3]), loclamp);
                float z = arg + fsqrt_ap(fmaf(arg, arg, -1.f));
                w3 = fex2(-sscale * flg2(z));
            }
            if (cl0 > rl0) w0 = 0.f;
            if (cl1 > rl0) w1 = 0.f;
            if (cl0 > rl1) w2 = 0.f;
            if (cl1 > rl1) w3 = 0.f;
            lsum0 += w0 + w1;
            lsum1 += w2 + w3;
            float r0f, r1f, r2f, r3f;
            uint32_t h01 = (uint32_t)bf_hi(w0, r0f) | ((uint32_t)bf_hi(w1, r1f) << 16);
            uint32_t h23 = (uint32_t)bf_hi(w2, r2f) | ((uint32_t)bf_hi(w3, r3f) << 16);
            uint32_t l01 = (uint32_t)bf_of(r0f) | ((uint32_t)bf_of(r1f) << 16);
            uint32_t l23 = (uint32_t)bf_of(r2f) | ((uint32_t)bf_of(r3f) << 16);
            int ks = nb >> 1, ix = (nb & 1) * 2;
            ph[ks][ix] = h01; ph[ks][ix + 1] = h23;
            pl[ks][ix] = l01; pl[ks][ix + 1] = l23;
        }

        // ---- O += P V (3-term) ----
        {
            const int g = lane >> 3, lr = lane & 7;
#pragma unroll
            for (int ks = 0; ks < 4; ks++) {
                const int rowv = ks * 16 + (g & 1) * 8 + lr;
#pragma unroll
                for (int dp = 0; dp < 4; dp++) {
                    uint32_t off = SW128((uint32_t)(rowv * 128 + dp * 32 + (g >> 1) * 16));
                    uint32_t bvh[4], bvl[4];
                    ldsm_x4_t(bvh, sVh + off);
                    ldsm_x4_t(bvl, sVl + off);
                    mma16816(o[2 * dp],     ph[ks], bvh[0], bvh[1]);
                    mma16816(o[2 * dp + 1], ph[ks], bvh[2], bvh[3]);
                    mma16816(o[2 * dp],     ph[ks], bvl[0], bvl[1]);
                    mma16816(o[2 * dp + 1], ph[ks], bvl[2], bvl[3]);
                    mma16816(o[2 * dp],     pl[ks], bvh[0], bvh[1]);
                    mma16816(o[2 * dp + 1], pl[ks], bvh[2], bvh[3]);
                }
            }
        }
        __syncthreads();
    }

    // ---- epilogue: store unnormalized partials ----
    lsum0 += __shfl_xor_sync(0xffffffffu, lsum0, 1);
    lsum0 += __shfl_xor_sync(0xffffffffu, lsum0, 2);
    lsum1 += __shfl_xor_sync(0xffffffffu, lsum1, 1);
    lsum1 += __shfl_xor_sync(0xffffffffu, lsum1, 2);

#pragma unroll
    for (int nb = 0; nb < 8; nb++) {
        int col = h * 64 + nb * 8 + colb;
        *(float2*)&ob[(size_t)rl0 * DM + col] = make_float2(o[nb][0], o[nb][1]);
        *(float2*)&ob[(size_t)rl1 * DM + col] = make_float2(o[nb][2], o[nb][3]);
    }
    if ((lane & 3) == 0) {
        lb[rl0 * NH + h] = lsum0;
        lb[rl1 * NH + h] = lsum1;
    }
}

// ---------------------------------------------------------------------------
// merge split partials, normalize, emit bf16 hi/lo attn output.
// rows t >= 1024 (blocks b >= 8) have two partials.
// ---------------------------------------------------------------------------
__global__ __launch_bounds__(256) void merge_norm(
    const float* __restrict__ oacc1, const float* __restrict__ oacc2,
    const float* __restrict__ lacc1, const float* __restrict__ lacc2,
    char* __restrict__ ah, char* __restrict__ al) {
    int j = threadIdx.x;
    int rowid = blockIdx.x * 16 + (j >> 4);
    int t = rowid >> 4;
    int hh = rowid & 15;
    int dd = (j & 15) * 4;
    bool two = (t >= 1024);

    float l = lacc1[rowid] + (two ? lacc2[rowid] : 0.f);
    size_t base = (size_t)t * DM + hh * 64 + dd;
    float4 ov = *(const float4*)&oacc1[base];
    if (two) {
        float4 o2 = *(const float4*)&oacc2[base];
        ov.x += o2.x; ov.y += o2.y; ov.z += o2.z; ov.w += o2.w;
    }
    float invl = 1.0f / l;
    float f[4] = {ov.x * invl, ov.y * invl, ov.z * invl, ov.w * invl};
    union { uint16_t u[4]; uint2 v; } hb, lb2;
#pragma unroll
    for (int k = 0; k < 4; k++) {
        float rem;
        hb.u[k] = bf_hi(f[k], rem);
        lb2.u[k] = bf_of(rem);
    }
    *(uint2*)(ah + base * 2) = hb.v;
    *(uint2*)(al + base * 2) = lb2.v;
}

// ---------------------------------------------------------------------------
// spatial_norm: two-stage reduction
// ---------------------------------------------------------------------------
__global__ __launch_bounds__(256) void norm_partial(const float* __restrict__ qn,
                                                    float* __restrict__ part) {
    __shared__ float red[256];
    int tid = threadIdx.x;
    float s = 0.f;
    for (int i = blockIdx.x * 256 + tid; i < TT * NH; i += 32 * 256) s += qn[i];
    red[tid] = s;
    __syncthreads();
#pragma unroll
    for (int k = 128; k > 0; k >>= 1) {
        if (tid < k) red[tid] += red[tid + k];
        __syncthreads();
    }
    if (tid == 0) part[blockIdx.x] = red[0];
}
__global__ __launch_bounds__(32) void norm_final(const float* __restrict__ part,
                                                 float* __restrict__ out_scalar) {
    int tid = threadIdx.x;
    float s = part[tid];
#pragma unroll
    for (int o = 16; o >= 1; o >>= 1) s += __shfl_xor_sync(0xffffffffu, s, o);
    if (tid == 0) *out_scalar = s * (1.0f / (float)(TT * NH));
}

// ---------------------------------------------------------------------------
// Launch
// ---------------------------------------------------------------------------
extern "C" void kernel_launch(void* const* d_in, const int* in_sizes, int n_in,
                              void* d_out, int out_size) {
    const float* x    = (const float*)d_in[0];
    const float* q_w  = (const float*)d_in[1];
    const float* k_w  = (const float*)d_in[2];
    const float* v_w  = (const float*)d_in[3];
    const float* o_w  = (const float*)d_in[4];
    const float* temp = (const float*)d_in[5];
    const float* curv = (const float*)d_in[6];
    float* out = (float*)d_out;

    float *pqkv, *pq0, *pk0, *pqn, *ppart, *po1, *po2, *pl1, *pl2;
    char *xh, *xl, *wh, *wl, *owh, *owl, *ah, *al;
    char *qbh, *qbl, *kbh, *kbl, *vbh, *vbl;
    cudaGetSymbolAddress((void**)&pqkv, g_qkv);
    cudaGetSymbolAddress((void**)&pq0, g_q0);
    cudaGetSymbolAddress((void**)&pk0, g_k0);
    cudaGetSymbolAddress((void**)&pqn, g_qn);
    cudaGetSymbolAddress((void**)&ppart, g_part);
    cudaGetSymbolAddress((void**)&po1, g_oacc1);
    cudaGetSymbolAddress((void**)&po2, g_oacc2);
    cudaGetSymbolAddress((void**)&pl1, g_lacc1);
    cudaGetSymbolAddress((void**)&pl2, g_lacc2);
    cudaGetSymbolAddress((void**)&xh, g_xh);
    cudaGetSymbolAddress((void**)&xl, g_xl);
    cudaGetSymbolAddress((void**)&wh, g_wh);
    cudaGetSymbolAddress((void**)&wl, g_wl);
    cudaGetSymbolAddress((void**)&owh, g_owh);
    cudaGetSymbolAddress((void**)&owl, g_owl);
    cudaGetSymbolAddress((void**)&ah, g_ah);
    cudaGetSymbolAddress((void**)&al, g_al);
    cudaGetSymbolAddress((void**)&qbh, g_qbh);
    cudaGetSymbolAddress((void**)&qbl, g_qbl);
    cudaGetSymbolAddress((void**)&kbh, g_kbh);
    cudaGetSymbolAddress((void**)&kbl, g_kbl);
    cudaGetSymbolAddress((void**)&vbh, g_vbh);
    cudaGetSymbolAddress((void**)&vbl, g_vbl);

    cudaFuncSetAttribute(gemm_mma_hl, cudaFuncAttributeMaxDynamicSharedMemorySize,
                         GEMM_SMEM_BYTES);
    cudaFuncSetAttribute(flash_attn_mma, cudaFuncAttributeMaxDynamicSharedMemorySize,
                         FA_SMEM_BYTES);

    char* qwh = wh;                         char* qwl = wl;
    char* kwh = wh + (size_t)1024 * DM * 2; char* kwl = wl + (size_t)1024 * DM * 2;
    char* vwh = wh + (size_t)1280 * DM * 2; char* vwl = wl + (size_t)1280 * DM * 2;

    conv_all<<<(N4_TOT + 255) / 256, 256>>>(x, q_w, k_w, v_w, o_w,
                                            xh, xl, qwh, qwl, kwh, kwl,
                                            vwh, vwl, owh, owl);

    gemm_mma_hl<<<dim3(NQKV / 128, TT / 128), 256, GEMM_SMEM_BYTES>>>(
        xh, xl, wh, wl, pqkv, NQKV, DM);

    rms_rope_kernel<<<TT * (NH + NKV) / 8, 256>>>(pqkv, qbh, qbl, kbh, kbl,
                                                  pq0, pk0, pqn, curv);
    v_conv<<<(TT * 64 + 255) / 256, 256>>>(pqkv, vbh, vbl);

    flash_attn_mma<<<dim3(NH, 24), 256, FA_SMEM_BYTES>>>(
        qbh, qbl, kbh, kbl, vbh, vbl, pq0, pk0, temp, curv,
        po1, po2, pl1, pl2);

    merge_norm<<<TT * NH / 16, 256>>>(po1, po2, pl1, pl2, ah, al);

    gemm_mma_hl<<<dim3(DM / 128, TT / 128), 256, GEMM_SMEM_BYTES>>>(
        ah, al, owh, owl, out, DM, DM);

    norm_partial<<<32, 256>>>(pqn, ppart);
    norm_final<<<1, 32>>>(ppart, out + (out_size - 1));
}